// round 6
// baseline (speedup 1.0000x reference)
#include <cuda_runtime.h>
#include <cuda_bf16.h>
#include <math.h>

// ---------------------------------------------------------------------------
// GPT-2 small forward: L=6, C=768, H=12, D=64, B=4, T=1024, V=32000
// Output layout: logits [4096*32000] | loss [1] | x_final [4096*768]
// Round 5: FFMA2 GEMMs with duplicated-A smem (no pack MOVs) and LDS.128
// B-fragment reads (bank-conflict-free-ish). Register-pipelined k-loop.
// ---------------------------------------------------------------------------

#define BT   4096
#define CH   768
#define NH   12
#define DH   64
#define TSEQ 1024
#define VOC  32000
#define NLAY 6

typedef unsigned long long ull;

// Scratch (device globals: no allocation allowed)
__device__ float g_x[BT * CH];
__device__ float g_h[BT * CH];
__device__ float g_qkv[BT * 3 * CH];
__device__ float g_y[BT * CH];
__device__ float g_m[BT * 4 * CH];
__device__ float g_num;
__device__ float g_den;

// ---------------------------------------------------------------------------
__global__ void embed_k(const int* __restrict__ idx, const float* __restrict__ wte,
                        const float* __restrict__ wpe, float* __restrict__ x) {
    int row = blockIdx.x;
    int t = row & (TSEQ - 1);
    int tok = idx[row];
    const float* a = wte + (size_t)tok * CH;
    const float* b = wpe + (size_t)t * CH;
    float* o = x + (size_t)row * CH;
    for (int c = threadIdx.x; c < CH; c += blockDim.x) o[c] = a[c] + b[c];
}

__global__ void copy_k(const float* __restrict__ src, float* __restrict__ dst, int n) {
    int i = blockIdx.x * blockDim.x + threadIdx.x;
    if (i < n) dst[i] = src[i];
}

// ---------------------------------------------------------------------------
__global__ void ln_k(const float* __restrict__ x, const float* __restrict__ g,
                     const float* __restrict__ b, float* __restrict__ o) {
    __shared__ float r1[256], r2[256];
    int row = blockIdx.x;
    const float* xr = x + (size_t)row * CH;
    float s = 0.f, s2 = 0.f;
    for (int i = threadIdx.x; i < CH; i += 256) { float v = xr[i]; s += v; s2 += v * v; }
    r1[threadIdx.x] = s; r2[threadIdx.x] = s2;
    __syncthreads();
    for (int off = 128; off > 0; off >>= 1) {
        if (threadIdx.x < off) {
            r1[threadIdx.x] += r1[threadIdx.x + off];
            r2[threadIdx.x] += r2[threadIdx.x + off];
        }
        __syncthreads();
    }
    float mean = r1[0] * (1.0f / CH);
    float var  = r2[0] * (1.0f / CH) - mean * mean;
    float rstd = rsqrtf(var + 1e-5f);
    float* orow = o + (size_t)row * CH;
    for (int i = threadIdx.x; i < CH; i += 256)
        orow[i] = (xr[i] - mean) * rstd * g[i] + b[i];
}

// ---------------------------------------------------------------------------
__device__ __forceinline__ void ffma2(ull& acc, ull a, ull b) {
    asm("fma.rn.f32x2 %0, %1, %2, %0;" : "+l"(acc) : "l"(a), "l"(b));
}
__device__ __forceinline__ float lo32(ull v) { return __uint_as_float((unsigned)v); }
__device__ __forceinline__ float hi32(ull v) { return __uint_as_float((unsigned)(v >> 32)); }

#define AS2W 272   // As2 row stride in floats (16B-aligned: 272*4=1088)
#define BSW  132   // Bs row stride in floats (528B, 16B-aligned)

// ---------------------------------------------------------------------------
// Tiled fp32 GEMM (FFMA2, dup-A smem, pipelined): C = act(A@B + bias) (+res)
// Tile 128x128x16, 256 threads, 8x8/thread. A 16B-aligned, K%16==0, M,N%128==0.
template <int ACT, int RES>
__global__ __launch_bounds__(256, 2)
void gemm_nn_k(const float* __restrict__ A, const float* __restrict__ B,
               const float* __restrict__ bias, const float* __restrict__ res,
               float* __restrict__ Cmat, int M, int N, int K) {
    __shared__ __align__(16) float As2[16][AS2W];  // duplicated: [kk][2m]=[kk][2m+1]=a_m
    __shared__ __align__(16) float Bs[16][BSW];
    int tid = threadIdx.x;
    int tx = tid & 15, ty = tid >> 4;
    int row0 = blockIdx.y * 128, col0 = blockIdx.x * 128;
    ull acc[8][4] = {};
    const float* Ab = A + (size_t)row0 * K;

    // per-thread load coords
    int am0 = tid >> 2,          akq0 = (tid & 3) * 4;
    int am1 = (tid + 256) >> 2,  akq1 = ((tid + 256) & 3) * 4;
    int bkk0 = tid >> 5,         bnq0 = (tid & 31) * 4;
    int bkk1 = (tid + 256) >> 5, bnq1 = ((tid + 256) & 31) * 4;

    float4 pa0, pa1, pb0, pb1;
    pa0 = *reinterpret_cast<const float4*>(&Ab[(size_t)am0 * K + akq0]);
    pa1 = *reinterpret_cast<const float4*>(&Ab[(size_t)am1 * K + akq1]);
    pb0 = *reinterpret_cast<const float4*>(&B[(size_t)bkk0 * N + col0 + bnq0]);
    pb1 = *reinterpret_cast<const float4*>(&B[(size_t)bkk1 * N + col0 + bnq1]);
    // duplicated stores: one STS.64 of (v,v) per element
    *reinterpret_cast<float2*>(&As2[akq0 + 0][2 * am0]) = make_float2(pa0.x, pa0.x);
    *reinterpret_cast<float2*>(&As2[akq0 + 1][2 * am0]) = make_float2(pa0.y, pa0.y);
    *reinterpret_cast<float2*>(&As2[akq0 + 2][2 * am0]) = make_float2(pa0.z, pa0.z);
    *reinterpret_cast<float2*>(&As2[akq0 + 3][2 * am0]) = make_float2(pa0.w, pa0.w);
    *reinterpret_cast<float2*>(&As2[akq1 + 0][2 * am1]) = make_float2(pa1.x, pa1.x);
    *reinterpret_cast<float2*>(&As2[akq1 + 1][2 * am1]) = make_float2(pa1.y, pa1.y);
    *reinterpret_cast<float2*>(&As2[akq1 + 2][2 * am1]) = make_float2(pa1.z, pa1.z);
    *reinterpret_cast<float2*>(&As2[akq1 + 3][2 * am1]) = make_float2(pa1.w, pa1.w);
    *reinterpret_cast<float4*>(&Bs[bkk0][bnq0]) = pb0;
    *reinterpret_cast<float4*>(&Bs[bkk1][bnq1]) = pb1;
    __syncthreads();

    int nS = K >> 4;
    for (int s = 0; s < nS; s++) {
        bool more = (s + 1) < nS;
        int k0n = (s + 1) << 4;
        if (more) {
            pa0 = *reinterpret_cast<const float4*>(&Ab[(size_t)am0 * K + k0n + akq0]);
            pa1 = *reinterpret_cast<const float4*>(&Ab[(size_t)am1 * K + k0n + akq1]);
            pb0 = *reinterpret_cast<const float4*>(&B[(size_t)(k0n + bkk0) * N + col0 + bnq0]);
            pb1 = *reinterpret_cast<const float4*>(&B[(size_t)(k0n + bkk1) * N + col0 + bnq1]);
        }
#pragma unroll
        for (int kk = 0; kk < 16; kk++) {
            const ulonglong2* aq = reinterpret_cast<const ulonglong2*>(&As2[kk][ty * 16]);
            ulonglong2 A01 = aq[0], A23 = aq[1], A45 = aq[2], A67 = aq[3];
            const ulonglong2* bqv = reinterpret_cast<const ulonglong2*>(&Bs[kk][tx * 8]);
            ulonglong2 B01 = bqv[0], B23 = bqv[1];
            ull ap[8] = {A01.x, A01.y, A23.x, A23.y, A45.x, A45.y, A67.x, A67.y};
#pragma unroll
            for (int i = 0; i < 8; i++) {
                ffma2(acc[i][0], ap[i], B01.x);
                ffma2(acc[i][1], ap[i], B01.y);
                ffma2(acc[i][2], ap[i], B23.x);
                ffma2(acc[i][3], ap[i], B23.y);
            }
        }
        __syncthreads();
        if (more) {
            *reinterpret_cast<float2*>(&As2[akq0 + 0][2 * am0]) = make_float2(pa0.x, pa0.x);
            *reinterpret_cast<float2*>(&As2[akq0 + 1][2 * am0]) = make_float2(pa0.y, pa0.y);
            *reinterpret_cast<float2*>(&As2[akq0 + 2][2 * am0]) = make_float2(pa0.z, pa0.z);
            *reinterpret_cast<float2*>(&As2[akq0 + 3][2 * am0]) = make_float2(pa0.w, pa0.w);
            *reinterpret_cast<float2*>(&As2[akq1 + 0][2 * am1]) = make_float2(pa1.x, pa1.x);
            *reinterpret_cast<float2*>(&As2[akq1 + 1][2 * am1]) = make_float2(pa1.y, pa1.y);
            *reinterpret_cast<float2*>(&As2[akq1 + 2][2 * am1]) = make_float2(pa1.z, pa1.z);
            *reinterpret_cast<float2*>(&As2[akq1 + 3][2 * am1]) = make_float2(pa1.w, pa1.w);
            *reinterpret_cast<float4*>(&Bs[bkk0][bnq0]) = pb0;
            *reinterpret_cast<float4*>(&Bs[bkk1][bnq1]) = pb1;
            __syncthreads();
        }
    }
#pragma unroll
    for (int i = 0; i < 8; i++) {
        int r = row0 + ty * 8 + i;
#pragma unroll
        for (int j = 0; j < 4; j++) {
            int c = col0 + tx * 8 + j * 2;
            float v0 = lo32(acc[i][j]) + bias[c];
            float v1 = hi32(acc[i][j]) + bias[c + 1];
            if (ACT == 1) {
                v0 = 0.5f * v0 * (1.0f + erff(v0 * 0.70710678118654752440f));
                v1 = 0.5f * v1 * (1.0f + erff(v1 * 0.70710678118654752440f));
            }
            if (RES == 1) {
                float2 rv = *reinterpret_cast<const float2*>(&res[(size_t)r * N + c]);
                v0 += rv.x; v1 += rv.y;
            }
            float2 ov = make_float2(v0, v1);
            *reinterpret_cast<float2*>(&Cmat[(size_t)r * N + c]) = ov;
        }
    }
}

// ---------------------------------------------------------------------------
// NT GEMM (FFMA2, dup-A smem, pipelined): C[M,N] = A[M,K] @ W[N,K]^T
__global__ __launch_bounds__(256, 2)
void gemm_nt_k(const float* __restrict__ A, const float* __restrict__ W,
               float* __restrict__ Cmat, int M, int N, int K) {
    __shared__ __align__(16) float As2[16][AS2W];
    __shared__ __align__(16) float Bs[16][BSW];
    int tid = threadIdx.x;
    int tx = tid & 15, ty = tid >> 4;
    int row0 = blockIdx.y * 128, col0 = blockIdx.x * 128;
    ull acc[8][4] = {};
    const float* Ab = A + (size_t)row0 * K;
    const float* Wb = W + (size_t)col0 * K;

    int am0 = tid >> 2,          akq0 = (tid & 3) * 4;
    int am1 = (tid + 256) >> 2,  akq1 = ((tid + 256) & 3) * 4;

    float4 pa0, pa1, pb0, pb1;
    pa0 = *reinterpret_cast<const float4*>(&Ab[(size_t)am0 * K + akq0]);
    pa1 = *reinterpret_cast<const float4*>(&Ab[(size_t)am1 * K + akq1]);
    pb0 = *reinterpret_cast<const float4*>(&Wb[(size_t)am0 * K + akq0]);
    pb1 = *reinterpret_cast<const float4*>(&Wb[(size_t)am1 * K + akq1]);
    *reinterpret_cast<float2*>(&As2[akq0 + 0][2 * am0]) = make_float2(pa0.x, pa0.x);
    *reinterpret_cast<float2*>(&As2[akq0 + 1][2 * am0]) = make_float2(pa0.y, pa0.y);
    *reinterpret_cast<float2*>(&As2[akq0 + 2][2 * am0]) = make_float2(pa0.z, pa0.z);
    *reinterpret_cast<float2*>(&As2[akq0 + 3][2 * am0]) = make_float2(pa0.w, pa0.w);
    *reinterpret_cast<float2*>(&As2[akq1 + 0][2 * am1]) = make_float2(pa1.x, pa1.x);
    *reinterpret_cast<float2*>(&As2[akq1 + 1][2 * am1]) = make_float2(pa1.y, pa1.y);
    *reinterpret_cast<float2*>(&As2[akq1 + 2][2 * am1]) = make_float2(pa1.z, pa1.z);
    *reinterpret_cast<float2*>(&As2[akq1 + 3][2 * am1]) = make_float2(pa1.w, pa1.w);
    Bs[akq0 + 0][am0] = pb0.x; Bs[akq0 + 1][am0] = pb0.y;
    Bs[akq0 + 2][am0] = pb0.z; Bs[akq0 + 3][am0] = pb0.w;
    Bs[akq1 + 0][am1] = pb1.x; Bs[akq1 + 1][am1] = pb1.y;
    Bs[akq1 + 2][am1] = pb1.z; Bs[akq1 + 3][am1] = pb1.w;
    __syncthreads();

    int nS = K >> 4;
    for (int s = 0; s < nS; s++) {
        bool more = (s + 1) < nS;
        int k0n = (s + 1) << 4;
        if (more) {
            pa0 = *reinterpret_cast<const float4*>(&Ab[(size_t)am0 * K + k0n + akq0]);
            pa1 = *reinterpret_cast<const float4*>(&Ab[(size_t)am1 * K + k0n + akq1]);
            pb0 = *reinterpret_cast<const float4*>(&Wb[(size_t)am0 * K + k0n + akq0]);
            pb1 = *reinterpret_cast<const float4*>(&Wb[(size_t)am1 * K + k0n + akq1]);
        }
#pragma unroll
        for (int kk = 0; kk < 16; kk++) {
            const ulonglong2* aq = reinterpret_cast<const ulonglong2*>(&As2[kk][ty * 16]);
            ulonglong2 A01 = aq[0], A23 = aq[1], A45 = aq[2], A67 = aq[3];
            const ulonglong2* bqv = reinterpret_cast<const ulonglong2*>(&Bs[kk][tx * 8]);
            ulonglong2 B01 = bqv[0], B23 = bqv[1];
            ull ap[8] = {A01.x, A01.y, A23.x, A23.y, A45.x, A45.y, A67.x, A67.y};
#pragma unroll
            for (int i = 0; i < 8; i++) {
                ffma2(acc[i][0], ap[i], B01.x);
                ffma2(acc[i][1], ap[i], B01.y);
                ffma2(acc[i][2], ap[i], B23.x);
                ffma2(acc[i][3], ap[i], B23.y);
            }
        }
        __syncthreads();
        if (more) {
            *reinterpret_cast<float2*>(&As2[akq0 + 0][2 * am0]) = make_float2(pa0.x, pa0.x);
            *reinterpret_cast<float2*>(&As2[akq0 + 1][2 * am0]) = make_float2(pa0.y, pa0.y);
            *reinterpret_cast<float2*>(&As2[akq0 + 2][2 * am0]) = make_float2(pa0.z, pa0.z);
            *reinterpret_cast<float2*>(&As2[akq0 + 3][2 * am0]) = make_float2(pa0.w, pa0.w);
            *reinterpret_cast<float2*>(&As2[akq1 + 0][2 * am1]) = make_float2(pa1.x, pa1.x);
            *reinterpret_cast<float2*>(&As2[akq1 + 1][2 * am1]) = make_float2(pa1.y, pa1.y);
            *reinterpret_cast<float2*>(&As2[akq1 + 2][2 * am1]) = make_float2(pa1.z, pa1.z);
            *reinterpret_cast<float2*>(&As2[akq1 + 3][2 * am1]) = make_float2(pa1.w, pa1.w);
            Bs[akq0 + 0][am0] = pb0.x; Bs[akq0 + 1][am0] = pb0.y;
            Bs[akq0 + 2][am0] = pb0.z; Bs[akq0 + 3][am0] = pb0.w;
            Bs[akq1 + 0][am1] = pb1.x; Bs[akq1 + 1][am1] = pb1.y;
            Bs[akq1 + 2][am1] = pb1.z; Bs[akq1 + 3][am1] = pb1.w;
            __syncthreads();
        }
    }
#pragma unroll
    for (int i = 0; i < 8; i++) {
        int r = row0 + ty * 8 + i;
#pragma unroll
        for (int j = 0; j < 4; j++) {
            int c = col0 + tx * 8 + j * 2;
            float2 ov = make_float2(lo32(acc[i][j]), hi32(acc[i][j]));
            *reinterpret_cast<float2*>(&Cmat[(size_t)r * N + c]) = ov;
        }
    }
}

// ---------------------------------------------------------------------------
// Causal attention, one block per (t, h, b).
__global__ void attn_k(const float* __restrict__ qkv, float* __restrict__ y) {
    __shared__ float qs[DH];
    __shared__ float sc[TSEQ];
    __shared__ float red[128];
    int t = blockIdx.x, h = blockIdx.y, b = blockIdx.z;
    int tid = threadIdx.x;
    const float* base = qkv + (size_t)b * TSEQ * (3 * CH);
    if (tid < DH) qs[tid] = base[(size_t)t * (3 * CH) + h * DH + tid];
    __syncthreads();
    int nS = t + 1;
    float lmax = -3.0e38f;
    for (int s = tid; s < nS; s += 128) {
        const float* kr = base + (size_t)s * (3 * CH) + CH + h * DH;
        float d = 0.f;
#pragma unroll
        for (int i = 0; i < DH; i++) d += qs[i] * kr[i];
        d *= 0.125f;
        sc[s] = d;
        lmax = fmaxf(lmax, d);
    }
    red[tid] = lmax;
    __syncthreads();
    for (int off = 64; off > 0; off >>= 1) {
        if (tid < off) red[tid] = fmaxf(red[tid], red[tid + off]);
        __syncthreads();
    }
    float mx = red[0];
    __syncthreads();
    float lsum = 0.f;
    for (int s = tid; s < nS; s += 128) {
        float e = __expf(sc[s] - mx);
        sc[s] = e;
        lsum += e;
    }
    red[tid] = lsum;
    __syncthreads();
    for (int off = 64; off > 0; off >>= 1) {
        if (tid < off) red[tid] += red[tid + off];
        __syncthreads();
    }
    float inv = 1.0f / red[0];
    __syncthreads();
    if (tid < DH) {
        const float* vr = base + 2 * CH + h * DH + tid;
        float acc = 0.f;
        for (int s = 0; s < nS; s++) acc += sc[s] * vr[(size_t)s * (3 * CH)];
        y[((size_t)(b * TSEQ + t)) * CH + h * DH + tid] = acc * inv;
    }
}

// ---------------------------------------------------------------------------
__global__ void zero_loss_k(float* num, float* den) { *num = 0.f; *den = 0.f; }

__global__ void loss_k(const float* __restrict__ logits, const int* __restrict__ tg,
                       float* num, float* den) {
    __shared__ float red[256];
    int row = blockIdx.x;
    const float* lr = logits + (size_t)row * VOC;
    float m = -3.0e38f;
    for (int j = threadIdx.x; j < VOC; j += 256) m = fmaxf(m, lr[j]);
    red[threadIdx.x] = m;
    __syncthreads();
    for (int off = 128; off > 0; off >>= 1) {
        if (threadIdx.x < off) red[threadIdx.x] = fmaxf(red[threadIdx.x], red[threadIdx.x + off]);
        __syncthreads();
    }
    m = red[0];
    __syncthreads();
    float s = 0.f;
    for (int j = threadIdx.x; j < VOC; j += 256) s += __expf(lr[j] - m);
    red[threadIdx.x] = s;
    __syncthreads();
    for (int off = 128; off > 0; off >>= 1) {
        if (threadIdx.x < off) red[threadIdx.x] += red[threadIdx.x + off];
        __syncthreads();
    }
    if (threadIdx.x == 0) {
        int t = tg[row];
        if (t != 0) {
            float lse = m + logf(red[0]);
            float nll = lse - lr[t];
            atomicAdd(num, nll);
            atomicAdd(den, 1.0f);
        }
    }
}

__global__ void final_loss_k(const float* num, const float* den, float* out) {
    out[0] = *num / fmaxf(*den, 1.0f);
}

// ---------------------------------------------------------------------------
extern "C" void kernel_launch(void* const* d_in, const int* in_sizes, int n_in,
                              void* d_out, int out_size) {
    const int*   idx     = (const int*)d_in[0];
    const int*   targets = (const int*)d_in[1];
    const float* wte     = (const float*)d_in[2];
    const float* wpe     = (const float*)d_in[3];
    const float* ln1_g   = (const float*)d_in[4];
    const float* ln1_b   = (const float*)d_in[5];
    const float* attn_w  = (const float*)d_in[6];
    const float* attn_b  = (const float*)d_in[7];
    const float* proj_w  = (const float*)d_in[8];
    const float* proj_b  = (const float*)d_in[9];
    const float* ln2_g   = (const float*)d_in[10];
    const float* ln2_b   = (const float*)d_in[11];
    const float* fc_w    = (const float*)d_in[12];
    const float* fc_b    = (const float*)d_in[13];
    const float* fc2_w   = (const float*)d_in[14];
    const float* fc2_b   = (const float*)d_in[15];
    const float* lnf_g   = (const float*)d_in[16];
    const float* lnf_b   = (const float*)d_in[17];
    float* out = (float*)d_out;

    float *x, *h, *qkv, *y, *mbuf, *pnum, *pden;
    cudaGetSymbolAddress((void**)&x, g_x);
    cudaGetSymbolAddress((void**)&h, g_h);
    cudaGetSymbolAddress((void**)&qkv, g_qkv);
    cudaGetSymbolAddress((void**)&y, g_y);
    cudaGetSymbolAddress((void**)&mbuf, g_m);
    cudaGetSymbolAddress((void**)&pnum, g_num);
    cudaGetSymbolAddress((void**)&pden, g_den);

    const size_t LOGN = (size_t)BT * VOC;
    float* out_loss = out + LOGN;
    float* out_x    = out + LOGN + 1;  // 4B-aligned only: scalar access

    embed_k<<<BT, 256>>>(idx, wte, wpe, x);

    for (int l = 0; l < NLAY; l++) {
        ln_k<<<BT, 256>>>(x, ln1_g + l * CH, ln1_b + l * CH, h);
        gemm_nn_k<0, 0><<<dim3(3 * CH / 128, BT / 128), 256>>>(
            h, attn_w + (size_t)l * CH * 3 * CH, attn_b + (size_t)l * 3 * CH,
            nullptr, qkv, BT, 3 * CH, CH);
        attn_k<<<dim3(TSEQ, NH, 4), 128>>>(qkv, y);
        gemm_nn_k<0, 1><<<dim3(CH / 128, BT / 128), 256>>>(
            y, proj_w + (size_t)l * CH * CH, proj_b + (size_t)l * CH,
            x, x, BT, CH, CH);
        ln_k<<<BT, 256>>>(x, ln2_g + l * CH, ln2_b + l * CH, h);
        gemm_nn_k<1, 0><<<dim3(4 * CH / 128, BT / 128), 256>>>(
            h, fc_w + (size_t)l * CH * 4 * CH, fc_b + (size_t)l * 4 * CH,
            nullptr, mbuf, BT, 4 * CH, CH);
        gemm_nn_k<0, 1><<<dim3(CH / 128, BT / 128), 256>>>(
            mbuf, fc2_w + (size_t)l * 4 * CH * CH, fc2_b + (size_t)l * CH,
            x, x, BT, CH, 4 * CH);
    }

    ln_k<<<BT, 256>>>(x, lnf_g, lnf_b, h);
    copy_k<<<(BT * CH + 255) / 256, 256>>>(h, out_x, BT * CH);
    gemm_nt_k<<<dim3(VOC / 128, BT / 128), 256>>>(h, wte, out, BT, VOC, CH);
    zero_loss_k<<<1, 1>>>(pnum, pden);
    loss_k<<<BT, 256>>>(out, targets, pnum, pden);
    final_loss_k<<<1, 1>>>(pnum, pden, out_loss);
}

// round 7
// speedup vs baseline: 1.6438x; 1.6438x over previous
#include <cuda_runtime.h>
#include <cuda_bf16.h>
#include <math.h>

// ---------------------------------------------------------------------------
// GPT-2 small forward: L=6, C=768, H=12, D=64, B=4, T=1024, V=32000
// Output layout: logits [4096*32000] | loss [1] | x_final [4096*768]
// Round 5: FFMA2 GEMMs with duplicated-A smem (no pack MOVs) and LDS.128
// B-fragment reads (bank-conflict-free-ish). Register-pipelined k-loop.
// ---------------------------------------------------------------------------

#define BT   4096
#define CH   768
#define NH   12
#define DH   64
#define TSEQ 1024
#define VOC  32000
#define NLAY 6

typedef unsigned long long ull;

// Scratch (device globals: no allocation allowed)
__device__ float g_x[BT * CH];
__device__ float g_h[BT * CH];
__device__ float g_qkv[BT * 3 * CH];
__device__ float g_y[BT * CH];
__device__ float g_m[BT * 4 * CH];
__device__ float g_num;
__device__ float g_den;

// ---------------------------------------------------------------------------
__global__ void embed_k(const int* __restrict__ idx, const float* __restrict__ wte,
                        const float* __restrict__ wpe, float* __restrict__ x) {
    int row = blockIdx.x;
    int t = row & (TSEQ - 1);
    int tok = idx[row];
    const float* a = wte + (size_t)tok * CH;
    const float* b = wpe + (size_t)t * CH;
    float* o = x + (size_t)row * CH;
    for (int c = threadIdx.x; c < CH; c += blockDim.x) o[c] = a[c] + b[c];
}

__global__ void copy_k(const float* __restrict__ src, float* __restrict__ dst, int n) {
    int i = blockIdx.x * blockDim.x + threadIdx.x;
    if (i < n) dst[i] = src[i];
}

// ---------------------------------------------------------------------------
__global__ void ln_k(const float* __restrict__ x, const float* __restrict__ g,
                     const float* __restrict__ b, float* __restrict__ o) {
    __shared__ float r1[256], r2[256];
    int row = blockIdx.x;
    const float* xr = x + (size_t)row * CH;
    float s = 0.f, s2 = 0.f;
    for (int i = threadIdx.x; i < CH; i += 256) { float v = xr[i]; s += v; s2 += v * v; }
    r1[threadIdx.x] = s; r2[threadIdx.x] = s2;
    __syncthreads();
    for (int off = 128; off > 0; off >>= 1) {
        if (threadIdx.x < off) {
            r1[threadIdx.x] += r1[threadIdx.x + off];
            r2[threadIdx.x] += r2[threadIdx.x + off];
        }
        __syncthreads();
    }
    float mean = r1[0] * (1.0f / CH);
    float var  = r2[0] * (1.0f / CH) - mean * mean;
    float rstd = rsqrtf(var + 1e-5f);
    float* orow = o + (size_t)row * CH;
    for (int i = threadIdx.x; i < CH; i += 256)
        orow[i] = (xr[i] - mean) * rstd * g[i] + b[i];
}

// ---------------------------------------------------------------------------
__device__ __forceinline__ void ffma2(ull& acc, ull a, ull b) {
    asm("fma.rn.f32x2 %0, %1, %2, %0;" : "+l"(acc) : "l"(a), "l"(b));
}
__device__ __forceinline__ float lo32(ull v) { return __uint_as_float((unsigned)v); }
__device__ __forceinline__ float hi32(ull v) { return __uint_as_float((unsigned)(v >> 32)); }

#define AS2W 272   // As2 row stride in floats (16B-aligned: 272*4=1088)
#define BSW  132   // Bs row stride in floats (528B, 16B-aligned)

// ---------------------------------------------------------------------------
// Tiled fp32 GEMM (FFMA2, dup-A smem, pipelined): C = act(A@B + bias) (+res)
// Tile 128x128x16, 256 threads, 8x8/thread. A 16B-aligned, K%16==0, M,N%128==0.
template <int ACT, int RES>
__global__ __launch_bounds__(256, 2)
void gemm_nn_k(const float* __restrict__ A, const float* __restrict__ B,
               const float* __restrict__ bias, const float* __restrict__ res,
               float* __restrict__ Cmat, int M, int N, int K) {
    __shared__ __align__(16) float As2[16][AS2W];  // duplicated: [kk][2m]=[kk][2m+1]=a_m
    __shared__ __align__(16) float Bs[16][BSW];
    int tid = threadIdx.x;
    int tx = tid & 15, ty = tid >> 4;
    int row0 = blockIdx.y * 128, col0 = blockIdx.x * 128;
    ull acc[8][4] = {};
    const float* Ab = A + (size_t)row0 * K;

    // per-thread load coords
    int am0 = tid >> 2,          akq0 = (tid & 3) * 4;
    int am1 = (tid + 256) >> 2,  akq1 = ((tid + 256) & 3) * 4;
    int bkk0 = tid >> 5,         bnq0 = (tid & 31) * 4;
    int bkk1 = (tid + 256) >> 5, bnq1 = ((tid + 256) & 31) * 4;

    float4 pa0, pa1, pb0, pb1;
    pa0 = *reinterpret_cast<const float4*>(&Ab[(size_t)am0 * K + akq0]);
    pa1 = *reinterpret_cast<const float4*>(&Ab[(size_t)am1 * K + akq1]);
    pb0 = *reinterpret_cast<const float4*>(&B[(size_t)bkk0 * N + col0 + bnq0]);
    pb1 = *reinterpret_cast<const float4*>(&B[(size_t)bkk1 * N + col0 + bnq1]);
    // duplicated stores: one STS.64 of (v,v) per element
    *reinterpret_cast<float2*>(&As2[akq0 + 0][2 * am0]) = make_float2(pa0.x, pa0.x);
    *reinterpret_cast<float2*>(&As2[akq0 + 1][2 * am0]) = make_float2(pa0.y, pa0.y);
    *reinterpret_cast<float2*>(&As2[akq0 + 2][2 * am0]) = make_float2(pa0.z, pa0.z);
    *reinterpret_cast<float2*>(&As2[akq0 + 3][2 * am0]) = make_float2(pa0.w, pa0.w);
    *reinterpret_cast<float2*>(&As2[akq1 + 0][2 * am1]) = make_float2(pa1.x, pa1.x);
    *reinterpret_cast<float2*>(&As2[akq1 + 1][2 * am1]) = make_float2(pa1.y, pa1.y);
    *reinterpret_cast<float2*>(&As2[akq1 + 2][2 * am1]) = make_float2(pa1.z, pa1.z);
    *reinterpret_cast<float2*>(&As2[akq1 + 3][2 * am1]) = make_float2(pa1.w, pa1.w);
    *reinterpret_cast<float4*>(&Bs[bkk0][bnq0]) = pb0;
    *reinterpret_cast<float4*>(&Bs[bkk1][bnq1]) = pb1;
    __syncthreads();

    int nS = K >> 4;
    for (int s = 0; s < nS; s++) {
        bool more = (s + 1) < nS;
        int k0n = (s + 1) << 4;
        if (more) {
            pa0 = *reinterpret_cast<const float4*>(&Ab[(size_t)am0 * K + k0n + akq0]);
            pa1 = *reinterpret_cast<const float4*>(&Ab[(size_t)am1 * K + k0n + akq1]);
            pb0 = *reinterpret_cast<const float4*>(&B[(size_t)(k0n + bkk0) * N + col0 + bnq0]);
            pb1 = *reinterpret_cast<const float4*>(&B[(size_t)(k0n + bkk1) * N + col0 + bnq1]);
        }
#pragma unroll
        for (int kk = 0; kk < 16; kk++) {
            const ulonglong2* aq = reinterpret_cast<const ulonglong2*>(&As2[kk][ty * 16]);
            ulonglong2 A01 = aq[0], A23 = aq[1], A45 = aq[2], A67 = aq[3];
            const ulonglong2* bqv = reinterpret_cast<const ulonglong2*>(&Bs[kk][tx * 8]);
            ulonglong2 B01 = bqv[0], B23 = bqv[1];
            ull ap[8] = {A01.x, A01.y, A23.x, A23.y, A45.x, A45.y, A67.x, A67.y};
#pragma unroll
            for (int i = 0; i < 8; i++) {
                ffma2(acc[i][0], ap[i], B01.x);
                ffma2(acc[i][1], ap[i], B01.y);
                ffma2(acc[i][2], ap[i], B23.x);
                ffma2(acc[i][3], ap[i], B23.y);
            }
        }
        __syncthreads();
        if (more) {
            *reinterpret_cast<float2*>(&As2[akq0 + 0][2 * am0]) = make_float2(pa0.x, pa0.x);
            *reinterpret_cast<float2*>(&As2[akq0 + 1][2 * am0]) = make_float2(pa0.y, pa0.y);
            *reinterpret_cast<float2*>(&As2[akq0 + 2][2 * am0]) = make_float2(pa0.z, pa0.z);
            *reinterpret_cast<float2*>(&As2[akq0 + 3][2 * am0]) = make_float2(pa0.w, pa0.w);
            *reinterpret_cast<float2*>(&As2[akq1 + 0][2 * am1]) = make_float2(pa1.x, pa1.x);
            *reinterpret_cast<float2*>(&As2[akq1 + 1][2 * am1]) = make_float2(pa1.y, pa1.y);
            *reinterpret_cast<float2*>(&As2[akq1 + 2][2 * am1]) = make_float2(pa1.z, pa1.z);
            *reinterpret_cast<float2*>(&As2[akq1 + 3][2 * am1]) = make_float2(pa1.w, pa1.w);
            *reinterpret_cast<float4*>(&Bs[bkk0][bnq0]) = pb0;
            *reinterpret_cast<float4*>(&Bs[bkk1][bnq1]) = pb1;
            __syncthreads();
        }
    }
#pragma unroll
    for (int i = 0; i < 8; i++) {
        int r = row0 + ty * 8 + i;
#pragma unroll
        for (int j = 0; j < 4; j++) {
            int c = col0 + tx * 8 + j * 2;
            float v0 = lo32(acc[i][j]) + bias[c];
            float v1 = hi32(acc[i][j]) + bias[c + 1];
            if (ACT == 1) {
                v0 = 0.5f * v0 * (1.0f + erff(v0 * 0.70710678118654752440f));
                v1 = 0.5f * v1 * (1.0f + erff(v1 * 0.70710678118654752440f));
            }
            if (RES == 1) {
                float2 rv = *reinterpret_cast<const float2*>(&res[(size_t)r * N + c]);
                v0 += rv.x; v1 += rv.y;
            }
            float2 ov = make_float2(v0, v1);
            *reinterpret_cast<float2*>(&Cmat[(size_t)r * N + c]) = ov;
        }
    }
}

// ---------------------------------------------------------------------------
// NT GEMM (FFMA2, dup-A smem, pipelined): C[M,N] = A[M,K] @ W[N,K]^T
__global__ __launch_bounds__(256, 2)
void gemm_nt_k(const float* __restrict__ A, const float* __restrict__ W,
               float* __restrict__ Cmat, int M, int N, int K) {
    __shared__ __align__(16) float As2[16][AS2W];
    __shared__ __align__(16) float Bs[16][BSW];
    int tid = threadIdx.x;
    int tx = tid & 15, ty = tid >> 4;
    int row0 = blockIdx.y * 128, col0 = blockIdx.x * 128;
    ull acc[8][4] = {};
    const float* Ab = A + (size_t)row0 * K;
    const float* Wb = W + (size_t)col0 * K;

    int am0 = tid >> 2,          akq0 = (tid & 3) * 4;
    int am1 = (tid + 256) >> 2,  akq1 = ((tid + 256) & 3) * 4;

    float4 pa0, pa1, pb0, pb1;
    pa0 = *reinterpret_cast<const float4*>(&Ab[(size_t)am0 * K + akq0]);
    pa1 = *reinterpret_cast<const float4*>(&Ab[(size_t)am1 * K + akq1]);
    pb0 = *reinterpret_cast<const float4*>(&Wb[(size_t)am0 * K + akq0]);
    pb1 = *reinterpret_cast<const float4*>(&Wb[(size_t)am1 * K + akq1]);
    *reinterpret_cast<float2*>(&As2[akq0 + 0][2 * am0]) = make_float2(pa0.x, pa0.x);
    *reinterpret_cast<float2*>(&As2[akq0 + 1][2 * am0]) = make_float2(pa0.y, pa0.y);
    *reinterpret_cast<float2*>(&As2[akq0 + 2][2 * am0]) = make_float2(pa0.z, pa0.z);
    *reinterpret_cast<float2*>(&As2[akq0 + 3][2 * am0]) = make_float2(pa0.w, pa0.w);
    *reinterpret_cast<float2*>(&As2[akq1 + 0][2 * am1]) = make_float2(pa1.x, pa1.x);
    *reinterpret_cast<float2*>(&As2[akq1 + 1][2 * am1]) = make_float2(pa1.y, pa1.y);
    *reinterpret_cast<float2*>(&As2[akq1 + 2][2 * am1]) = make_float2(pa1.z, pa1.z);
    *reinterpret_cast<float2*>(&As2[akq1 + 3][2 * am1]) = make_float2(pa1.w, pa1.w);
    Bs[akq0 + 0][am0] = pb0.x; Bs[akq0 + 1][am0] = pb0.y;
    Bs[akq0 + 2][am0] = pb0.z; Bs[akq0 + 3][am0] = pb0.w;
    Bs[akq1 + 0][am1] = pb1.x; Bs[akq1 + 1][am1] = pb1.y;
    Bs[akq1 + 2][am1] = pb1.z; Bs[akq1 + 3][am1] = pb1.w;
    __syncthreads();

    int nS = K >> 4;
    for (int s = 0; s < nS; s++) {
        bool more = (s + 1) < nS;
        int k0n = (s + 1) << 4;
        if (more) {
            pa0 = *reinterpret_cast<const float4*>(&Ab[(size_t)am0 * K + k0n + akq0]);
            pa1 = *reinterpret_cast<const float4*>(&Ab[(size_t)am1 * K + k0n + akq1]);
            pb0 = *reinterpret_cast<const float4*>(&Wb[(size_t)am0 * K + k0n + akq0]);
            pb1 = *reinterpret_cast<const float4*>(&Wb[(size_t)am1 * K + k0n + akq1]);
        }
#pragma unroll
        for (int kk = 0; kk < 16; kk++) {
            const ulonglong2* aq = reinterpret_cast<const ulonglong2*>(&As2[kk][ty * 16]);
            ulonglong2 A01 = aq[0], A23 = aq[1], A45 = aq[2], A67 = aq[3];
            const ulonglong2* bqv = reinterpret_cast<const ulonglong2*>(&Bs[kk][tx * 8]);
            ulonglong2 B01 = bqv[0], B23 = bqv[1];
            ull ap[8] = {A01.x, A01.y, A23.x, A23.y, A45.x, A45.y, A67.x, A67.y};
#pragma unroll
            for (int i = 0; i < 8; i++) {
                ffma2(acc[i][0], ap[i], B01.x);
                ffma2(acc[i][1], ap[i], B01.y);
                ffma2(acc[i][2], ap[i], B23.x);
                ffma2(acc[i][3], ap[i], B23.y);
            }
        }
        __syncthreads();
        if (more) {
            *reinterpret_cast<float2*>(&As2[akq0 + 0][2 * am0]) = make_float2(pa0.x, pa0.x);
            *reinterpret_cast<float2*>(&As2[akq0 + 1][2 * am0]) = make_float2(pa0.y, pa0.y);
            *reinterpret_cast<float2*>(&As2[akq0 + 2][2 * am0]) = make_float2(pa0.z, pa0.z);
            *reinterpret_cast<float2*>(&As2[akq0 + 3][2 * am0]) = make_float2(pa0.w, pa0.w);
            *reinterpret_cast<float2*>(&As2[akq1 + 0][2 * am1]) = make_float2(pa1.x, pa1.x);
            *reinterpret_cast<float2*>(&As2[akq1 + 1][2 * am1]) = make_float2(pa1.y, pa1.y);
            *reinterpret_cast<float2*>(&As2[akq1 + 2][2 * am1]) = make_float2(pa1.z, pa1.z);
            *reinterpret_cast<float2*>(&As2[akq1 + 3][2 * am1]) = make_float2(pa1.w, pa1.w);
            Bs[akq0 + 0][am0] = pb0.x; Bs[akq0 + 1][am0] = pb0.y;
            Bs[akq0 + 2][am0] = pb0.z; Bs[akq0 + 3][am0] = pb0.w;
            Bs[akq1 + 0][am1] = pb1.x; Bs[akq1 + 1][am1] = pb1.y;
            Bs[akq1 + 2][am1] = pb1.z; Bs[akq1 + 3][am1] = pb1.w;
            __syncthreads();
        }
    }
#pragma unroll
    for (int i = 0; i < 8; i++) {
        int r = row0 + ty * 8 + i;
#pragma unroll
        for (int j = 0; j < 4; j++) {
            int c = col0 + tx * 8 + j * 2;
            float2 ov = make_float2(lo32(acc[i][j]), hi32(acc[i][j]));
            *reinterpret_cast<float2*>(&Cmat[(size_t)r * N + c]) = ov;
        }
    }
}

// ---------------------------------------------------------------------------
// Causal attention, one block per (t, h, b).
__global__ void attn_k(const float* __restrict__ qkv, float* __restrict__ y) {
    __shared__ float qs[DH];
    __shared__ float sc[TSEQ];
    __shared__ float red[128];
    int t = blockIdx.x, h = blockIdx.y, b = blockIdx.z;
    int tid = threadIdx.x;
    const float* base = qkv + (size_t)b * TSEQ * (3 * CH);
    if (tid < DH) qs[tid] = base[(size_t)t * (3 * CH) + h * DH + tid];
    __syncthreads();
    int nS = t + 1;
    float lmax = -3.0e38f;
    for (int s = tid; s < nS; s += 128) {
        const float* kr = base + (size_t)s * (3 * CH) + CH + h * DH;
        float d = 0.f;
#pragma unroll
        for (int i = 0; i < DH; i++) d += qs[i] * kr[i];
        d *= 0.125f;
        sc[s] = d;
        lmax = fmaxf(lmax, d);
    }
    red[tid] = lmax;
    __syncthreads();
    for (int off = 64; off > 0; off >>= 1) {
        if (tid < off) red[tid] = fmaxf(red[tid], red[tid + off]);
        __syncthreads();
    }
    float mx = red[0];
    __syncthreads();
    float lsum = 0.f;
    for (int s = tid; s < nS; s += 128) {
        float e = __expf(sc[s] - mx);
        sc[s] = e;
        lsum += e;
    }
    red[tid] = lsum;
    __syncthreads();
    for (int off = 64; off > 0; off >>= 1) {
        if (tid < off) red[tid] += red[tid + off];
        __syncthreads();
    }
    float inv = 1.0f / red[0];
    __syncthreads();
    if (tid < DH) {
        const float* vr = base + 2 * CH + h * DH + tid;
        float acc = 0.f;
        for (int s = 0; s < nS; s++) acc += sc[s] * vr[(size_t)s * (3 * CH)];
        y[((size_t)(b * TSEQ + t)) * CH + h * DH + tid] = acc * inv;
    }
}

// ---------------------------------------------------------------------------
__global__ void zero_loss_k(float* num, float* den) { *num = 0.f; *den = 0.f; }

__global__ void loss_k(const float* __restrict__ logits, const int* __restrict__ tg,
                       float* num, float* den) {
    __shared__ float red[256];
    int row = blockIdx.x;
    const float* lr = logits + (size_t)row * VOC;
    float m = -3.0e38f;
    for (int j = threadIdx.x; j < VOC; j += 256) m = fmaxf(m, lr[j]);
    red[threadIdx.x] = m;
    __syncthreads();
    for (int off = 128; off > 0; off >>= 1) {
        if (threadIdx.x < off) red[threadIdx.x] = fmaxf(red[threadIdx.x], red[threadIdx.x + off]);
        __syncthreads();
    }
    m = red[0];
    __syncthreads();
    float s = 0.f;
    for (int j = threadIdx.x; j < VOC; j += 256) s += __expf(lr[j] - m);
    red[threadIdx.x] = s;
    __syncthreads();
    for (int off = 128; off > 0; off >>= 1) {
        if (threadIdx.x < off) red[threadIdx.x] += red[threadIdx.x + off];
        __syncthreads();
    }
    if (threadIdx.x == 0) {
        int t = tg[row];
        if (t != 0) {
            float lse = m + logf(red[0]);
            float nll = lse - lr[t];
            atomicAdd(num, nll);
            atomicAdd(den, 1.0f);
        }
    }
}

__global__ void final_loss_k(const float* num, const float* den, float* out) {
    out[0] = *num / fmaxf(*den, 1.0f);
}

// ---------------------------------------------------------------------------
extern "C" void kernel_launch(void* const* d_in, const int* in_sizes, int n_in,
                              void* d_out, int out_size) {
    const int*   idx     = (const int*)d_in[0];
    const int*   targets = (const int*)d_in[1];
    const float* wte     = (const float*)d_in[2];
    const float* wpe     = (const float*)d_in[3];
    const float* ln1_g   = (const float*)d_in[4];
    const float* ln1_b   = (const float*)d_in[5];
    const float* attn_w  = (const float*)d_in[6];
    const float* attn_b  = (const float*)d_in[7];
    const float* proj_w  = (const float*)d_in[8];
    const float* proj_b  = (const float*)d_in[9];
    const float* ln2_g   = (const float*)d_in[10];
    const float* ln2_b   = (const float*)d_in[11];
    const float* fc_w    = (const float*)d_in[12];
    const float* fc_b    = (const float*)d_in[13];
    const float* fc2_w   = (const float*)d_in[14];
    const float* fc2_b   = (const float*)d_in[15];
    const float* lnf_g   = (const float*)d_in[16];
    const float* lnf_b   = (const float*)d_in[17];
    float* out = (float*)d_out;

    float *x, *h, *qkv, *y, *mbuf, *pnum, *pden;
    cudaGetSymbolAddress((void**)&x, g_x);
    cudaGetSymbolAddress((void**)&h, g_h);
    cudaGetSymbolAddress((void**)&qkv, g_qkv);
    cudaGetSymbolAddress((void**)&y, g_y);
    cudaGetSymbolAddress((void**)&mbuf, g_m);
    cudaGetSymbolAddress((void**)&pnum, g_num);
    cudaGetSymbolAddress((void**)&pden, g_den);

    const size_t LOGN = (size_t)BT * VOC;
    float* out_loss = out + LOGN;
    float* out_x    = out + LOGN + 1;  // 4B-aligned only: scalar access

    embed_k<<<BT, 256>>>(idx, wte, wpe, x);

    for (int l = 0; l < NLAY; l++) {
        ln_k<<<BT, 256>>>(x, ln1_g + l * CH, ln1_b + l * CH, h);
        gemm_nn_k<0, 0><<<dim3(3 * CH / 128, BT / 128), 256>>>(
            h, attn_w + (size_t)l * CH * 3 * CH, attn_b + (size_t)l * 3 * CH,
            nullptr, qkv, BT, 3 * CH, CH);
        attn_k<<<dim3(TSEQ, NH, 4), 128>>>(qkv, y);
        gemm_nn_k<0, 1><<<dim3(CH / 128, BT / 128), 256>>>(
            y, proj_w + (size_t)l * CH * CH, proj_b + (size_t)l * CH,
            x, x, BT, CH, CH);
        ln_k<<<BT, 256>>>(x, ln2_g + l * CH, ln2_b + l * CH, h);
        gemm_nn_k<1, 0><<<dim3(4 * CH / 128, BT / 128), 256>>>(
            h, fc_w + (size_t)l * CH * 4 * CH, fc_b + (size_t)l * 4 * CH,
            nullptr, mbuf, BT, 4 * CH, CH);
        gemm_nn_k<0, 1><<<dim3(CH / 128, BT / 128), 256>>>(
            mbuf, fc2_w + (size_t)l * 4 * CH * CH, fc2_b + (size_t)l * CH,
            x, x, BT, CH, 4 * CH);
    }

    ln_k<<<BT, 256>>>(x, lnf_g, lnf_b, h);
    copy_k<<<(BT * CH + 255) / 256, 256>>>(h, out_x, BT * CH);
    gemm_nt_k<<<dim3(VOC / 128, BT / 128), 256>>>(h, wte, out, BT, VOC, CH);
    zero_loss_k<<<1, 1>>>(pnum, pden);
    loss_k<<<BT, 256>>>(out, targets, pnum, pden);
    final_loss_k<<<1, 1>>>(pnum, pden, out_loss);
}

// round 8
// speedup vs baseline: 1.6442x; 1.0002x over previous
#include <cuda_runtime.h>
#include <cuda_bf16.h>
#include <math.h>

// ---------------------------------------------------------------------------
// GPT-2 small forward: L=6, C=768, H=12, D=64, B=4, T=1024, V=32000
// Output layout: logits [4096*32000] | loss [1] | x_final [4096*768]
// Round 5: FFMA2 GEMMs with duplicated-A smem (no pack MOVs) and LDS.128
// B-fragment reads (bank-conflict-free-ish). Register-pipelined k-loop.
// ---------------------------------------------------------------------------

#define BT   4096
#define CH   768
#define NH   12
#define DH   64
#define TSEQ 1024
#define VOC  32000
#define NLAY 6

typedef unsigned long long ull;

// Scratch (device globals: no allocation allowed)
__device__ float g_x[BT * CH];
__device__ float g_h[BT * CH];
__device__ float g_qkv[BT * 3 * CH];
__device__ float g_y[BT * CH];
__device__ float g_m[BT * 4 * CH];
__device__ float g_num;
__device__ float g_den;

// ---------------------------------------------------------------------------
__global__ void embed_k(const int* __restrict__ idx, const float* __restrict__ wte,
                        const float* __restrict__ wpe, float* __restrict__ x) {
    int row = blockIdx.x;
    int t = row & (TSEQ - 1);
    int tok = idx[row];
    const float* a = wte + (size_t)tok * CH;
    const float* b = wpe + (size_t)t * CH;
    float* o = x + (size_t)row * CH;
    for (int c = threadIdx.x; c < CH; c += blockDim.x) o[c] = a[c] + b[c];
}

__global__ void copy_k(const float* __restrict__ src, float* __restrict__ dst, int n) {
    int i = blockIdx.x * blockDim.x + threadIdx.x;
    if (i < n) dst[i] = src[i];
}

// ---------------------------------------------------------------------------
__global__ void ln_k(const float* __restrict__ x, const float* __restrict__ g,
                     const float* __restrict__ b, float* __restrict__ o) {
    __shared__ float r1[256], r2[256];
    int row = blockIdx.x;
    const float* xr = x + (size_t)row * CH;
    float s = 0.f, s2 = 0.f;
    for (int i = threadIdx.x; i < CH; i += 256) { float v = xr[i]; s += v; s2 += v * v; }
    r1[threadIdx.x] = s; r2[threadIdx.x] = s2;
    __syncthreads();
    for (int off = 128; off > 0; off >>= 1) {
        if (threadIdx.x < off) {
            r1[threadIdx.x] += r1[threadIdx.x + off];
            r2[threadIdx.x] += r2[threadIdx.x + off];
        }
        __syncthreads();
    }
    float mean = r1[0] * (1.0f / CH);
    float var  = r2[0] * (1.0f / CH) - mean * mean;
    float rstd = rsqrtf(var + 1e-5f);
    float* orow = o + (size_t)row * CH;
    for (int i = threadIdx.x; i < CH; i += 256)
        orow[i] = (xr[i] - mean) * rstd * g[i] + b[i];
}

// ---------------------------------------------------------------------------
__device__ __forceinline__ void ffma2(ull& acc, ull a, ull b) {
    asm("fma.rn.f32x2 %0, %1, %2, %0;" : "+l"(acc) : "l"(a), "l"(b));
}
__device__ __forceinline__ float lo32(ull v) { return __uint_as_float((unsigned)v); }
__device__ __forceinline__ float hi32(ull v) { return __uint_as_float((unsigned)(v >> 32)); }

#define AS2W 272   // As2 row stride in floats (16B-aligned: 272*4=1088)
#define BSW  132   // Bs row stride in floats (528B, 16B-aligned)

// ---------------------------------------------------------------------------
// Tiled fp32 GEMM (FFMA2, dup-A smem, pipelined): C = act(A@B + bias) (+res)
// Tile 128x128x16, 256 threads, 8x8/thread. A 16B-aligned, K%16==0, M,N%128==0.
template <int ACT, int RES>
__global__ __launch_bounds__(256, 2)
void gemm_nn_k(const float* __restrict__ A, const float* __restrict__ B,
               const float* __restrict__ bias, const float* __restrict__ res,
               float* __restrict__ Cmat, int M, int N, int K) {
    __shared__ __align__(16) float As2[16][AS2W];  // duplicated: [kk][2m]=[kk][2m+1]=a_m
    __shared__ __align__(16) float Bs[16][BSW];
    int tid = threadIdx.x;
    int tx = tid & 15, ty = tid >> 4;
    int row0 = blockIdx.y * 128, col0 = blockIdx.x * 128;
    ull acc[8][4] = {};
    const float* Ab = A + (size_t)row0 * K;

    // per-thread load coords
    int am0 = tid >> 2,          akq0 = (tid & 3) * 4;
    int am1 = (tid + 256) >> 2,  akq1 = ((tid + 256) & 3) * 4;
    int bkk0 = tid >> 5,         bnq0 = (tid & 31) * 4;
    int bkk1 = (tid + 256) >> 5, bnq1 = ((tid + 256) & 31) * 4;

    float4 pa0, pa1, pb0, pb1;
    pa0 = *reinterpret_cast<const float4*>(&Ab[(size_t)am0 * K + akq0]);
    pa1 = *reinterpret_cast<const float4*>(&Ab[(size_t)am1 * K + akq1]);
    pb0 = *reinterpret_cast<const float4*>(&B[(size_t)bkk0 * N + col0 + bnq0]);
    pb1 = *reinterpret_cast<const float4*>(&B[(size_t)bkk1 * N + col0 + bnq1]);
    // duplicated stores: one STS.64 of (v,v) per element
    *reinterpret_cast<float2*>(&As2[akq0 + 0][2 * am0]) = make_float2(pa0.x, pa0.x);
    *reinterpret_cast<float2*>(&As2[akq0 + 1][2 * am0]) = make_float2(pa0.y, pa0.y);
    *reinterpret_cast<float2*>(&As2[akq0 + 2][2 * am0]) = make_float2(pa0.z, pa0.z);
    *reinterpret_cast<float2*>(&As2[akq0 + 3][2 * am0]) = make_float2(pa0.w, pa0.w);
    *reinterpret_cast<float2*>(&As2[akq1 + 0][2 * am1]) = make_float2(pa1.x, pa1.x);
    *reinterpret_cast<float2*>(&As2[akq1 + 1][2 * am1]) = make_float2(pa1.y, pa1.y);
    *reinterpret_cast<float2*>(&As2[akq1 + 2][2 * am1]) = make_float2(pa1.z, pa1.z);
    *reinterpret_cast<float2*>(&As2[akq1 + 3][2 * am1]) = make_float2(pa1.w, pa1.w);
    *reinterpret_cast<float4*>(&Bs[bkk0][bnq0]) = pb0;
    *reinterpret_cast<float4*>(&Bs[bkk1][bnq1]) = pb1;
    __syncthreads();

    int nS = K >> 4;
    for (int s = 0; s < nS; s++) {
        bool more = (s + 1) < nS;
        int k0n = (s + 1) << 4;
        if (more) {
            pa0 = *reinterpret_cast<const float4*>(&Ab[(size_t)am0 * K + k0n + akq0]);
            pa1 = *reinterpret_cast<const float4*>(&Ab[(size_t)am1 * K + k0n + akq1]);
            pb0 = *reinterpret_cast<const float4*>(&B[(size_t)(k0n + bkk0) * N + col0 + bnq0]);
            pb1 = *reinterpret_cast<const float4*>(&B[(size_t)(k0n + bkk1) * N + col0 + bnq1]);
        }
#pragma unroll
        for (int kk = 0; kk < 16; kk++) {
            const ulonglong2* aq = reinterpret_cast<const ulonglong2*>(&As2[kk][ty * 16]);
            ulonglong2 A01 = aq[0], A23 = aq[1], A45 = aq[2], A67 = aq[3];
            const ulonglong2* bqv = reinterpret_cast<const ulonglong2*>(&Bs[kk][tx * 8]);
            ulonglong2 B01 = bqv[0], B23 = bqv[1];
            ull ap[8] = {A01.x, A01.y, A23.x, A23.y, A45.x, A45.y, A67.x, A67.y};
#pragma unroll
            for (int i = 0; i < 8; i++) {
                ffma2(acc[i][0], ap[i], B01.x);
                ffma2(acc[i][1], ap[i], B01.y);
                ffma2(acc[i][2], ap[i], B23.x);
                ffma2(acc[i][3], ap[i], B23.y);
            }
        }
        __syncthreads();
        if (more) {
            *reinterpret_cast<float2*>(&As2[akq0 + 0][2 * am0]) = make_float2(pa0.x, pa0.x);
            *reinterpret_cast<float2*>(&As2[akq0 + 1][2 * am0]) = make_float2(pa0.y, pa0.y);
            *reinterpret_cast<float2*>(&As2[akq0 + 2][2 * am0]) = make_float2(pa0.z, pa0.z);
            *reinterpret_cast<float2*>(&As2[akq0 + 3][2 * am0]) = make_float2(pa0.w, pa0.w);
            *reinterpret_cast<float2*>(&As2[akq1 + 0][2 * am1]) = make_float2(pa1.x, pa1.x);
            *reinterpret_cast<float2*>(&As2[akq1 + 1][2 * am1]) = make_float2(pa1.y, pa1.y);
            *reinterpret_cast<float2*>(&As2[akq1 + 2][2 * am1]) = make_float2(pa1.z, pa1.z);
            *reinterpret_cast<float2*>(&As2[akq1 + 3][2 * am1]) = make_float2(pa1.w, pa1.w);
            *reinterpret_cast<float4*>(&Bs[bkk0][bnq0]) = pb0;
            *reinterpret_cast<float4*>(&Bs[bkk1][bnq1]) = pb1;
            __syncthreads();
        }
    }
#pragma unroll
    for (int i = 0; i < 8; i++) {
        int r = row0 + ty * 8 + i;
#pragma unroll
        for (int j = 0; j < 4; j++) {
            int c = col0 + tx * 8 + j * 2;
            float v0 = lo32(acc[i][j]) + bias[c];
            float v1 = hi32(acc[i][j]) + bias[c + 1];
            if (ACT == 1) {
                v0 = 0.5f * v0 * (1.0f + erff(v0 * 0.70710678118654752440f));
                v1 = 0.5f * v1 * (1.0f + erff(v1 * 0.70710678118654752440f));
            }
            if (RES == 1) {
                float2 rv = *reinterpret_cast<const float2*>(&res[(size_t)r * N + c]);
                v0 += rv.x; v1 += rv.y;
            }
            float2 ov = make_float2(v0, v1);
            *reinterpret_cast<float2*>(&Cmat[(size_t)r * N + c]) = ov;
        }
    }
}

// ---------------------------------------------------------------------------
// NT GEMM (FFMA2, dup-A smem, pipelined): C[M,N] = A[M,K] @ W[N,K]^T
__global__ __launch_bounds__(256, 2)
void gemm_nt_k(const float* __restrict__ A, const float* __restrict__ W,
               float* __restrict__ Cmat, int M, int N, int K) {
    __shared__ __align__(16) float As2[16][AS2W];
    __shared__ __align__(16) float Bs[16][BSW];
    int tid = threadIdx.x;
    int tx = tid & 15, ty = tid >> 4;
    int row0 = blockIdx.y * 128, col0 = blockIdx.x * 128;
    ull acc[8][4] = {};
    const float* Ab = A + (size_t)row0 * K;
    const float* Wb = W + (size_t)col0 * K;

    int am0 = tid >> 2,          akq0 = (tid & 3) * 4;
    int am1 = (tid + 256) >> 2,  akq1 = ((tid + 256) & 3) * 4;

    float4 pa0, pa1, pb0, pb1;
    pa0 = *reinterpret_cast<const float4*>(&Ab[(size_t)am0 * K + akq0]);
    pa1 = *reinterpret_cast<const float4*>(&Ab[(size_t)am1 * K + akq1]);
    pb0 = *reinterpret_cast<const float4*>(&Wb[(size_t)am0 * K + akq0]);
    pb1 = *reinterpret_cast<const float4*>(&Wb[(size_t)am1 * K + akq1]);
    *reinterpret_cast<float2*>(&As2[akq0 + 0][2 * am0]) = make_float2(pa0.x, pa0.x);
    *reinterpret_cast<float2*>(&As2[akq0 + 1][2 * am0]) = make_float2(pa0.y, pa0.y);
    *reinterpret_cast<float2*>(&As2[akq0 + 2][2 * am0]) = make_float2(pa0.z, pa0.z);
    *reinterpret_cast<float2*>(&As2[akq0 + 3][2 * am0]) = make_float2(pa0.w, pa0.w);
    *reinterpret_cast<float2*>(&As2[akq1 + 0][2 * am1]) = make_float2(pa1.x, pa1.x);
    *reinterpret_cast<float2*>(&As2[akq1 + 1][2 * am1]) = make_float2(pa1.y, pa1.y);
    *reinterpret_cast<float2*>(&As2[akq1 + 2][2 * am1]) = make_float2(pa1.z, pa1.z);
    *reinterpret_cast<float2*>(&As2[akq1 + 3][2 * am1]) = make_float2(pa1.w, pa1.w);
    Bs[akq0 + 0][am0] = pb0.x; Bs[akq0 + 1][am0] = pb0.y;
    Bs[akq0 + 2][am0] = pb0.z; Bs[akq0 + 3][am0] = pb0.w;
    Bs[akq1 + 0][am1] = pb1.x; Bs[akq1 + 1][am1] = pb1.y;
    Bs[akq1 + 2][am1] = pb1.z; Bs[akq1 + 3][am1] = pb1.w;
    __syncthreads();

    int nS = K >> 4;
    for (int s = 0; s < nS; s++) {
        bool more = (s + 1) < nS;
        int k0n = (s + 1) << 4;
        if (more) {
            pa0 = *reinterpret_cast<const float4*>(&Ab[(size_t)am0 * K + k0n + akq0]);
            pa1 = *reinterpret_cast<const float4*>(&Ab[(size_t)am1 * K + k0n + akq1]);
            pb0 = *reinterpret_cast<const float4*>(&Wb[(size_t)am0 * K + k0n + akq0]);
            pb1 = *reinterpret_cast<const float4*>(&Wb[(size_t)am1 * K + k0n + akq1]);
        }
#pragma unroll
        for (int kk = 0; kk < 16; kk++) {
            const ulonglong2* aq = reinterpret_cast<const ulonglong2*>(&As2[kk][ty * 16]);
            ulonglong2 A01 = aq[0], A23 = aq[1], A45 = aq[2], A67 = aq[3];
            const ulonglong2* bqv = reinterpret_cast<const ulonglong2*>(&Bs[kk][tx * 8]);
            ulonglong2 B01 = bqv[0], B23 = bqv[1];
            ull ap[8] = {A01.x, A01.y, A23.x, A23.y, A45.x, A45.y, A67.x, A67.y};
#pragma unroll
            for (int i = 0; i < 8; i++) {
                ffma2(acc[i][0], ap[i], B01.x);
                ffma2(acc[i][1], ap[i], B01.y);
                ffma2(acc[i][2], ap[i], B23.x);
                ffma2(acc[i][3], ap[i], B23.y);
            }
        }
        __syncthreads();
        if (more) {
            *reinterpret_cast<float2*>(&As2[akq0 + 0][2 * am0]) = make_float2(pa0.x, pa0.x);
            *reinterpret_cast<float2*>(&As2[akq0 + 1][2 * am0]) = make_float2(pa0.y, pa0.y);
            *reinterpret_cast<float2*>(&As2[akq0 + 2][2 * am0]) = make_float2(pa0.z, pa0.z);
            *reinterpret_cast<float2*>(&As2[akq0 + 3][2 * am0]) = make_float2(pa0.w, pa0.w);
            *reinterpret_cast<float2*>(&As2[akq1 + 0][2 * am1]) = make_float2(pa1.x, pa1.x);
            *reinterpret_cast<float2*>(&As2[akq1 + 1][2 * am1]) = make_float2(pa1.y, pa1.y);
            *reinterpret_cast<float2*>(&As2[akq1 + 2][2 * am1]) = make_float2(pa1.z, pa1.z);
            *reinterpret_cast<float2*>(&As2[akq1 + 3][2 * am1]) = make_float2(pa1.w, pa1.w);
            Bs[akq0 + 0][am0] = pb0.x; Bs[akq0 + 1][am0] = pb0.y;
            Bs[akq0 + 2][am0] = pb0.z; Bs[akq0 + 3][am0] = pb0.w;
            Bs[akq1 + 0][am1] = pb1.x; Bs[akq1 + 1][am1] = pb1.y;
            Bs[akq1 + 2][am1] = pb1.z; Bs[akq1 + 3][am1] = pb1.w;
            __syncthreads();
        }
    }
#pragma unroll
    for (int i = 0; i < 8; i++) {
        int r = row0 + ty * 8 + i;
#pragma unroll
        for (int j = 0; j < 4; j++) {
            int c = col0 + tx * 8 + j * 2;
            float2 ov = make_float2(lo32(acc[i][j]), hi32(acc[i][j]));
            *reinterpret_cast<float2*>(&Cmat[(size_t)r * N + c]) = ov;
        }
    }
}

// ---------------------------------------------------------------------------
// Causal attention, one block per (t, h, b).
__global__ void attn_k(const float* __restrict__ qkv, float* __restrict__ y) {
    __shared__ float qs[DH];
    __shared__ float sc[TSEQ];
    __shared__ float red[128];
    int t = blockIdx.x, h = blockIdx.y, b = blockIdx.z;
    int tid = threadIdx.x;
    const float* base = qkv + (size_t)b * TSEQ * (3 * CH);
    if (tid < DH) qs[tid] = base[(size_t)t * (3 * CH) + h * DH + tid];
    __syncthreads();
    int nS = t + 1;
    float lmax = -3.0e38f;
    for (int s = tid; s < nS; s += 128) {
        const float* kr = base + (size_t)s * (3 * CH) + CH + h * DH;
        float d = 0.f;
#pragma unroll
        for (int i = 0; i < DH; i++) d += qs[i] * kr[i];
        d *= 0.125f;
        sc[s] = d;
        lmax = fmaxf(lmax, d);
    }
    red[tid] = lmax;
    __syncthreads();
    for (int off = 64; off > 0; off >>= 1) {
        if (tid < off) red[tid] = fmaxf(red[tid], red[tid + off]);
        __syncthreads();
    }
    float mx = red[0];
    __syncthreads();
    float lsum = 0.f;
    for (int s = tid; s < nS; s += 128) {
        float e = __expf(sc[s] - mx);
        sc[s] = e;
        lsum += e;
    }
    red[tid] = lsum;
    __syncthreads();
    for (int off = 64; off > 0; off >>= 1) {
        if (tid < off) red[tid] += red[tid + off];
        __syncthreads();
    }
    float inv = 1.0f / red[0];
    __syncthreads();
    if (tid < DH) {
        const float* vr = base + 2 * CH + h * DH + tid;
        float acc = 0.f;
        for (int s = 0; s < nS; s++) acc += sc[s] * vr[(size_t)s * (3 * CH)];
        y[((size_t)(b * TSEQ + t)) * CH + h * DH + tid] = acc * inv;
    }
}

// ---------------------------------------------------------------------------
__global__ void zero_loss_k(float* num, float* den) { *num = 0.f; *den = 0.f; }

__global__ void loss_k(const float* __restrict__ logits, const int* __restrict__ tg,
                       float* num, float* den) {
    __shared__ float red[256];
    int row = blockIdx.x;
    const float* lr = logits + (size_t)row * VOC;
    float m = -3.0e38f;
    for (int j = threadIdx.x; j < VOC; j += 256) m = fmaxf(m, lr[j]);
    red[threadIdx.x] = m;
    __syncthreads();
    for (int off = 128; off > 0; off >>= 1) {
        if (threadIdx.x < off) red[threadIdx.x] = fmaxf(red[threadIdx.x], red[threadIdx.x + off]);
        __syncthreads();
    }
    m = red[0];
    __syncthreads();
    float s = 0.f;
    for (int j = threadIdx.x; j < VOC; j += 256) s += __expf(lr[j] - m);
    red[threadIdx.x] = s;
    __syncthreads();
    for (int off = 128; off > 0; off >>= 1) {
        if (threadIdx.x < off) red[threadIdx.x] += red[threadIdx.x + off];
        __syncthreads();
    }
    if (threadIdx.x == 0) {
        int t = tg[row];
        if (t != 0) {
            float lse = m + logf(red[0]);
            float nll = lse - lr[t];
            atomicAdd(num, nll);
            atomicAdd(den, 1.0f);
        }
    }
}

__global__ void final_loss_k(const float* num, const float* den, float* out) {
    out[0] = *num / fmaxf(*den, 1.0f);
}

// ---------------------------------------------------------------------------
extern "C" void kernel_launch(void* const* d_in, const int* in_sizes, int n_in,
                              void* d_out, int out_size) {
    const int*   idx     = (const int*)d_in[0];
    const int*   targets = (const int*)d_in[1];
    const float* wte     = (const float*)d_in[2];
    const float* wpe     = (const float*)d_in[3];
    const float* ln1_g   = (const float*)d_in[4];
    const float* ln1_b   = (const float*)d_in[5];
    const float* attn_w  = (const float*)d_in[6];
    const float* attn_b  = (const float*)d_in[7];
    const float* proj_w  = (const float*)d_in[8];
    const float* proj_b  = (const float*)d_in[9];
    const float* ln2_g   = (const float*)d_in[10];
    const float* ln2_b   = (const float*)d_in[11];
    const float* fc_w    = (const float*)d_in[12];
    const float* fc_b    = (const float*)d_in[13];
    const float* fc2_w   = (const float*)d_in[14];
    const float* fc2_b   = (const float*)d_in[15];
    const float* lnf_g   = (const float*)d_in[16];
    const float* lnf_b   = (const float*)d_in[17];
    float* out = (float*)d_out;

    float *x, *h, *qkv, *y, *mbuf, *pnum, *pden;
    cudaGetSymbolAddress((void**)&x, g_x);
    cudaGetSymbolAddress((void**)&h, g_h);
    cudaGetSymbolAddress((void**)&qkv, g_qkv);
    cudaGetSymbolAddress((void**)&y, g_y);
    cudaGetSymbolAddress((void**)&mbuf, g_m);
    cudaGetSymbolAddress((void**)&pnum, g_num);
    cudaGetSymbolAddress((void**)&pden, g_den);

    const size_t LOGN = (size_t)BT * VOC;
    float* out_loss = out + LOGN;
    float* out_x    = out + LOGN + 1;  // 4B-aligned only: scalar access

    embed_k<<<BT, 256>>>(idx, wte, wpe, x);

    for (int l = 0; l < NLAY; l++) {
        ln_k<<<BT, 256>>>(x, ln1_g + l * CH, ln1_b + l * CH, h);
        gemm_nn_k<0, 0><<<dim3(3 * CH / 128, BT / 128), 256>>>(
            h, attn_w + (size_t)l * CH * 3 * CH, attn_b + (size_t)l * 3 * CH,
            nullptr, qkv, BT, 3 * CH, CH);
        attn_k<<<dim3(TSEQ, NH, 4), 128>>>(qkv, y);
        gemm_nn_k<0, 1><<<dim3(CH / 128, BT / 128), 256>>>(
            y, proj_w + (size_t)l * CH * CH, proj_b + (size_t)l * CH,
            x, x, BT, CH, CH);
        ln_k<<<BT, 256>>>(x, ln2_g + l * CH, ln2_b + l * CH, h);
        gemm_nn_k<1, 0><<<dim3(4 * CH / 128, BT / 128), 256>>>(
            h, fc_w + (size_t)l * CH * 4 * CH, fc_b + (size_t)l * 4 * CH,
            nullptr, mbuf, BT, 4 * CH, CH);
        gemm_nn_k<0, 1><<<dim3(CH / 128, BT / 128), 256>>>(
            mbuf, fc2_w + (size_t)l * 4 * CH * CH, fc2_b + (size_t)l * CH,
            x, x, BT, CH, 4 * CH);
    }

    ln_k<<<BT, 256>>>(x, lnf_g, lnf_b, h);
    copy_k<<<(BT * CH + 255) / 256, 256>>>(h, out_x, BT * CH);
    gemm_nt_k<<<dim3(VOC / 128, BT / 128), 256>>>(h, wte, out, BT, VOC, CH);
    zero_loss_k<<<1, 1>>>(pnum, pden);
    loss_k<<<BT, 256>>>(out, targets, pnum, pden);
    final_loss_k<<<1, 1>>>(pnum, pden, out_loss);
}

// round 9
// speedup vs baseline: 2.0416x; 1.2417x over previous
#include <cuda_runtime.h>
#include <cuda_bf16.h>
#include <math.h>

// ---------------------------------------------------------------------------
// GPT-2 small forward: L=6, C=768, H=12, D=64, B=4, T=1024, V=32000
// Output layout: logits [4096*32000] | loss [1] | x_final [4096*768]
// Round 9: all GEMMs on tensor cores (mma.sync m16n8k16 bf16) with split-bf16
// (hi+lo) operands: D = Ahi@Bhi + Ahi@Blo + Alo@Bhi  (~fp32 accuracy).
// Weights transpose-converted to [N][K] bf16 hi/lo per launch.
// ---------------------------------------------------------------------------

#define BT   4096
#define CH   768
#define NH   12
#define DH   64
#define TSEQ 1024
#define VOC  32000
#define NLAY 6

// transposed-weight pool offsets (elements)
#define W_ATTN_OFF 0
#define W_ATTN_SZ  (2304 * 768)
#define W_PROJ_OFF (W_ATTN_OFF + 6 * W_ATTN_SZ)          // 10,616,832
#define W_PROJ_SZ  (768 * 768)
#define W_FC_OFF   (W_PROJ_OFF + 6 * W_PROJ_SZ)          // 14,155,776
#define W_FC_SZ    (3072 * 768)
#define W_FC2_OFF  (W_FC_OFF + 6 * W_FC_SZ)              // 28,311,552
#define W_FC2_SZ   (768 * 3072)
#define W_TOTAL    (W_FC2_OFF + 6 * W_FC2_SZ)            // 42,467,328

// Scratch (device globals: no allocation allowed)
__device__ float g_x[BT * CH];
__device__ float g_h[BT * CH];
__device__ float g_qkv[BT * 3 * CH];
__device__ __nv_bfloat16 g_h_hi[BT * CH], g_h_lo[BT * CH];
__device__ __nv_bfloat16 g_y_hi[BT * CH], g_y_lo[BT * CH];
__device__ __nv_bfloat16 g_m_hi[BT * 4 * CH], g_m_lo[BT * 4 * CH];
__device__ __nv_bfloat16 g_wt_hi[W_TOTAL], g_wt_lo[W_TOTAL];
__device__ __nv_bfloat16 g_wte_hi[VOC * CH], g_wte_lo[VOC * CH];
__device__ float g_num;
__device__ float g_den;

// ---------------------------------------------------------------------------
__device__ __forceinline__ void split_bf16(float v, __nv_bfloat16& hi, __nv_bfloat16& lo) {
    hi = __float2bfloat16(v);
    lo = __float2bfloat16(v - __bfloat162float(hi));
}

// elementwise split-convert (wte)
__global__ void conv_k(const float* __restrict__ src, __nv_bfloat16* __restrict__ hi,
                       __nv_bfloat16* __restrict__ lo, int n) {
    int i = blockIdx.x * 256 + threadIdx.x;
    if (i < n) { __nv_bfloat16 h, l; split_bf16(src[i], h, l); hi[i] = h; lo[i] = l; }
}

// transpose + split-convert: W[K,N] fp32 -> T[N,K] bf16 hi/lo.  K,N %32==0.
__global__ void tconv_k(const float* __restrict__ W, __nv_bfloat16* __restrict__ Thi,
                        __nv_bfloat16* __restrict__ Tlo, int K, int N) {
    __shared__ float s[32][33];
    int n0 = blockIdx.x * 32, k0 = blockIdx.y * 32;
    int tx = threadIdx.x, ty = threadIdx.y;
#pragma unroll
    for (int i = 0; i < 4; i++)
        s[ty + i * 8][tx] = W[(size_t)(k0 + ty + i * 8) * N + n0 + tx];
    __syncthreads();
#pragma unroll
    for (int i = 0; i < 4; i++) {
        float v = s[tx][ty + i * 8];
        __nv_bfloat16 h, l; split_bf16(v, h, l);
        size_t o = (size_t)(n0 + ty + i * 8) * K + k0 + tx;
        Thi[o] = h; Tlo[o] = l;
    }
}

// ---------------------------------------------------------------------------
__global__ void embed_k(const int* __restrict__ idx, const float* __restrict__ wte,
                        const float* __restrict__ wpe, float* __restrict__ x) {
    int row = blockIdx.x;
    int t = row & (TSEQ - 1);
    int tok = idx[row];
    const float* a = wte + (size_t)tok * CH;
    const float* b = wpe + (size_t)t * CH;
    float* o = x + (size_t)row * CH;
    for (int c = threadIdx.x; c < CH; c += blockDim.x) o[c] = a[c] + b[c];
}

__global__ void copy_k(const float* __restrict__ src, float* __restrict__ dst, int n) {
    int i = blockIdx.x * blockDim.x + threadIdx.x;
    if (i < n) dst[i] = src[i];
}

// LayerNorm: writes fp32 AND split-bf16 outputs
__global__ void ln_k(const float* __restrict__ x, const float* __restrict__ g,
                     const float* __restrict__ b, float* __restrict__ o,
                     __nv_bfloat16* __restrict__ ohi, __nv_bfloat16* __restrict__ olo) {
    __shared__ float r1[256], r2[256];
    int row = blockIdx.x;
    const float* xr = x + (size_t)row * CH;
    float s = 0.f, s2 = 0.f;
    for (int i = threadIdx.x; i < CH; i += 256) { float v = xr[i]; s += v; s2 += v * v; }
    r1[threadIdx.x] = s; r2[threadIdx.x] = s2;
    __syncthreads();
    for (int off = 128; off > 0; off >>= 1) {
        if (threadIdx.x < off) {
            r1[threadIdx.x] += r1[threadIdx.x + off];
            r2[threadIdx.x] += r2[threadIdx.x + off];
        }
        __syncthreads();
    }
    float mean = r1[0] * (1.0f / CH);
    float var  = r2[0] * (1.0f / CH) - mean * mean;
    float rstd = rsqrtf(var + 1e-5f);
    for (int i = threadIdx.x; i < CH; i += 256) {
        float v = (xr[i] - mean) * rstd * g[i] + b[i];
        size_t oo = (size_t)row * CH + i;
        o[oo] = v;
        __nv_bfloat16 h, l; split_bf16(v, h, l);
        ohi[oo] = h; olo[oo] = l;
    }
}

// ---------------------------------------------------------------------------
// tensor-core primitives
__device__ __forceinline__ void ldmx4(unsigned addr, unsigned r[4]) {
    asm volatile("ldmatrix.sync.aligned.m8n8.x4.shared.b16 {%0,%1,%2,%3}, [%4];"
                 : "=r"(r[0]), "=r"(r[1]), "=r"(r[2]), "=r"(r[3]) : "r"(addr));
}
__device__ __forceinline__ void mma16816(float d[4], const unsigned a[4],
                                         unsigned b0, unsigned b1) {
    asm volatile("mma.sync.aligned.m16n8k16.row.col.f32.bf16.bf16.f32 "
                 "{%0,%1,%2,%3},{%4,%5,%6,%7},{%8,%9},{%0,%1,%2,%3};"
                 : "+f"(d[0]), "+f"(d[1]), "+f"(d[2]), "+f"(d[3])
                 : "r"(a[0]), "r"(a[1]), "r"(a[2]), "r"(a[3]), "r"(b0), "r"(b1));
}

#define SPITCH 40   // smem row pitch in bf16 (80 B) — conflict-free ldmatrix

// ---------------------------------------------------------------------------
// Split-bf16 NT GEMM: D[M,N] = Ahi/lo[M,K] @ (Bhi/lo[N,K])^T  (3-term split)
// 128x128 tile, 256 threads (8 warps of 64x32), k-chunk 32, reg-prefetched.
// MODE 0: +bias -> fp32 C.   MODE 1: +bias, exact GELU -> bf16 hi/lo (Ohi/Olo).
// MODE 2: +bias +res -> fp32 C.   MODE 3: plain -> fp32 C.
template <int MODE>
__global__ __launch_bounds__(256, 1)
void hgemm_k(const __nv_bfloat16* __restrict__ Ahi, const __nv_bfloat16* __restrict__ Alo,
             const __nv_bfloat16* __restrict__ Bhi, const __nv_bfloat16* __restrict__ Blo,
             const float* __restrict__ bias, const float* __restrict__ res,
             float* __restrict__ C, __nv_bfloat16* __restrict__ Ohi,
             __nv_bfloat16* __restrict__ Olo, int M, int N, int K) {
    __shared__ __align__(16) __nv_bfloat16 sAh[128 * SPITCH], sAl[128 * SPITCH];
    __shared__ __align__(16) __nv_bfloat16 sBh[128 * SPITCH], sBl[128 * SPITCH];
    int tid = threadIdx.x, lane = tid & 31, wid = tid >> 5;
    int wm = wid >> 2, wn = wid & 3;
    int row0 = blockIdx.y * 128, col0 = blockIdx.x * 128;

    // global/smem copy coords: vec0 = tid, vec1 = tid+256 (row+64, same seg)
    int r0 = tid >> 2, sg = (tid & 3) * 8;
    size_t aoff0 = (size_t)(row0 + r0) * K + sg;
    size_t aoff1 = (size_t)(row0 + r0 + 64) * K + sg;
    size_t boff0 = (size_t)(col0 + r0) * K + sg;
    size_t boff1 = (size_t)(col0 + r0 + 64) * K + sg;
    int sm0 = r0 * SPITCH + sg, sm1 = (r0 + 64) * SPITCH + sg;

    // ldmatrix per-lane addresses
    int lr  = (lane & 7) + ((lane >> 3) & 1) * 8;
    int lcb = (lane >> 4) * 16;
    unsigned adAh[4], adAl[4], adBh[2], adBl[2];
#pragma unroll
    for (int i = 0; i < 4; i++) {
        int rr = wm * 64 + i * 16 + lr;
        adAh[i] = (unsigned)__cvta_generic_to_shared(&sAh[rr * SPITCH]) + lcb;
        adAl[i] = (unsigned)__cvta_generic_to_shared(&sAl[rr * SPITCH]) + lcb;
    }
#pragma unroll
    for (int p = 0; p < 2; p++) {
        int rr = wn * 32 + p * 16 + lr;
        adBh[p] = (unsigned)__cvta_generic_to_shared(&sBh[rr * SPITCH]) + lcb;
        adBl[p] = (unsigned)__cvta_generic_to_shared(&sBl[rr * SPITCH]) + lcb;
    }

    float acc[4][4][4];
#pragma unroll
    for (int i = 0; i < 4; i++)
#pragma unroll
        for (int j = 0; j < 4; j++)
#pragma unroll
            for (int q = 0; q < 4; q++) acc[i][j][q] = 0.f;

    uint4 pa0, pa1, pl0, pl1, pb0, pb1, pc0, pc1;
    pa0 = *(const uint4*)&Ahi[aoff0]; pa1 = *(const uint4*)&Ahi[aoff1];
    pl0 = *(const uint4*)&Alo[aoff0]; pl1 = *(const uint4*)&Alo[aoff1];
    pb0 = *(const uint4*)&Bhi[boff0]; pb1 = *(const uint4*)&Bhi[boff1];
    pc0 = *(const uint4*)&Blo[boff0]; pc1 = *(const uint4*)&Blo[boff1];
    *(uint4*)&sAh[sm0] = pa0; *(uint4*)&sAh[sm1] = pa1;
    *(uint4*)&sAl[sm0] = pl0; *(uint4*)&sAl[sm1] = pl1;
    *(uint4*)&sBh[sm0] = pb0; *(uint4*)&sBh[sm1] = pb1;
    *(uint4*)&sBl[sm0] = pc0; *(uint4*)&sBl[sm1] = pc1;
    __syncthreads();

    int nC = K >> 5;
    for (int c = 0; c < nC; c++) {
        bool more = (c + 1) < nC;
        int ko = (c + 1) << 5;
        if (more) {
            pa0 = *(const uint4*)&Ahi[aoff0 + ko]; pa1 = *(const uint4*)&Ahi[aoff1 + ko];
            pl0 = *(const uint4*)&Alo[aoff0 + ko]; pl1 = *(const uint4*)&Alo[aoff1 + ko];
            pb0 = *(const uint4*)&Bhi[boff0 + ko]; pb1 = *(const uint4*)&Bhi[boff1 + ko];
            pc0 = *(const uint4*)&Blo[boff0 + ko]; pc1 = *(const uint4*)&Blo[boff1 + ko];
        }
#pragma unroll
        for (int s = 0; s < 2; s++) {
            unsigned ah[4][4], al[4][4], bh[2][4], bl[2][4];
#pragma unroll
            for (int i = 0; i < 4; i++) { ldmx4(adAh[i] + s * 32, ah[i]); ldmx4(adAl[i] + s * 32, al[i]); }
#pragma unroll
            for (int p = 0; p < 2; p++) { ldmx4(adBh[p] + s * 32, bh[p]); ldmx4(adBl[p] + s * 32, bl[p]); }
#pragma unroll
            for (int i = 0; i < 4; i++)
#pragma unroll
                for (int j = 0; j < 4; j++) {
                    int p = j >> 1, q = j & 1;
                    mma16816(acc[i][j], ah[i], bh[p][q], bh[p][2 + q]);
                    mma16816(acc[i][j], ah[i], bl[p][q], bl[p][2 + q]);
                    mma16816(acc[i][j], al[i], bh[p][q], bh[p][2 + q]);
                }
        }
        __syncthreads();
        if (more) {
            *(uint4*)&sAh[sm0] = pa0; *(uint4*)&sAh[sm1] = pa1;
            *(uint4*)&sAl[sm0] = pl0; *(uint4*)&sAl[sm1] = pl1;
            *(uint4*)&sBh[sm0] = pb0; *(uint4*)&sBh[sm1] = pb1;
            *(uint4*)&sBl[sm0] = pc0; *(uint4*)&sBl[sm1] = pc1;
            __syncthreads();
        }
    }

    // epilogue
    int g = lane >> 2, t2 = (lane & 3) * 2;
#pragma unroll
    for (int i = 0; i < 4; i++) {
        int rA = row0 + wm * 64 + i * 16 + g;
#pragma unroll
        for (int j = 0; j < 4; j++) {
            int cA = col0 + wn * 32 + j * 8 + t2;
            float v0 = acc[i][j][0], v1 = acc[i][j][1];
            float w0 = acc[i][j][2], w1 = acc[i][j][3];
            if (MODE == 0 || MODE == 1 || MODE == 2) {
                float b0 = bias[cA], b1 = bias[cA + 1];
                v0 += b0; v1 += b1; w0 += b0; w1 += b1;
            }
            if (MODE == 1) {
                v0 = 0.5f * v0 * (1.0f + erff(v0 * 0.70710678118654752440f));
                v1 = 0.5f * v1 * (1.0f + erff(v1 * 0.70710678118654752440f));
                w0 = 0.5f * w0 * (1.0f + erff(w0 * 0.70710678118654752440f));
                w1 = 0.5f * w1 * (1.0f + erff(w1 * 0.70710678118654752440f));
                __nv_bfloat16 h0, l0, h1, l1;
                __nv_bfloat162 th, tl;
                split_bf16(v0, h0, l0); split_bf16(v1, h1, l1);
                th.x = h0; th.y = h1; tl.x = l0; tl.y = l1;
                *(__nv_bfloat162*)&Ohi[(size_t)rA * N + cA] = th;
                *(__nv_bfloat162*)&Olo[(size_t)rA * N + cA] = tl;
                split_bf16(w0, h0, l0); split_bf16(w1, h1, l1);
                th.x = h0; th.y = h1; tl.x = l0; tl.y = l1;
                *(__nv_bfloat162*)&Ohi[(size_t)(rA + 8) * N + cA] = th;
                *(__nv_bfloat162*)&Olo[(size_t)(rA + 8) * N + cA] = tl;
            } else {
                if (MODE == 2) {
                    float2 q0 = *(const float2*)&res[(size_t)rA * N + cA];
                    float2 q1 = *(const float2*)&res[(size_t)(rA + 8) * N + cA];
                    v0 += q0.x; v1 += q0.y; w0 += q1.x; w1 += q1.y;
                }
                *(float2*)&C[(size_t)rA * N + cA] = make_float2(v0, v1);
                *(float2*)&C[(size_t)(rA + 8) * N + cA] = make_float2(w0, w1);
            }
        }
    }
}

// ---------------------------------------------------------------------------
// Causal attention, one block per (t, h, b). qkv fp32 in; y split-bf16 out.
__global__ void attn_k(const float* __restrict__ qkv,
                       __nv_bfloat16* __restrict__ y_hi, __nv_bfloat16* __restrict__ y_lo) {
    __shared__ float qs[DH];
    __shared__ float sc[TSEQ];
    __shared__ float red[128];
    int t = blockIdx.x, h = blockIdx.y, b = blockIdx.z;
    int tid = threadIdx.x;
    const float* base = qkv + (size_t)b * TSEQ * (3 * CH);
    if (tid < DH) qs[tid] = base[(size_t)t * (3 * CH) + h * DH + tid];
    __syncthreads();
    int nS = t + 1;
    float lmax = -3.0e38f;
    for (int s = tid; s < nS; s += 128) {
        const float* kr = base + (size_t)s * (3 * CH) + CH + h * DH;
        float d = 0.f;
#pragma unroll
        for (int i = 0; i < DH; i++) d += qs[i] * kr[i];
        d *= 0.125f;
        sc[s] = d;
        lmax = fmaxf(lmax, d);
    }
    red[tid] = lmax;
    __syncthreads();
    for (int off = 64; off > 0; off >>= 1) {
        if (tid < off) red[tid] = fmaxf(red[tid], red[tid + off]);
        __syncthreads();
    }
    float mx = red[0];
    __syncthreads();
    float lsum = 0.f;
    for (int s = tid; s < nS; s += 128) {
        float e = __expf(sc[s] - mx);
        sc[s] = e;
        lsum += e;
    }
    red[tid] = lsum;
    __syncthreads();
    for (int off = 64; off > 0; off >>= 1) {
        if (tid < off) red[tid] += red[tid + off];
        __syncthreads();
    }
    float inv = 1.0f / red[0];
    __syncthreads();
    if (tid < DH) {
        const float* vr = base + 2 * CH + h * DH + tid;
        float acc = 0.f;
        for (int s = 0; s < nS; s++) acc += sc[s] * vr[(size_t)s * (3 * CH)];
        float o = acc * inv;
        size_t oi = ((size_t)(b * TSEQ + t)) * CH + h * DH + tid;
        __nv_bfloat16 hh, ll; split_bf16(o, hh, ll);
        y_hi[oi] = hh; y_lo[oi] = ll;
    }
}

// ---------------------------------------------------------------------------
__global__ void zero_loss_k(float* num, float* den) { *num = 0.f; *den = 0.f; }

__global__ void loss_k(const float* __restrict__ logits, const int* __restrict__ tg,
                       float* num, float* den) {
    __shared__ float red[256];
    int row = blockIdx.x;
    const float* lr = logits + (size_t)row * VOC;
    float m = -3.0e38f;
    for (int j = threadIdx.x; j < VOC; j += 256) m = fmaxf(m, lr[j]);
    red[threadIdx.x] = m;
    __syncthreads();
    for (int off = 128; off > 0; off >>= 1) {
        if (threadIdx.x < off) red[threadIdx.x] = fmaxf(red[threadIdx.x], red[threadIdx.x + off]);
        __syncthreads();
    }
    m = red[0];
    __syncthreads();
    float s = 0.f;
    for (int j = threadIdx.x; j < VOC; j += 256) s += __expf(lr[j] - m);
    red[threadIdx.x] = s;
    __syncthreads();
    for (int off = 128; off > 0; off >>= 1) {
        if (threadIdx.x < off) red[threadIdx.x] += red[threadIdx.x + off];
        __syncthreads();
    }
    if (threadIdx.x == 0) {
        int t = tg[row];
        if (t != 0) {
            float lse = m + logf(red[0]);
            float nll = lse - lr[t];
            atomicAdd(num, nll);
            atomicAdd(den, 1.0f);
        }
    }
}

__global__ void final_loss_k(const float* num, const float* den, float* out) {
    out[0] = *num / fmaxf(*den, 1.0f);
}

// ---------------------------------------------------------------------------
extern "C" void kernel_launch(void* const* d_in, const int* in_sizes, int n_in,
                              void* d_out, int out_size) {
    const int*   idx     = (const int*)d_in[0];
    const int*   targets = (const int*)d_in[1];
    const float* wte     = (const float*)d_in[2];
    const float* wpe     = (const float*)d_in[3];
    const float* ln1_g   = (const float*)d_in[4];
    const float* ln1_b   = (const float*)d_in[5];
    const float* attn_w  = (const float*)d_in[6];
    const float* attn_b  = (const float*)d_in[7];
    const float* proj_w  = (const float*)d_in[8];
    const float* proj_b  = (const float*)d_in[9];
    const float* ln2_g   = (const float*)d_in[10];
    const float* ln2_b   = (const float*)d_in[11];
    const float* fc_w    = (const float*)d_in[12];
    const float* fc_b    = (const float*)d_in[13];
    const float* fc2_w   = (const float*)d_in[14];
    const float* fc2_b   = (const float*)d_in[15];
    const float* lnf_g   = (const float*)d_in[16];
    const float* lnf_b   = (const float*)d_in[17];
    float* out = (float*)d_out;

    float *x, *h, *qkv, *pnum, *pden;
    __nv_bfloat16 *h_hi, *h_lo, *y_hi, *y_lo, *m_hi, *m_lo, *wt_hi, *wt_lo, *wte_hi, *wte_lo;
    cudaGetSymbolAddress((void**)&x, g_x);
    cudaGetSymbolAddress((void**)&h, g_h);
    cudaGetSymbolAddress((void**)&qkv, g_qkv);
    cudaGetSymbolAddress((void**)&h_hi, g_h_hi);
    cudaGetSymbolAddress((void**)&h_lo, g_h_lo);
    cudaGetSymbolAddress((void**)&y_hi, g_y_hi);
    cudaGetSymbolAddress((void**)&y_lo, g_y_lo);
    cudaGetSymbolAddress((void**)&m_hi, g_m_hi);
    cudaGetSymbolAddress((void**)&m_lo, g_m_lo);
    cudaGetSymbolAddress((void**)&wt_hi, g_wt_hi);
    cudaGetSymbolAddress((void**)&wt_lo, g_wt_lo);
    cudaGetSymbolAddress((void**)&wte_hi, g_wte_hi);
    cudaGetSymbolAddress((void**)&wte_lo, g_wte_lo);
    cudaGetSymbolAddress((void**)&pnum, g_num);
    cudaGetSymbolAddress((void**)&pden, g_den);

    const size_t LOGN = (size_t)BT * VOC;
    float* out_loss = out + LOGN;
    float* out_x    = out + LOGN + 1;  // 4B-aligned only: scalar access

    dim3 tblk(32, 8);

    // ---- weight preprocessing (transpose + split-convert) ----
    conv_k<<<(VOC * CH + 255) / 256, 256>>>(wte, wte_hi, wte_lo, VOC * CH);
    for (int l = 0; l < NLAY; l++) {
        tconv_k<<<dim3(2304 / 32, 768 / 32), tblk>>>(
            attn_w + (size_t)l * W_ATTN_SZ, wt_hi + W_ATTN_OFF + (size_t)l * W_ATTN_SZ,
            wt_lo + W_ATTN_OFF + (size_t)l * W_ATTN_SZ, 768, 2304);
        tconv_k<<<dim3(768 / 32, 768 / 32), tblk>>>(
            proj_w + (size_t)l * W_PROJ_SZ, wt_hi + W_PROJ_OFF + (size_t)l * W_PROJ_SZ,
            wt_lo + W_PROJ_OFF + (size_t)l * W_PROJ_SZ, 768, 768);
        tconv_k<<<dim3(3072 / 32, 768 / 32), tblk>>>(
            fc_w + (size_t)l * W_FC_SZ, wt_hi + W_FC_OFF + (size_t)l * W_FC_SZ,
            wt_lo + W_FC_OFF + (size_t)l * W_FC_SZ, 768, 3072);
        tconv_k<<<dim3(768 / 32, 3072 / 32), tblk>>>(
            fc2_w + (size_t)l * W_FC2_SZ, wt_hi + W_FC2_OFF + (size_t)l * W_FC2_SZ,
            wt_lo + W_FC2_OFF + (size_t)l * W_FC2_SZ, 3072, 768);
    }

    embed_k<<<BT, 256>>>(idx, wte, wpe, x);

    for (int l = 0; l < NLAY; l++) {
        const __nv_bfloat16* wa_h = wt_hi + W_ATTN_OFF + (size_t)l * W_ATTN_SZ;
        const __nv_bfloat16* wa_l = wt_lo + W_ATTN_OFF + (size_t)l * W_ATTN_SZ;
        const __nv_bfloat16* wp_h = wt_hi + W_PROJ_OFF + (size_t)l * W_PROJ_SZ;
        const __nv_bfloat16* wp_l = wt_lo + W_PROJ_OFF + (size_t)l * W_PROJ_SZ;
        const __nv_bfloat16* wf_h = wt_hi + W_FC_OFF + (size_t)l * W_FC_SZ;
        const __nv_bfloat16* wf_l = wt_lo + W_FC_OFF + (size_t)l * W_FC_SZ;
        const __nv_bfloat16* w2_h = wt_hi + W_FC2_OFF + (size_t)l * W_FC2_SZ;
        const __nv_bfloat16* w2_l = wt_lo + W_FC2_OFF + (size_t)l * W_FC2_SZ;

        ln_k<<<BT, 256>>>(x, ln1_g + l * CH, ln1_b + l * CH, h, h_hi, h_lo);
        hgemm_k<0><<<dim3(2304 / 128, BT / 128), 256>>>(
            h_hi, h_lo, wa_h, wa_l, attn_b + (size_t)l * 3 * CH,
            nullptr, qkv, nullptr, nullptr, BT, 3 * CH, CH);
        attn_k<<<dim3(TSEQ, NH, 4), 128>>>(qkv, y_hi, y_lo);
        hgemm_k<2><<<dim3(CH / 128, BT / 128), 256>>>(
            y_hi, y_lo, wp_h, wp_l, proj_b + (size_t)l * CH,
            x, x, nullptr, nullptr, BT, CH, CH);
        ln_k<<<BT, 256>>>(x, ln2_g + l * CH, ln2_b + l * CH, h, h_hi, h_lo);
        hgemm_k<1><<<dim3(4 * CH / 128, BT / 128), 256>>>(
            h_hi, h_lo, wf_h, wf_l, fc_b + (size_t)l * 4 * CH,
            nullptr, nullptr, m_hi, m_lo, BT, 4 * CH, CH);
        hgemm_k<2><<<dim3(CH / 128, BT / 128), 256>>>(
            m_hi, m_lo, w2_h, w2_l, fc2_b + (size_t)l * CH,
            x, x, nullptr, nullptr, BT, CH, 4 * CH);
    }

    ln_k<<<BT, 256>>>(x, lnf_g, lnf_b, h, h_hi, h_lo);
    copy_k<<<(BT * CH + 255) / 256, 256>>>(h, out_x, BT * CH);
    hgemm_k<3><<<dim3(VOC / 128, BT / 128), 256>>>(
        h_hi, h_lo, wte_hi, wte_lo, nullptr, nullptr, out, nullptr, nullptr,
        BT, VOC, CH);
    zero_loss_k<<<1, 1>>>(pnum, pden);
    loss_k<<<BT, 256>>>(out, targets, pnum, pden);
    final_loss_k<<<1, 1>>>(pnum, pden, out_loss);
}

// round 10
// speedup vs baseline: 2.0657x; 1.0118x over previous
#include <cuda_runtime.h>
#include <cuda_bf16.h>
#include <math.h>

// ---------------------------------------------------------------------------
// GPT-2 small forward: L=6, C=768, H=12, D=64, B=4, T=1024, V=32000
// Output layout: logits [4096*32000] | loss [1] | x_final [4096*768]
// Round 10: split-bf16 mma.sync GEMMs with cp.async 2-stage smem pipeline and
// occupancy 2 (was 1).  D = Ahi@Bhi + Ahi@Blo + Alo@Bhi.
// ---------------------------------------------------------------------------

#define BT   4096
#define CH   768
#define NH   12
#define DH   64
#define TSEQ 1024
#define VOC  32000
#define NLAY 6

// transposed-weight pool offsets (elements)
#define W_ATTN_OFF 0
#define W_ATTN_SZ  (2304 * 768)
#define W_PROJ_OFF (W_ATTN_OFF + 6 * W_ATTN_SZ)
#define W_PROJ_SZ  (768 * 768)
#define W_FC_OFF   (W_PROJ_OFF + 6 * W_PROJ_SZ)
#define W_FC_SZ    (3072 * 768)
#define W_FC2_OFF  (W_FC_OFF + 6 * W_FC_SZ)
#define W_FC2_SZ   (768 * 3072)
#define W_TOTAL    (W_FC2_OFF + 6 * W_FC2_SZ)

// Scratch (device globals: no allocation allowed)
__device__ float g_x[BT * CH];
__device__ float g_h[BT * CH];
__device__ float g_qkv[BT * 3 * CH];
__device__ __nv_bfloat16 g_h_hi[BT * CH], g_h_lo[BT * CH];
__device__ __nv_bfloat16 g_y_hi[BT * CH], g_y_lo[BT * CH];
__device__ __nv_bfloat16 g_m_hi[BT * 4 * CH], g_m_lo[BT * 4 * CH];
__device__ __nv_bfloat16 g_wt_hi[W_TOTAL], g_wt_lo[W_TOTAL];
__device__ __nv_bfloat16 g_wte_hi[VOC * CH], g_wte_lo[VOC * CH];
__device__ float g_num;
__device__ float g_den;

// ---------------------------------------------------------------------------
__device__ __forceinline__ void split_bf16(float v, __nv_bfloat16& hi, __nv_bfloat16& lo) {
    hi = __float2bfloat16(v);
    lo = __float2bfloat16(v - __bfloat162float(hi));
}

__global__ void conv_k(const float* __restrict__ src, __nv_bfloat16* __restrict__ hi,
                       __nv_bfloat16* __restrict__ lo, int n) {
    int i = blockIdx.x * 256 + threadIdx.x;
    if (i < n) { __nv_bfloat16 h, l; split_bf16(src[i], h, l); hi[i] = h; lo[i] = l; }
}

// transpose + split-convert: W[K,N] fp32 -> T[N,K] bf16 hi/lo.  K,N %32==0.
__global__ void tconv_k(const float* __restrict__ W, __nv_bfloat16* __restrict__ Thi,
                        __nv_bfloat16* __restrict__ Tlo, int K, int N) {
    __shared__ float s[32][33];
    int n0 = blockIdx.x * 32, k0 = blockIdx.y * 32;
    int tx = threadIdx.x, ty = threadIdx.y;
#pragma unroll
    for (int i = 0; i < 4; i++)
        s[ty + i * 8][tx] = W[(size_t)(k0 + ty + i * 8) * N + n0 + tx];
    __syncthreads();
#pragma unroll
    for (int i = 0; i < 4; i++) {
        float v = s[tx][ty + i * 8];
        __nv_bfloat16 h, l; split_bf16(v, h, l);
        size_t o = (size_t)(n0 + ty + i * 8) * K + k0 + tx;
        Thi[o] = h; Tlo[o] = l;
    }
}

// ---------------------------------------------------------------------------
__global__ void embed_k(const int* __restrict__ idx, const float* __restrict__ wte,
                        const float* __restrict__ wpe, float* __restrict__ x) {
    int row = blockIdx.x;
    int t = row & (TSEQ - 1);
    int tok = idx[row];
    const float* a = wte + (size_t)tok * CH;
    const float* b = wpe + (size_t)t * CH;
    float* o = x + (size_t)row * CH;
    for (int c = threadIdx.x; c < CH; c += blockDim.x) o[c] = a[c] + b[c];
}

__global__ void copy_k(const float* __restrict__ src, float* __restrict__ dst, int n) {
    int i = blockIdx.x * blockDim.x + threadIdx.x;
    if (i < n) dst[i] = src[i];
}

// LayerNorm: writes fp32 AND split-bf16 outputs
__global__ void ln_k(const float* __restrict__ x, const float* __restrict__ g,
                     const float* __restrict__ b, float* __restrict__ o,
                     __nv_bfloat16* __restrict__ ohi, __nv_bfloat16* __restrict__ olo) {
    __shared__ float r1[256], r2[256];
    int row = blockIdx.x;
    const float* xr = x + (size_t)row * CH;
    float s = 0.f, s2 = 0.f;
    for (int i = threadIdx.x; i < CH; i += 256) { float v = xr[i]; s += v; s2 += v * v; }
    r1[threadIdx.x] = s; r2[threadIdx.x] = s2;
    __syncthreads();
    for (int off = 128; off > 0; off >>= 1) {
        if (threadIdx.x < off) {
            r1[threadIdx.x] += r1[threadIdx.x + off];
            r2[threadIdx.x] += r2[threadIdx.x + off];
        }
        __syncthreads();
    }
    float mean = r1[0] * (1.0f / CH);
    float var  = r2[0] * (1.0f / CH) - mean * mean;
    float rstd = rsqrtf(var + 1e-5f);
    for (int i = threadIdx.x; i < CH; i += 256) {
        float v = (xr[i] - mean) * rstd * g[i] + b[i];
        size_t oo = (size_t)row * CH + i;
        o[oo] = v;
        __nv_bfloat16 h, l; split_bf16(v, h, l);
        ohi[oo] = h; olo[oo] = l;
    }
}

// ---------------------------------------------------------------------------
// tensor-core / async-copy primitives
__device__ __forceinline__ void ldmx4(unsigned addr, unsigned r[4]) {
    asm volatile("ldmatrix.sync.aligned.m8n8.x4.shared.b16 {%0,%1,%2,%3}, [%4];"
                 : "=r"(r[0]), "=r"(r[1]), "=r"(r[2]), "=r"(r[3]) : "r"(addr));
}
__device__ __forceinline__ void mma16816(float d[4], const unsigned a[4],
                                         unsigned b0, unsigned b1) {
    asm volatile("mma.sync.aligned.m16n8k16.row.col.f32.bf16.bf16.f32 "
                 "{%0,%1,%2,%3},{%4,%5,%6,%7},{%8,%9},{%0,%1,%2,%3};"
                 : "+f"(d[0]), "+f"(d[1]), "+f"(d[2]), "+f"(d[3])
                 : "r"(a[0]), "r"(a[1]), "r"(a[2]), "r"(a[3]), "r"(b0), "r"(b1));
}
__device__ __forceinline__ void cp16(unsigned sa, const void* gm) {
    asm volatile("cp.async.cg.shared.global [%0], [%1], 16;" :: "r"(sa), "l"(gm));
}
__device__ __forceinline__ void cp_commit() { asm volatile("cp.async.commit_group;"); }
template <int N>
__device__ __forceinline__ void cp_wait() {
    asm volatile("cp.async.wait_group %0;" :: "n"(N));
}

#define SPITCH 40                     // smem row pitch (bf16); 80B, ldmatrix-conflict-free
#define ARR    (128 * SPITCH)         // elements per tile array
#define STGE   (4 * ARR)              // elements per stage (Ah,Al,Bh,Bl)
#define STGB   (STGE * 2)             // bytes per stage = 40960
#define HSMEM  (2 * STGB)             // total dynamic smem = 81920

// ---------------------------------------------------------------------------
// Split-bf16 NT GEMM: D[M,N] = Ahi/lo[M,K] @ (Bhi/lo[N,K])^T  (3-term split)
// 128x128 tile, 256 threads (8 warps of 64x32), k-chunk 32.
// cp.async 2-stage smem pipeline; occupancy 2.
// MODE 0: +bias -> fp32.  MODE 1: +bias,GELU -> bf16 hi/lo.
// MODE 2: +bias +res -> fp32.  MODE 3: plain -> fp32.
template <int MODE>
__global__ __launch_bounds__(256, 2)
void hgemm_k(const __nv_bfloat16* __restrict__ Ahi, const __nv_bfloat16* __restrict__ Alo,
             const __nv_bfloat16* __restrict__ Bhi, const __nv_bfloat16* __restrict__ Blo,
             const float* __restrict__ bias, const float* __restrict__ res,
             float* __restrict__ C, __nv_bfloat16* __restrict__ Ohi,
             __nv_bfloat16* __restrict__ Olo, int M, int N, int K) {
    extern __shared__ __align__(16) __nv_bfloat16 smbuf[];
    int tid = threadIdx.x, lane = tid & 31, wid = tid >> 5;
    int wm = wid >> 2, wn = wid & 3;
    int row0 = blockIdx.y * 128, col0 = blockIdx.x * 128;

    // global source coords (8 bf16 = 16B per copy; 2 rows per array per thread)
    int r0 = tid >> 2, sg = (tid & 3) * 8;
    size_t aoff0 = (size_t)(row0 + r0) * K + sg;
    size_t aoff1 = aoff0 + (size_t)64 * K;
    size_t boff0 = (size_t)(col0 + r0) * K + sg;
    size_t boff1 = boff0 + (size_t)64 * K;
    int sm0 = r0 * SPITCH + sg, sm1 = sm0 + 64 * SPITCH;

    unsigned smbase = (unsigned)__cvta_generic_to_shared(smbuf);
    unsigned dAh0 = smbase + (0 * ARR + sm0) * 2, dAh1 = smbase + (0 * ARR + sm1) * 2;
    unsigned dAl0 = smbase + (1 * ARR + sm0) * 2, dAl1 = smbase + (1 * ARR + sm1) * 2;
    unsigned dBh0 = smbase + (2 * ARR + sm0) * 2, dBh1 = smbase + (2 * ARR + sm1) * 2;
    unsigned dBl0 = smbase + (3 * ARR + sm0) * 2, dBl1 = smbase + (3 * ARR + sm1) * 2;

    // ldmatrix per-lane base addresses (stage 0; Ah array 0, Bh array 2)
    int lr  = (lane & 7) + ((lane >> 3) & 1) * 8;
    int lcb = (lane >> 4) * 16;
    unsigned adA[4], adB[2];
#pragma unroll
    for (int i = 0; i < 4; i++) {
        int rr = wm * 64 + i * 16 + lr;
        adA[i] = smbase + (unsigned)(rr * SPITCH) * 2 + lcb;
    }
#pragma unroll
    for (int p = 0; p < 2; p++) {
        int rr = wn * 32 + p * 16 + lr;
        adB[p] = smbase + (unsigned)(2 * ARR + rr * SPITCH) * 2 + lcb;
    }

    float acc[4][4][4];
#pragma unroll
    for (int i = 0; i < 4; i++)
#pragma unroll
        for (int j = 0; j < 4; j++)
#pragma unroll
            for (int q = 0; q < 4; q++) acc[i][j][q] = 0.f;

    int nC = K >> 5;
    // prologue: issue chunk 0 into stage 0
    {
        cp16(dAh0, Ahi + aoff0); cp16(dAh1, Ahi + aoff1);
        cp16(dAl0, Alo + aoff0); cp16(dAl1, Alo + aoff1);
        cp16(dBh0, Bhi + boff0); cp16(dBh1, Bhi + boff1);
        cp16(dBl0, Blo + boff0); cp16(dBl1, Blo + boff1);
        cp_commit();
    }

    for (int c = 0; c < nC; c++) {
        if (c + 1 < nC) {  // issue chunk c+1 into the other stage
            unsigned so = (unsigned)((c + 1) & 1) * STGB;
            size_t ko = (size_t)(c + 1) << 5;
            cp16(dAh0 + so, Ahi + aoff0 + ko); cp16(dAh1 + so, Ahi + aoff1 + ko);
            cp16(dAl0 + so, Alo + aoff0 + ko); cp16(dAl1 + so, Alo + aoff1 + ko);
            cp16(dBh0 + so, Bhi + boff0 + ko); cp16(dBh1 + so, Bhi + boff1 + ko);
            cp16(dBl0 + so, Blo + boff0 + ko); cp16(dBl1 + so, Blo + boff1 + ko);
            cp_commit();
            cp_wait<1>();   // chunk c complete (one group still in flight)
        } else {
            cp_wait<0>();
        }
        __syncthreads();

        unsigned so = (unsigned)(c & 1) * STGB;
#pragma unroll
        for (int s = 0; s < 2; s++) {
            unsigned ah[4][4], al[4][4], bh[2][4], bl[2][4];
#pragma unroll
            for (int i = 0; i < 4; i++) {
                ldmx4(adA[i] + so + s * 32, ah[i]);
                ldmx4(adA[i] + so + ARR * 2 + s * 32, al[i]);
            }
#pragma unroll
            for (int p = 0; p < 2; p++) {
                ldmx4(adB[p] + so + s * 32, bh[p]);
                ldmx4(adB[p] + so + ARR * 2 + s * 32, bl[p]);
            }
#pragma unroll
            for (int i = 0; i < 4; i++)
#pragma unroll
                for (int j = 0; j < 4; j++) {
                    int p = j >> 1, q = j & 1;
                    mma16816(acc[i][j], ah[i], bh[p][q], bh[p][2 + q]);
                    mma16816(acc[i][j], ah[i], bl[p][q], bl[p][2 + q]);
                    mma16816(acc[i][j], al[i], bh[p][q], bh[p][2 + q]);
                }
        }
        __syncthreads();
    }

    // epilogue
    int g = lane >> 2, t2 = (lane & 3) * 2;
#pragma unroll
    for (int i = 0; i < 4; i++) {
        int rA = row0 + wm * 64 + i * 16 + g;
#pragma unroll
        for (int j = 0; j < 4; j++) {
            int cA = col0 + wn * 32 + j * 8 + t2;
            float v0 = acc[i][j][0], v1 = acc[i][j][1];
            float w0 = acc[i][j][2], w1 = acc[i][j][3];
            if (MODE == 0 || MODE == 1 || MODE == 2) {
                float b0 = bias[cA], b1 = bias[cA + 1];
                v0 += b0; v1 += b1; w0 += b0; w1 += b1;
            }
            if (MODE == 1) {
                v0 = 0.5f * v0 * (1.0f + erff(v0 * 0.70710678118654752440f));
                v1 = 0.5f * v1 * (1.0f + erff(v1 * 0.70710678118654752440f));
                w0 = 0.5f * w0 * (1.0f + erff(w0 * 0.70710678118654752440f));
                w1 = 0.5f * w1 * (1.0f + erff(w1 * 0.70710678118654752440f));
                __nv_bfloat16 h0, l0, h1, l1;
                __nv_bfloat162 th, tl;
                split_bf16(v0, h0, l0); split_bf16(v1, h1, l1);
                th.x = h0; th.y = h1; tl.x = l0; tl.y = l1;
                *(__nv_bfloat162*)&Ohi[(size_t)rA * N + cA] = th;
                *(__nv_bfloat162*)&Olo[(size_t)rA * N + cA] = tl;
                split_bf16(w0, h0, l0); split_bf16(w1, h1, l1);
                th.x = h0; th.y = h1; tl.x = l0; tl.y = l1;
                *(__nv_bfloat162*)&Ohi[(size_t)(rA + 8) * N + cA] = th;
                *(__nv_bfloat162*)&Olo[(size_t)(rA + 8) * N + cA] = tl;
            } else {
                if (MODE == 2) {
                    float2 q0 = *(const float2*)&res[(size_t)rA * N + cA];
                    float2 q1 = *(const float2*)&res[(size_t)(rA + 8) * N + cA];
                    v0 += q0.x; v1 += q0.y; w0 += q1.x; w1 += q1.y;
                }
                *(float2*)&C[(size_t)rA * N + cA] = make_float2(v0, v1);
                *(float2*)&C[(size_t)(rA + 8) * N + cA] = make_float2(w0, w1);
            }
        }
    }
}

// ---------------------------------------------------------------------------
// Causal attention, one block per (t, h, b). qkv fp32 in; y split-bf16 out.
__global__ void attn_k(const float* __restrict__ qkv,
                       __nv_bfloat16* __restrict__ y_hi, __nv_bfloat16* __restrict__ y_lo) {
    __shared__ float qs[DH];
    __shared__ float sc[TSEQ];
    __shared__ float red[128];
    int t = blockIdx.x, h = blockIdx.y, b = blockIdx.z;
    int tid = threadIdx.x;
    const float* base = qkv + (size_t)b * TSEQ * (3 * CH);
    if (tid < DH) qs[tid] = base[(size_t)t * (3 * CH) + h * DH + tid];
    __syncthreads();
    int nS = t + 1;
    float lmax = -3.0e38f;
    for (int s = tid; s < nS; s += 128) {
        const float* kr = base + (size_t)s * (3 * CH) + CH + h * DH;
        float d = 0.f;
#pragma unroll
        for (int i = 0; i < DH; i++) d += qs[i] * kr[i];
        d *= 0.125f;
        sc[s] = d;
        lmax = fmaxf(lmax, d);
    }
    red[tid] = lmax;
    __syncthreads();
    for (int off = 64; off > 0; off >>= 1) {
        if (tid < off) red[tid] = fmaxf(red[tid], red[tid + off]);
        __syncthreads();
    }
    float mx = red[0];
    __syncthreads();
    float lsum = 0.f;
    for (int s = tid; s < nS; s += 128) {
        float e = __expf(sc[s] - mx);
        sc[s] = e;
        lsum += e;
    }
    red[tid] = lsum;
    __syncthreads();
    for (int off = 64; off > 0; off >>= 1) {
        if (tid < off) red[tid] += red[tid + off];
        __syncthreads();
    }
    float inv = 1.0f / red[0];
    __syncthreads();
    if (tid < DH) {
        const float* vr = base + 2 * CH + h * DH + tid;
        float acc = 0.f;
        for (int s = 0; s < nS; s++) acc += sc[s] * vr[(size_t)s * (3 * CH)];
        float o = acc * inv;
        size_t oi = ((size_t)(b * TSEQ + t)) * CH + h * DH + tid;
        __nv_bfloat16 hh, ll; split_bf16(o, hh, ll);
        y_hi[oi] = hh; y_lo[oi] = ll;
    }
}

// ---------------------------------------------------------------------------
__global__ void zero_loss_k(float* num, float* den) { *num = 0.f; *den = 0.f; }

__global__ void loss_k(const float* __restrict__ logits, const int* __restrict__ tg,
                       float* num, float* den) {
    __shared__ float red[256];
    int row = blockIdx.x;
    const float* lr = logits + (size_t)row * VOC;
    float m = -3.0e38f;
    for (int j = threadIdx.x; j < VOC; j += 256) m = fmaxf(m, lr[j]);
    red[threadIdx.x] = m;
    __syncthreads();
    for (int off = 128; off > 0; off >>= 1) {
        if (threadIdx.x < off) red[threadIdx.x] = fmaxf(red[threadIdx.x], red[threadIdx.x + off]);
        __syncthreads();
    }
    m = red[0];
    __syncthreads();
    float s = 0.f;
    for (int j = threadIdx.x; j < VOC; j += 256) s += __expf(lr[j] - m);
    red[threadIdx.x] = s;
    __syncthreads();
    for (int off = 128; off > 0; off >>= 1) {
        if (threadIdx.x < off) red[threadIdx.x] += red[threadIdx.x + off];
        __syncthreads();
    }
    if (threadIdx.x == 0) {
        int t = tg[row];
        if (t != 0) {
            float lse = m + logf(red[0]);
            float nll = lse - lr[t];
            atomicAdd(num, nll);
            atomicAdd(den, 1.0f);
        }
    }
}

__global__ void final_loss_k(const float* num, const float* den, float* out) {
    out[0] = *num / fmaxf(*den, 1.0f);
}

// ---------------------------------------------------------------------------
extern "C" void kernel_launch(void* const* d_in, const int* in_sizes, int n_in,
                              void* d_out, int out_size) {
    const int*   idx     = (const int*)d_in[0];
    const int*   targets = (const int*)d_in[1];
    const float* wte     = (const float*)d_in[2];
    const float* wpe     = (const float*)d_in[3];
    const float* ln1_g   = (const float*)d_in[4];
    const float* ln1_b   = (const float*)d_in[5];
    const float* attn_w  = (const float*)d_in[6];
    const float* attn_b  = (const float*)d_in[7];
    const float* proj_w  = (const float*)d_in[8];
    const float* proj_b  = (const float*)d_in[9];
    const float* ln2_g   = (const float*)d_in[10];
    const float* ln2_b   = (const float*)d_in[11];
    const float* fc_w    = (const float*)d_in[12];
    const float* fc_b    = (const float*)d_in[13];
    const float* fc2_w   = (const float*)d_in[14];
    const float* fc2_b   = (const float*)d_in[15];
    const float* lnf_g   = (const float*)d_in[16];
    const float* lnf_b   = (const float*)d_in[17];
    float* out = (float*)d_out;

    float *x, *h, *qkv, *pnum, *pden;
    __nv_bfloat16 *h_hi, *h_lo, *y_hi, *y_lo, *m_hi, *m_lo, *wt_hi, *wt_lo, *wte_hi, *wte_lo;
    cudaGetSymbolAddress((void**)&x, g_x);
    cudaGetSymbolAddress((void**)&h, g_h);
    cudaGetSymbolAddress((void**)&qkv, g_qkv);
    cudaGetSymbolAddress((void**)&h_hi, g_h_hi);
    cudaGetSymbolAddress((void**)&h_lo, g_h_lo);
    cudaGetSymbolAddress((void**)&y_hi, g_y_hi);
    cudaGetSymbolAddress((void**)&y_lo, g_y_lo);
    cudaGetSymbolAddress((void**)&m_hi, g_m_hi);
    cudaGetSymbolAddress((void**)&m_lo, g_m_lo);
    cudaGetSymbolAddress((void**)&wt_hi, g_wt_hi);
    cudaGetSymbolAddress((void**)&wt_lo, g_wt_lo);
    cudaGetSymbolAddress((void**)&wte_hi, g_wte_hi);
    cudaGetSymbolAddress((void**)&wte_lo, g_wte_lo);
    cudaGetSymbolAddress((void**)&pnum, g_num);
    cudaGetSymbolAddress((void**)&pden, g_den);

    const size_t LOGN = (size_t)BT * VOC;
    float* out_loss = out + LOGN;
    float* out_x    = out + LOGN + 1;  // 4B-aligned only: scalar access

    // opt-in dynamic smem for the pipelined GEMM (host attr set; idempotent)
    cudaFuncSetAttribute(hgemm_k<0>, cudaFuncAttributeMaxDynamicSharedMemorySize, HSMEM);
    cudaFuncSetAttribute(hgemm_k<1>, cudaFuncAttributeMaxDynamicSharedMemorySize, HSMEM);
    cudaFuncSetAttribute(hgemm_k<2>, cudaFuncAttributeMaxDynamicSharedMemorySize, HSMEM);
    cudaFuncSetAttribute(hgemm_k<3>, cudaFuncAttributeMaxDynamicSharedMemorySize, HSMEM);

    dim3 tblk(32, 8);

    // ---- weight preprocessing (transpose + split-convert) ----
    conv_k<<<(VOC * CH + 255) / 256, 256>>>(wte, wte_hi, wte_lo, VOC * CH);
    for (int l = 0; l < NLAY; l++) {
        tconv_k<<<dim3(2304 / 32, 768 / 32), tblk>>>(
            attn_w + (size_t)l * W_ATTN_SZ, wt_hi + W_ATTN_OFF + (size_t)l * W_ATTN_SZ,
            wt_lo + W_ATTN_OFF + (size_t)l * W_ATTN_SZ, 768, 2304);
        tconv_k<<<dim3(768 / 32, 768 / 32), tblk>>>(
            proj_w + (size_t)l * W_PROJ_SZ, wt_hi + W_PROJ_OFF + (size_t)l * W_PROJ_SZ,
            wt_lo + W_PROJ_OFF + (size_t)l * W_PROJ_SZ, 768, 768);
        tconv_k<<<dim3(3072 / 32, 768 / 32), tblk>>>(
            fc_w + (size_t)l * W_FC_SZ, wt_hi + W_FC_OFF + (size_t)l * W_FC_SZ,
            wt_lo + W_FC_OFF + (size_t)l * W_FC_SZ, 768, 3072);
        tconv_k<<<dim3(768 / 32, 3072 / 32), tblk>>>(
            fc2_w + (size_t)l * W_FC2_SZ, wt_hi + W_FC2_OFF + (size_t)l * W_FC2_SZ,
            wt_lo + W_FC2_OFF + (size_t)l * W_FC2_SZ, 3072, 768);
    }

    embed_k<<<BT, 256>>>(idx, wte, wpe, x);

    for (int l = 0; l < NLAY; l++) {
        const __nv_bfloat16* wa_h = wt_hi + W_ATTN_OFF + (size_t)l * W_ATTN_SZ;
        const __nv_bfloat16* wa_l = wt_lo + W_ATTN_OFF + (size_t)l * W_ATTN_SZ;
        const __nv_bfloat16* wp_h = wt_hi + W_PROJ_OFF + (size_t)l * W_PROJ_SZ;
        const __nv_bfloat16* wp_l = wt_lo + W_PROJ_OFF + (size_t)l * W_PROJ_SZ;
        const __nv_bfloat16* wf_h = wt_hi + W_FC_OFF + (size_t)l * W_FC_SZ;
        const __nv_bfloat16* wf_l = wt_lo + W_FC_OFF + (size_t)l * W_FC_SZ;
        const __nv_bfloat16* w2_h = wt_hi + W_FC2_OFF + (size_t)l * W_FC2_SZ;
        const __nv_bfloat16* w2_l = wt_lo + W_FC2_OFF + (size_t)l * W_FC2_SZ;

        ln_k<<<BT, 256>>>(x, ln1_g + l * CH, ln1_b + l * CH, h, h_hi, h_lo);
        hgemm_k<0><<<dim3(2304 / 128, BT / 128), 256, HSMEM>>>(
            h_hi, h_lo, wa_h, wa_l, attn_b + (size_t)l * 3 * CH,
            nullptr, qkv, nullptr, nullptr, BT, 3 * CH, CH);
        attn_k<<<dim3(TSEQ, NH, 4), 128>>>(qkv, y_hi, y_lo);
        hgemm_k<2><<<dim3(CH / 128, BT / 128), 256, HSMEM>>>(
            y_hi, y_lo, wp_h, wp_l, proj_b + (size_t)l * CH,
            x, x, nullptr, nullptr, BT, CH, CH);
        ln_k<<<BT, 256>>>(x, ln2_g + l * CH, ln2_b + l * CH, h, h_hi, h_lo);
        hgemm_k<1><<<dim3(4 * CH / 128, BT / 128), 256, HSMEM>>>(
            h_hi, h_lo, wf_h, wf_l, fc_b + (size_t)l * 4 * CH,
            nullptr, nullptr, m_hi, m_lo, BT, 4 * CH, CH);
        hgemm_k<2><<<dim3(CH / 128, BT / 128), 256, HSMEM>>>(
            m_hi, m_lo, w2_h, w2_l, fc2_b + (size_t)l * CH,
            x, x, nullptr, nullptr, BT, CH, 4 * CH);
    }

    ln_k<<<BT, 256>>>(x, lnf_g, lnf_b, h, h_hi, h_lo);
    copy_k<<<(BT * CH + 255) / 256, 256>>>(h, out_x, BT * CH);
    hgemm_k<3><<<dim3(VOC / 128, BT / 128), 256, HSMEM>>>(
        h_hi, h_lo, wte_hi, wte_lo, nullptr, nullptr, out, nullptr, nullptr,
        BT, VOC, CH);
    zero_loss_k<<<1, 1>>>(pnum, pden);
    loss_k<<<BT, 256>>>(out, targets, pnum, pden);
    final_loss_k<<<1, 1>>>(pnum, pden, out_loss);
}

// round 12
// speedup vs baseline: 2.2696x; 1.0987x over previous
#include <cuda_runtime.h>
#include <cuda_bf16.h>
#include <cuda_fp16.h>
#include <math.h>
#include <stdint.h>

// ---------------------------------------------------------------------------
// GPT-2 small forward: L=6, C=768, H=12, D=64, B=4, T=1024, V=32000
// Output layout: logits [4096*32000] | loss [1] | x_final [4096*768]
// Round 12: single-term fp16 mma.sync GEMMs (tcgen05 unavailable: harness PTX
// target is sm_103 non-'a').  1/3 the MMA instructions of split-bf16.
// ---------------------------------------------------------------------------

#define BT   4096
#define CH   768
#define NH   12
#define DH   64
#define TSEQ 1024
#define VOC  32000
#define NLAY 6

#define W_ATTN_OFF 0
#define W_ATTN_SZ  (2304 * 768)
#define W_PROJ_OFF (W_ATTN_OFF + 6 * W_ATTN_SZ)
#define W_PROJ_SZ  (768 * 768)
#define W_FC_OFF   (W_PROJ_OFF + 6 * W_PROJ_SZ)
#define W_FC_SZ    (3072 * 768)
#define W_FC2_OFF  (W_FC_OFF + 6 * W_FC_SZ)
#define W_FC2_SZ   (768 * 3072)
#define W_TOTAL    (W_FC2_OFF + 6 * W_FC2_SZ)

// Scratch (device globals: no allocation allowed)
__device__ float g_x[BT * CH];
__device__ float g_hf[BT * CH];
__device__ float g_qkv[BT * 3 * CH];
__device__ __half g_h_h[BT * CH];
__device__ __half g_y_h[BT * CH];
__device__ __half g_m_h[BT * 4 * CH];
__device__ __half g_wt_h[W_TOTAL];
__device__ __half g_wte_h[VOC * CH];
__device__ float g_num;
__device__ float g_den;

// ---------------------------------------------------------------------------
__global__ void conv_k(const float* __restrict__ src, __half* __restrict__ dst, int n) {
    int i = blockIdx.x * 256 + threadIdx.x;
    if (i < n) dst[i] = __float2half(src[i]);
}

// transpose + convert: W[K,N] fp32 -> T[N,K] fp16
__global__ void tconv_k(const float* __restrict__ W, __half* __restrict__ T,
                        int K, int N) {
    __shared__ float s[32][33];
    int n0 = blockIdx.x * 32, k0 = blockIdx.y * 32;
    int tx = threadIdx.x, ty = threadIdx.y;
#pragma unroll
    for (int i = 0; i < 4; i++)
        s[ty + i * 8][tx] = W[(size_t)(k0 + ty + i * 8) * N + n0 + tx];
    __syncthreads();
#pragma unroll
    for (int i = 0; i < 4; i++)
        T[(size_t)(n0 + ty + i * 8) * K + k0 + tx] = __float2half(s[tx][ty + i * 8]);
}

// ---------------------------------------------------------------------------
__global__ void embed_k(const int* __restrict__ idx, const float* __restrict__ wte,
                        const float* __restrict__ wpe, float* __restrict__ x) {
    int row = blockIdx.x;
    int t = row & (TSEQ - 1);
    int tok = idx[row];
    const float* a = wte + (size_t)tok * CH;
    const float* b = wpe + (size_t)t * CH;
    float* o = x + (size_t)row * CH;
    for (int c = threadIdx.x; c < CH; c += blockDim.x) o[c] = a[c] + b[c];
}

__global__ void copy_k(const float* __restrict__ src, float* __restrict__ dst, int n) {
    int i = blockIdx.x * blockDim.x + threadIdx.x;
    if (i < n) dst[i] = src[i];
}

// LayerNorm: fp32 out + fp16 out
__global__ void ln_k(const float* __restrict__ x, const float* __restrict__ g,
                     const float* __restrict__ b, float* __restrict__ o,
                     __half* __restrict__ oh) {
    __shared__ float r1[256], r2[256];
    int row = blockIdx.x;
    const float* xr = x + (size_t)row * CH;
    float s = 0.f, s2 = 0.f;
    for (int i = threadIdx.x; i < CH; i += 256) { float v = xr[i]; s += v; s2 += v * v; }
    r1[threadIdx.x] = s; r2[threadIdx.x] = s2;
    __syncthreads();
    for (int off = 128; off > 0; off >>= 1) {
        if (threadIdx.x < off) {
            r1[threadIdx.x] += r1[threadIdx.x + off];
            r2[threadIdx.x] += r2[threadIdx.x + off];
        }
        __syncthreads();
    }
    float mean = r1[0] * (1.0f / CH);
    float var  = r2[0] * (1.0f / CH) - mean * mean;
    float rstd = rsqrtf(var + 1e-5f);
    for (int i = threadIdx.x; i < CH; i += 256) {
        float v = (xr[i] - mean) * rstd * g[i] + b[i];
        size_t oo = (size_t)row * CH + i;
        o[oo] = v;
        oh[oo] = __float2half(v);
    }
}

// ---------------------------------------------------------------------------
// tensor-core / async primitives
__device__ __forceinline__ void ldmx4(unsigned addr, unsigned r[4]) {
    asm volatile("ldmatrix.sync.aligned.m8n8.x4.shared.b16 {%0,%1,%2,%3}, [%4];"
                 : "=r"(r[0]), "=r"(r[1]), "=r"(r[2]), "=r"(r[3]) : "r"(addr));
}
__device__ __forceinline__ void mma16816h(float d[4], const unsigned a[4],
                                          unsigned b0, unsigned b1) {
    asm volatile("mma.sync.aligned.m16n8k16.row.col.f32.f16.f16.f32 "
                 "{%0,%1,%2,%3},{%4,%5,%6,%7},{%8,%9},{%0,%1,%2,%3};"
                 : "+f"(d[0]), "+f"(d[1]), "+f"(d[2]), "+f"(d[3])
                 : "r"(a[0]), "r"(a[1]), "r"(a[2]), "r"(a[3]), "r"(b0), "r"(b1));
}
__device__ __forceinline__ void cp16(unsigned sa, const void* gm) {
    asm volatile("cp.async.cg.shared.global [%0], [%1], 16;" :: "r"(sa), "l"(gm));
}
__device__ __forceinline__ void cp_commit() { asm volatile("cp.async.commit_group;"); }
template <int N>
__device__ __forceinline__ void cp_wait() {
    asm volatile("cp.async.wait_group %0;" :: "n"(N));
}

#define SPITCH 40                    // smem row pitch (fp16); 80B, ldmatrix-conflict-free
#define ARR    (128 * SPITCH)        // elements per tile array
#define STGB   (2 * ARR * 2)         // bytes per stage (A + B) = 20480
#define HSMEM  (2 * STGB)            // 40960

// ---------------------------------------------------------------------------
// fp16 NT GEMM: D[M,N] = A[M,K] @ (B[N,K])^T, fp32 accum, single term.
// 128x128 tile, 256 threads (8 warps of 64x32), k-chunk 32, cp.async 2-stage.
// MODE 0: +bias -> fp32.  MODE 1: +bias, exact GELU -> fp16 O.
// MODE 2: +bias +res -> fp32.  MODE 3: plain -> fp32.
template <int MODE>
__global__ __launch_bounds__(256, 2)
void hgemm_k(const __half* __restrict__ A, const __half* __restrict__ B,
             const float* __restrict__ bias, const float* __restrict__ res,
             float* __restrict__ C, __half* __restrict__ O,
             int M, int N, int K) {
    extern __shared__ __align__(16) __half smbuf[];
    int tid = threadIdx.x, lane = tid & 31, wid = tid >> 5;
    int wm = wid >> 2, wn = wid & 3;
    int row0 = blockIdx.y * 128, col0 = blockIdx.x * 128;

    int r0 = tid >> 2, sg = (tid & 3) * 8;
    size_t aoff0 = (size_t)(row0 + r0) * K + sg;
    size_t aoff1 = aoff0 + (size_t)64 * K;
    size_t boff0 = (size_t)(col0 + r0) * K + sg;
    size_t boff1 = boff0 + (size_t)64 * K;
    int sm0 = r0 * SPITCH + sg, sm1 = sm0 + 64 * SPITCH;

    unsigned smbase = (unsigned)__cvta_generic_to_shared(smbuf);
    unsigned dA0 = smbase + sm0 * 2,           dA1 = smbase + sm1 * 2;
    unsigned dB0 = smbase + (ARR + sm0) * 2,   dB1 = smbase + (ARR + sm1) * 2;

    int lr  = (lane & 7) + ((lane >> 3) & 1) * 8;
    int lcb = (lane >> 4) * 16;
    unsigned adA[4], adB[2];
#pragma unroll
    for (int i = 0; i < 4; i++) {
        int rr = wm * 64 + i * 16 + lr;
        adA[i] = smbase + (unsigned)(rr * SPITCH) * 2 + lcb;
    }
#pragma unroll
    for (int p = 0; p < 2; p++) {
        int rr = wn * 32 + p * 16 + lr;
        adB[p] = smbase + (unsigned)(ARR + rr * SPITCH) * 2 + lcb;
    }

    float acc[4][4][4];
#pragma unroll
    for (int i = 0; i < 4; i++)
#pragma unroll
        for (int j = 0; j < 4; j++)
#pragma unroll
            for (int q = 0; q < 4; q++) acc[i][j][q] = 0.f;

    int nC = K >> 5;
    // prologue: chunk 0 -> stage 0
    cp16(dA0, A + aoff0); cp16(dA1, A + aoff1);
    cp16(dB0, B + boff0); cp16(dB1, B + boff1);
    cp_commit();

    for (int c = 0; c < nC; c++) {
        if (c + 1 < nC) {
            unsigned so = (unsigned)((c + 1) & 1) * STGB;
            size_t ko = (size_t)(c + 1) << 5;
            cp16(dA0 + so, A + aoff0 + ko); cp16(dA1 + so, A + aoff1 + ko);
            cp16(dB0 + so, B + boff0 + ko); cp16(dB1 + so, B + boff1 + ko);
            cp_commit();
            cp_wait<1>();
        } else {
            cp_wait<0>();
        }
        __syncthreads();

        unsigned so = (unsigned)(c & 1) * STGB;
#pragma unroll
        for (int s = 0; s < 2; s++) {
            unsigned ah[4][4], bh[2][4];
#pragma unroll
            for (int i = 0; i < 4; i++) ldmx4(adA[i] + so + s * 32, ah[i]);
#pragma unroll
            for (int p = 0; p < 2; p++) ldmx4(adB[p] + so + s * 32, bh[p]);
#pragma unroll
            for (int i = 0; i < 4; i++)
#pragma unroll
                for (int j = 0; j < 4; j++) {
                    int p = j >> 1, q = j & 1;
                    mma16816h(acc[i][j], ah[i], bh[p][q], bh[p][2 + q]);
                }
        }
        __syncthreads();
    }

    // epilogue
    int g = lane >> 2, t2 = (lane & 3) * 2;
#pragma unroll
    for (int i = 0; i < 4; i++) {
        int rA = row0 + wm * 64 + i * 16 + g;
#pragma unroll
        for (int j = 0; j < 4; j++) {
            int cA = col0 + wn * 32 + j * 8 + t2;
            float v0 = acc[i][j][0], v1 = acc[i][j][1];
            float w0 = acc[i][j][2], w1 = acc[i][j][3];
            if (MODE == 0 || MODE == 1 || MODE == 2) {
                float b0 = bias[cA], b1 = bias[cA + 1];
                v0 += b0; v1 += b1; w0 += b0; w1 += b1;
            }
            if (MODE == 1) {
                v0 = 0.5f * v0 * (1.0f + erff(v0 * 0.70710678118654752440f));
                v1 = 0.5f * v1 * (1.0f + erff(v1 * 0.70710678118654752440f));
                w0 = 0.5f * w0 * (1.0f + erff(w0 * 0.70710678118654752440f));
                w1 = 0.5f * w1 * (1.0f + erff(w1 * 0.70710678118654752440f));
                __half2 t0 = __floats2half2_rn(v0, v1);
                __half2 t1 = __floats2half2_rn(w0, w1);
                *(__half2*)&O[(size_t)rA * N + cA] = t0;
                *(__half2*)&O[(size_t)(rA + 8) * N + cA] = t1;
            } else {
                if (MODE == 2) {
                    float2 q0 = *(const float2*)&res[(size_t)rA * N + cA];
                    float2 q1 = *(const float2*)&res[(size_t)(rA + 8) * N + cA];
                    v0 += q0.x; v1 += q0.y; w0 += q1.x; w1 += q1.y;
                }
                *(float2*)&C[(size_t)rA * N + cA] = make_float2(v0, v1);
                *(float2*)&C[(size_t)(rA + 8) * N + cA] = make_float2(w0, w1);
            }
        }
    }
}

// ---------------------------------------------------------------------------
// Causal attention, one block per (t, h, b). qkv fp32 in; y fp16 out.
__global__ void attn_k(const float* __restrict__ qkv, __half* __restrict__ y_h) {
    __shared__ float qs[DH];
    __shared__ float sc[TSEQ];
    __shared__ float red[128];
    int t = blockIdx.x, h = blockIdx.y, b = blockIdx.z;
    int tid = threadIdx.x;
    const float* base = qkv + (size_t)b * TSEQ * (3 * CH);
    if (tid < DH) qs[tid] = base[(size_t)t * (3 * CH) + h * DH + tid];
    __syncthreads();
    int nS = t + 1;
    float lmax = -3.0e38f;
    for (int s = tid; s < nS; s += 128) {
        const float* kr = base + (size_t)s * (3 * CH) + CH + h * DH;
        float d = 0.f;
#pragma unroll
        for (int i = 0; i < DH; i++) d += qs[i] * kr[i];
        d *= 0.125f;
        sc[s] = d;
        lmax = fmaxf(lmax, d);
    }
    red[tid] = lmax;
    __syncthreads();
    for (int off = 64; off > 0; off >>= 1) {
        if (tid < off) red[tid] = fmaxf(red[tid], red[tid + off]);
        __syncthreads();
    }
    float mx = red[0];
    __syncthreads();
    float lsum = 0.f;
    for (int s = tid; s < nS; s += 128) {
        float e = __expf(sc[s] - mx);
        sc[s] = e;
        lsum += e;
    }
    red[tid] = lsum;
    __syncthreads();
    for (int off = 64; off > 0; off >>= 1) {
        if (tid < off) red[tid] += red[tid + off];
        __syncthreads();
    }
    float inv = 1.0f / red[0];
    __syncthreads();
    if (tid < DH) {
        const float* vr = base + 2 * CH + h * DH + tid;
        float acc = 0.f;
        for (int s = 0; s < nS; s++) acc += sc[s] * vr[(size_t)s * (3 * CH)];
        y_h[((size_t)(b * TSEQ + t)) * CH + h * DH + tid] = __float2half(acc * inv);
    }
}

// ---------------------------------------------------------------------------
__global__ void zero_loss_k(float* num, float* den) { *num = 0.f; *den = 0.f; }

// single-pass online log-sum-exp NLL
__global__ void loss_k(const float* __restrict__ logits, const int* __restrict__ tg,
                       float* num, float* den) {
    __shared__ float rm[256], rs[256];
    int row = blockIdx.x;
    const float* lr = logits + (size_t)row * VOC;
    float m = -3.0e38f, s = 0.f;
    for (int j = threadIdx.x; j < VOC; j += 256) {
        float v = lr[j];
        if (v > m) { s = s * __expf(m - v) + 1.0f; m = v; }
        else s += __expf(v - m);
    }
    rm[threadIdx.x] = m; rs[threadIdx.x] = s;
    __syncthreads();
    for (int off = 128; off > 0; off >>= 1) {
        if (threadIdx.x < off) {
            float m2 = rm[threadIdx.x + off], s2 = rs[threadIdx.x + off];
            float m1 = rm[threadIdx.x], s1 = rs[threadIdx.x];
            float mn = fmaxf(m1, m2);
            rs[threadIdx.x] = s1 * __expf(m1 - mn) + s2 * __expf(m2 - mn);
            rm[threadIdx.x] = mn;
        }
        __syncthreads();
    }
    if (threadIdx.x == 0) {
        int t = tg[row];
        if (t != 0) {
            float lse = rm[0] + logf(rs[0]);
            atomicAdd(num, lse - lr[t]);
            atomicAdd(den, 1.0f);
        }
    }
}

__global__ void final_loss_k(const float* num, const float* den, float* out) {
    out[0] = *num / fmaxf(*den, 1.0f);
}

// ---------------------------------------------------------------------------
extern "C" void kernel_launch(void* const* d_in, const int* in_sizes, int n_in,
                              void* d_out, int out_size) {
    const int*   idx     = (const int*)d_in[0];
    const int*   targets = (const int*)d_in[1];
    const float* wte     = (const float*)d_in[2];
    const float* wpe     = (const float*)d_in[3];
    const float* ln1_g   = (const float*)d_in[4];
    const float* ln1_b   = (const float*)d_in[5];
    const float* attn_w  = (const float*)d_in[6];
    const float* attn_b  = (const float*)d_in[7];
    const float* proj_w  = (const float*)d_in[8];
    const float* proj_b  = (const float*)d_in[9];
    const float* ln2_g   = (const float*)d_in[10];
    const float* ln2_b   = (const float*)d_in[11];
    const float* fc_w    = (const float*)d_in[12];
    const float* fc_b    = (const float*)d_in[13];
    const float* fc2_w   = (const float*)d_in[14];
    const float* fc2_b   = (const float*)d_in[15];
    const float* lnf_g   = (const float*)d_in[16];
    const float* lnf_b   = (const float*)d_in[17];
    float* out = (float*)d_out;

    float *x, *h, *qkv, *pnum, *pden;
    __half *h_h, *y_h, *m_h, *wt_h, *wte_h;
    cudaGetSymbolAddress((void**)&x, g_x);
    cudaGetSymbolAddress((void**)&h, g_hf);
    cudaGetSymbolAddress((void**)&qkv, g_qkv);
    cudaGetSymbolAddress((void**)&h_h, g_h_h);
    cudaGetSymbolAddress((void**)&y_h, g_y_h);
    cudaGetSymbolAddress((void**)&m_h, g_m_h);
    cudaGetSymbolAddress((void**)&wt_h, g_wt_h);
    cudaGetSymbolAddress((void**)&wte_h, g_wte_h);
    cudaGetSymbolAddress((void**)&pnum, g_num);
    cudaGetSymbolAddress((void**)&pden, g_den);

    const size_t LOGN = (size_t)BT * VOC;
    float* out_loss = out + LOGN;
    float* out_x    = out + LOGN + 1;  // 4B-aligned only: scalar access

    cudaFuncSetAttribute(hgemm_k<0>, cudaFuncAttributeMaxDynamicSharedMemorySize, HSMEM);
    cudaFuncSetAttribute(hgemm_k<1>, cudaFuncAttributeMaxDynamicSharedMemorySize, HSMEM);
    cudaFuncSetAttribute(hgemm_k<2>, cudaFuncAttributeMaxDynamicSharedMemorySize, HSMEM);
    cudaFuncSetAttribute(hgemm_k<3>, cudaFuncAttributeMaxDynamicSharedMemorySize, HSMEM);

    dim3 tblk(32, 8);

    // ---- weight preprocessing (transpose + fp16 convert) ----
    conv_k<<<(VOC * CH + 255) / 256, 256>>>(wte, wte_h, VOC * CH);
    for (int l = 0; l < NLAY; l++) {
        tconv_k<<<dim3(2304 / 32, 768 / 32), tblk>>>(
            attn_w + (size_t)l * W_ATTN_SZ, wt_h + W_ATTN_OFF + (size_t)l * W_ATTN_SZ, 768, 2304);
        tconv_k<<<dim3(768 / 32, 768 / 32), tblk>>>(
            proj_w + (size_t)l * W_PROJ_SZ, wt_h + W_PROJ_OFF + (size_t)l * W_PROJ_SZ, 768, 768);
        tconv_k<<<dim3(3072 / 32, 768 / 32), tblk>>>(
            fc_w + (size_t)l * W_FC_SZ, wt_h + W_FC_OFF + (size_t)l * W_FC_SZ, 768, 3072);
        tconv_k<<<dim3(768 / 32, 3072 / 32), tblk>>>(
            fc2_w + (size_t)l * W_FC2_SZ, wt_h + W_FC2_OFF + (size_t)l * W_FC2_SZ, 3072, 768);
    }

    embed_k<<<BT, 256>>>(idx, wte, wpe, x);

    for (int l = 0; l < NLAY; l++) {
        const __half* wa = wt_h + W_ATTN_OFF + (size_t)l * W_ATTN_SZ;
        const __half* wp = wt_h + W_PROJ_OFF + (size_t)l * W_PROJ_SZ;
        const __half* wf = wt_h + W_FC_OFF + (size_t)l * W_FC_SZ;
        const __half* w2 = wt_h + W_FC2_OFF + (size_t)l * W_FC2_SZ;

        ln_k<<<BT, 256>>>(x, ln1_g + l * CH, ln1_b + l * CH, h, h_h);
        hgemm_k<0><<<dim3(2304 / 128, BT / 128), 256, HSMEM>>>(
            h_h, wa, attn_b + (size_t)l * 3 * CH, nullptr, qkv, nullptr, BT, 3 * CH, CH);
        attn_k<<<dim3(TSEQ, NH, 4), 128>>>(qkv, y_h);
        hgemm_k<2><<<dim3(CH / 128, BT / 128), 256, HSMEM>>>(
            y_h, wp, proj_b + (size_t)l * CH, x, x, nullptr, BT, CH, CH);
        ln_k<<<BT, 256>>>(x, ln2_g + l * CH, ln2_b + l * CH, h, h_h);
        hgemm_k<1><<<dim3(4 * CH / 128, BT / 128), 256, HSMEM>>>(
            h_h, wf, fc_b + (size_t)l * 4 * CH, nullptr, nullptr, m_h, BT, 4 * CH, CH);
        hgemm_k<2><<<dim3(CH / 128, BT / 128), 256, HSMEM>>>(
            m_h, w2, fc2_b + (size_t)l * CH, x, x, nullptr, BT, CH, 4 * CH);
    }

    ln_k<<<BT, 256>>>(x, lnf_g, lnf_b, h, h_h);
    copy_k<<<(BT * CH + 255) / 256, 256>>>(h, out_x, BT * CH);
    hgemm_k<3><<<dim3(VOC / 128, BT / 128), 256, HSMEM>>>(
        h_h, wte_h, nullptr, nullptr, out, nullptr, BT, VOC, CH);
    zero_loss_k<<<1, 1>>>(pnum, pden);
    loss_k<<<BT, 256>>>(out, targets, pnum, pden);
    final_loss_k<<<1, 1>>>(pnum, pden, out_loss);
}

// round 13
// speedup vs baseline: 25.8852x; 11.4051x over previous
#include <cuda_runtime.h>
#include <cuda_bf16.h>
#include <cuda_fp16.h>
#include <math.h>
#include <stdint.h>

// ---------------------------------------------------------------------------
// GPT-2 small forward: L=6, C=768, H=12, D=64, B=4, T=1024, V=32000
// Output layout: logits [4096*32000] | loss [1] | x_final [4096*768]
// Round 13: fp16 mma GEMMs + FLASH ATTENTION (tiled, fp16 mma, online softmax)
// replacing the serial per-(b,h,t) attention kernel.
// ---------------------------------------------------------------------------

#define BT   4096
#define CH   768
#define NH   12
#define DH   64
#define TSEQ 1024
#define VOC  32000
#define NLAY 6

#define W_ATTN_OFF 0
#define W_ATTN_SZ  (2304 * 768)
#define W_PROJ_OFF (W_ATTN_OFF + 6 * W_ATTN_SZ)
#define W_PROJ_SZ  (768 * 768)
#define W_FC_OFF   (W_PROJ_OFF + 6 * W_PROJ_SZ)
#define W_FC_SZ    (3072 * 768)
#define W_FC2_OFF  (W_FC_OFF + 6 * W_FC_SZ)
#define W_FC2_SZ   (768 * 3072)
#define W_TOTAL    (W_FC2_OFF + 6 * W_FC2_SZ)

// Scratch (device globals: no allocation allowed)
__device__ float g_x[BT * CH];
__device__ float g_hf[BT * CH];
__device__ __half g_qkv_h[BT * 3 * CH];
__device__ __half g_h_h[BT * CH];
__device__ __half g_y_h[BT * CH];
__device__ __half g_m_h[BT * 4 * CH];
__device__ __half g_wt_h[W_TOTAL];
__device__ __half g_wte_h[VOC * CH];
__device__ float g_num;
__device__ float g_den;

// ---------------------------------------------------------------------------
__global__ void conv_k(const float* __restrict__ src, __half* __restrict__ dst, int n) {
    int i = blockIdx.x * 256 + threadIdx.x;
    if (i < n) dst[i] = __float2half(src[i]);
}

__global__ void tconv_k(const float* __restrict__ W, __half* __restrict__ T,
                        int K, int N) {
    __shared__ float s[32][33];
    int n0 = blockIdx.x * 32, k0 = blockIdx.y * 32;
    int tx = threadIdx.x, ty = threadIdx.y;
#pragma unroll
    for (int i = 0; i < 4; i++)
        s[ty + i * 8][tx] = W[(size_t)(k0 + ty + i * 8) * N + n0 + tx];
    __syncthreads();
#pragma unroll
    for (int i = 0; i < 4; i++)
        T[(size_t)(n0 + ty + i * 8) * K + k0 + tx] = __float2half(s[tx][ty + i * 8]);
}

// ---------------------------------------------------------------------------
__global__ void embed_k(const int* __restrict__ idx, const float* __restrict__ wte,
                        const float* __restrict__ wpe, float* __restrict__ x) {
    int row = blockIdx.x;
    int t = row & (TSEQ - 1);
    int tok = idx[row];
    const float* a = wte + (size_t)tok * CH;
    const float* b = wpe + (size_t)t * CH;
    float* o = x + (size_t)row * CH;
    for (int c = threadIdx.x; c < CH; c += blockDim.x) o[c] = a[c] + b[c];
}

__global__ void copy_k(const float* __restrict__ src, float* __restrict__ dst, int n) {
    int i = blockIdx.x * blockDim.x + threadIdx.x;
    if (i < n) dst[i] = src[i];
}

__global__ void ln_k(const float* __restrict__ x, const float* __restrict__ g,
                     const float* __restrict__ b, float* __restrict__ o,
                     __half* __restrict__ oh) {
    __shared__ float r1[256], r2[256];
    int row = blockIdx.x;
    const float* xr = x + (size_t)row * CH;
    float s = 0.f, s2 = 0.f;
    for (int i = threadIdx.x; i < CH; i += 256) { float v = xr[i]; s += v; s2 += v * v; }
    r1[threadIdx.x] = s; r2[threadIdx.x] = s2;
    __syncthreads();
    for (int off = 128; off > 0; off >>= 1) {
        if (threadIdx.x < off) {
            r1[threadIdx.x] += r1[threadIdx.x + off];
            r2[threadIdx.x] += r2[threadIdx.x + off];
        }
        __syncthreads();
    }
    float mean = r1[0] * (1.0f / CH);
    float var  = r2[0] * (1.0f / CH) - mean * mean;
    float rstd = rsqrtf(var + 1e-5f);
    for (int i = threadIdx.x; i < CH; i += 256) {
        float v = (xr[i] - mean) * rstd * g[i] + b[i];
        size_t oo = (size_t)row * CH + i;
        o[oo] = v;
        oh[oo] = __float2half(v);
    }
}

// ---------------------------------------------------------------------------
// primitives
__device__ __forceinline__ void ldmx4(unsigned addr, unsigned r[4]) {
    asm volatile("ldmatrix.sync.aligned.m8n8.x4.shared.b16 {%0,%1,%2,%3}, [%4];"
                 : "=r"(r[0]), "=r"(r[1]), "=r"(r[2]), "=r"(r[3]) : "r"(addr));
}
__device__ __forceinline__ void ldmx4t(unsigned addr, unsigned r[4]) {
    asm volatile("ldmatrix.sync.aligned.m8n8.x4.trans.shared.b16 {%0,%1,%2,%3}, [%4];"
                 : "=r"(r[0]), "=r"(r[1]), "=r"(r[2]), "=r"(r[3]) : "r"(addr));
}
__device__ __forceinline__ void mma16816h(float d[4], const unsigned a[4],
                                          unsigned b0, unsigned b1) {
    asm volatile("mma.sync.aligned.m16n8k16.row.col.f32.f16.f16.f32 "
                 "{%0,%1,%2,%3},{%4,%5,%6,%7},{%8,%9},{%0,%1,%2,%3};"
                 : "+f"(d[0]), "+f"(d[1]), "+f"(d[2]), "+f"(d[3])
                 : "r"(a[0]), "r"(a[1]), "r"(a[2]), "r"(a[3]), "r"(b0), "r"(b1));
}
__device__ __forceinline__ void cp16(unsigned sa, const void* gm) {
    asm volatile("cp.async.cg.shared.global [%0], [%1], 16;" :: "r"(sa), "l"(gm));
}
__device__ __forceinline__ void cp_commit() { asm volatile("cp.async.commit_group;"); }
template <int N>
__device__ __forceinline__ void cp_wait() {
    asm volatile("cp.async.wait_group %0;" :: "n"(N));
}

#define SPITCH 40
#define ARR    (128 * SPITCH)
#define STGB   (2 * ARR * 2)
#define HSMEM  (2 * STGB)

// ---------------------------------------------------------------------------
// fp16 NT GEMM: D[M,N] = A[M,K] @ (B[N,K])^T, fp32 accum.
// MODE 0: +bias->fp32.  MODE 1: +bias,GELU->fp16.  MODE 2: +bias+res->fp32.
// MODE 3: plain->fp32.  MODE 4: +bias->fp16.
template <int MODE>
__global__ __launch_bounds__(256, 2)
void hgemm_k(const __half* __restrict__ A, const __half* __restrict__ B,
             const float* __restrict__ bias, const float* __restrict__ res,
             float* __restrict__ C, __half* __restrict__ O,
             int M, int N, int K) {
    extern __shared__ __align__(16) __half smbuf[];
    int tid = threadIdx.x, lane = tid & 31, wid = tid >> 5;
    int wm = wid >> 2, wn = wid & 3;
    int row0 = blockIdx.y * 128, col0 = blockIdx.x * 128;

    int r0 = tid >> 2, sg = (tid & 3) * 8;
    size_t aoff0 = (size_t)(row0 + r0) * K + sg;
    size_t aoff1 = aoff0 + (size_t)64 * K;
    size_t boff0 = (size_t)(col0 + r0) * K + sg;
    size_t boff1 = boff0 + (size_t)64 * K;
    int sm0 = r0 * SPITCH + sg, sm1 = sm0 + 64 * SPITCH;

    unsigned smbase = (unsigned)__cvta_generic_to_shared(smbuf);
    unsigned dA0 = smbase + sm0 * 2,         dA1 = smbase + sm1 * 2;
    unsigned dB0 = smbase + (ARR + sm0) * 2, dB1 = smbase + (ARR + sm1) * 2;

    int lr  = (lane & 7) + ((lane >> 3) & 1) * 8;
    int lcb = (lane >> 4) * 16;
    unsigned adA[4], adB[2];
#pragma unroll
    for (int i = 0; i < 4; i++) {
        int rr = wm * 64 + i * 16 + lr;
        adA[i] = smbase + (unsigned)(rr * SPITCH) * 2 + lcb;
    }
#pragma unroll
    for (int p = 0; p < 2; p++) {
        int rr = wn * 32 + p * 16 + lr;
        adB[p] = smbase + (unsigned)(ARR + rr * SPITCH) * 2 + lcb;
    }

    float acc[4][4][4];
#pragma unroll
    for (int i = 0; i < 4; i++)
#pragma unroll
        for (int j = 0; j < 4; j++)
#pragma unroll
            for (int q = 0; q < 4; q++) acc[i][j][q] = 0.f;

    int nC = K >> 5;
    cp16(dA0, A + aoff0); cp16(dA1, A + aoff1);
    cp16(dB0, B + boff0); cp16(dB1, B + boff1);
    cp_commit();

    for (int c = 0; c < nC; c++) {
        if (c + 1 < nC) {
            unsigned so = (unsigned)((c + 1) & 1) * STGB;
            size_t ko = (size_t)(c + 1) << 5;
            cp16(dA0 + so, A + aoff0 + ko); cp16(dA1 + so, A + aoff1 + ko);
            cp16(dB0 + so, B + boff0 + ko); cp16(dB1 + so, B + boff1 + ko);
            cp_commit();
            cp_wait<1>();
        } else {
            cp_wait<0>();
        }
        __syncthreads();

        unsigned so = (unsigned)(c & 1) * STGB;
#pragma unroll
        for (int s = 0; s < 2; s++) {
            unsigned ah[4][4], bh[2][4];
#pragma unroll
            for (int i = 0; i < 4; i++) ldmx4(adA[i] + so + s * 32, ah[i]);
#pragma unroll
            for (int p = 0; p < 2; p++) ldmx4(adB[p] + so + s * 32, bh[p]);
#pragma unroll
            for (int i = 0; i < 4; i++)
#pragma unroll
                for (int j = 0; j < 4; j++) {
                    int p = j >> 1, q = j & 1;
                    mma16816h(acc[i][j], ah[i], bh[p][q], bh[p][2 + q]);
                }
        }
        __syncthreads();
    }

    int g = lane >> 2, t2 = (lane & 3) * 2;
#pragma unroll
    for (int i = 0; i < 4; i++) {
        int rA = row0 + wm * 64 + i * 16 + g;
#pragma unroll
        for (int j = 0; j < 4; j++) {
            int cA = col0 + wn * 32 + j * 8 + t2;
            float v0 = acc[i][j][0], v1 = acc[i][j][1];
            float w0 = acc[i][j][2], w1 = acc[i][j][3];
            if (MODE != 3) {
                float b0 = bias[cA], b1 = bias[cA + 1];
                v0 += b0; v1 += b1; w0 += b0; w1 += b1;
            }
            if (MODE == 1) {
                v0 = 0.5f * v0 * (1.0f + erff(v0 * 0.70710678118654752440f));
                v1 = 0.5f * v1 * (1.0f + erff(v1 * 0.70710678118654752440f));
                w0 = 0.5f * w0 * (1.0f + erff(w0 * 0.70710678118654752440f));
                w1 = 0.5f * w1 * (1.0f + erff(w1 * 0.70710678118654752440f));
            }
            if (MODE == 1 || MODE == 4) {
                *(__half2*)&O[(size_t)rA * N + cA] = __floats2half2_rn(v0, v1);
                *(__half2*)&O[(size_t)(rA + 8) * N + cA] = __floats2half2_rn(w0, w1);
            } else {
                if (MODE == 2) {
                    float2 q0 = *(const float2*)&res[(size_t)rA * N + cA];
                    float2 q1 = *(const float2*)&res[(size_t)(rA + 8) * N + cA];
                    v0 += q0.x; v1 += q0.y; w0 += q1.x; w1 += q1.y;
                }
                *(float2*)&C[(size_t)rA * N + cA] = make_float2(v0, v1);
                *(float2*)&C[(size_t)(rA + 8) * N + cA] = make_float2(w0, w1);
            }
        }
    }
}

// ---------------------------------------------------------------------------
// Flash attention: q-tile 128, s-tile 64, fp16 mma, online softmax.
// Grid (TSEQ/128, NH, B), 256 threads (8 warps x 16 q-rows).
#define FKP   72                       // smem pitch in halves (144B)
#define FQB   (128 * FKP * 2)          // Q bytes = 18432
#define FKVST (64 * FKP * 2)           // one array (K or V) = 9216 B
#define FSTG  (2 * FKVST)              // K+V per stage = 18432 B
#define FSMEM (FQB + 2 * FSTG)         // 55296 B

__global__ __launch_bounds__(256)
void flash_k(const __half* __restrict__ qkv, __half* __restrict__ y) {
    extern __shared__ __align__(16) __half fsm[];
    int tid = threadIdx.x, lane = tid & 31, wid = tid >> 5;
    int qt = blockIdx.x, h = blockIdx.y, b = blockIdx.z;
    int q0 = qt * 128;
    const __half* base = qkv + (size_t)b * TSEQ * (3 * CH);
    unsigned Qb = (unsigned)__cvta_generic_to_shared(fsm);
    unsigned KVb = Qb + FQB;

    // Q: 1024 16B segs
#pragma unroll
    for (int i = 0; i < 4; i++) {
        int idx = tid + i * 256;
        int row = idx >> 3, seg = idx & 7;
        cp16(Qb + row * 144 + seg * 16,
             base + (size_t)(q0 + row) * (3 * CH) + h * DH + seg * 8);
    }
    // K,V tile 0 into stage 0
#pragma unroll
    for (int i = 0; i < 2; i++) {
        int idx = tid + i * 256;
        int row = idx >> 3, seg = idx & 7;
        cp16(KVb + row * 144 + seg * 16,
             base + (size_t)row * (3 * CH) + CH + h * DH + seg * 8);
        cp16(KVb + FKVST + row * 144 + seg * 16,
             base + (size_t)row * (3 * CH) + 2 * CH + h * DH + seg * 8);
    }
    cp_commit();

    int lr  = (lane & 7) + ((lane >> 3) & 1) * 8;
    int lcb = (lane >> 4) * 16;
    unsigned qad[4];
#pragma unroll
    for (int kk = 0; kk < 4; kk++)
        qad[kk] = Qb + (unsigned)((wid * 16 + lr) * 144) + kk * 32 + lcb;

    unsigned Qf[4][4];
    float Oa[8][4];
#pragma unroll
    for (int j = 0; j < 8; j++)
#pragma unroll
        for (int q = 0; q < 4; q++) Oa[j][q] = 0.f;
    float m0 = -1e30f, m1 = -1e30f, l0 = 0.f, l1 = 0.f;

    int nT = 2 * (qt + 1);
    for (int t = 0; t < nT; t++) {
        if (t + 1 < nT) {
            unsigned kb = KVb + (unsigned)((t + 1) & 1) * FSTG;
            int s0n = (t + 1) * 64;
#pragma unroll
            for (int i = 0; i < 2; i++) {
                int idx = tid + i * 256;
                int row = idx >> 3, seg = idx & 7;
                cp16(kb + row * 144 + seg * 16,
                     base + (size_t)(s0n + row) * (3 * CH) + CH + h * DH + seg * 8);
                cp16(kb + FKVST + row * 144 + seg * 16,
                     base + (size_t)(s0n + row) * (3 * CH) + 2 * CH + h * DH + seg * 8);
            }
            cp_commit();
            cp_wait<1>();
        } else {
            cp_wait<0>();
        }
        __syncthreads();
        if (t == 0) {
#pragma unroll
            for (int kk = 0; kk < 4; kk++) ldmx4(qad[kk], Qf[kk]);
        }
        unsigned kb = KVb + (unsigned)(t & 1) * FSTG;

        // S = Q @ K^T
        float S[8][4];
#pragma unroll
        for (int j = 0; j < 8; j++)
#pragma unroll
            for (int q = 0; q < 4; q++) S[j][q] = 0.f;
#pragma unroll
        for (int kk = 0; kk < 4; kk++) {
            unsigned kf[4][4];
#pragma unroll
            for (int p = 0; p < 4; p++)
                ldmx4(kb + (unsigned)((p * 16 + lr) * 144) + kk * 32 + lcb, kf[p]);
#pragma unroll
            for (int p = 0; p < 4; p++)
#pragma unroll
                for (int qn = 0; qn < 2; qn++)
                    mma16816h(S[p * 2 + qn], Qf[kk], kf[p][qn], kf[p][2 + qn]);
        }

        int s0 = t * 64;
        int rg = q0 + wid * 16 + (lane >> 2);
        if (s0 + 63 > q0 + wid * 16) {
#pragma unroll
            for (int j = 0; j < 8; j++) {
                int sc = s0 + j * 8 + (lane & 3) * 2;
                if (sc > rg)     S[j][0] = -1e30f;
                if (sc + 1 > rg) S[j][1] = -1e30f;
                if (sc > rg + 8)     S[j][2] = -1e30f;
                if (sc + 1 > rg + 8) S[j][3] = -1e30f;
            }
        }
        // online softmax (scale 0.125)
        float mx0 = -1e30f, mx1 = -1e30f;
#pragma unroll
        for (int j = 0; j < 8; j++) {
            mx0 = fmaxf(mx0, fmaxf(S[j][0], S[j][1]));
            mx1 = fmaxf(mx1, fmaxf(S[j][2], S[j][3]));
        }
        mx0 = fmaxf(mx0, __shfl_xor_sync(0xffffffffu, mx0, 1));
        mx0 = fmaxf(mx0, __shfl_xor_sync(0xffffffffu, mx0, 2));
        mx1 = fmaxf(mx1, __shfl_xor_sync(0xffffffffu, mx1, 1));
        mx1 = fmaxf(mx1, __shfl_xor_sync(0xffffffffu, mx1, 2));
        mx0 *= 0.125f; mx1 *= 0.125f;
        float mn0 = fmaxf(m0, mx0), mn1 = fmaxf(m1, mx1);
        float a0 = __expf(m0 - mn0), a1 = __expf(m1 - mn1);
        m0 = mn0; m1 = mn1;
        float rs0 = 0.f, rs1 = 0.f;
        __half2 P[8][2];
#pragma unroll
        for (int j = 0; j < 8; j++) {
            float p0 = __expf(S[j][0] * 0.125f - m0);
            float p1 = __expf(S[j][1] * 0.125f - m0);
            float p2 = __expf(S[j][2] * 0.125f - m1);
            float p3 = __expf(S[j][3] * 0.125f - m1);
            rs0 += p0 + p1; rs1 += p2 + p3;
            P[j][0] = __floats2half2_rn(p0, p1);
            P[j][1] = __floats2half2_rn(p2, p3);
        }
        l0 = l0 * a0 + rs0; l1 = l1 * a1 + rs1;
#pragma unroll
        for (int j = 0; j < 8; j++) {
            Oa[j][0] *= a0; Oa[j][1] *= a0; Oa[j][2] *= a1; Oa[j][3] *= a1;
        }
        // O += P @ V
        unsigned vb = kb + FKVST;
#pragma unroll
        for (int kt = 0; kt < 4; kt++) {
            unsigned vf[4][4];
#pragma unroll
            for (int dg = 0; dg < 4; dg++)
                ldmx4t(vb + (unsigned)((kt * 16 + lr) * 144) + dg * 32 + lcb, vf[dg]);
            unsigned pa[4];
            pa[0] = *(unsigned*)&P[2 * kt][0];
            pa[1] = *(unsigned*)&P[2 * kt][1];
            pa[2] = *(unsigned*)&P[2 * kt + 1][0];
            pa[3] = *(unsigned*)&P[2 * kt + 1][1];
#pragma unroll
            for (int dg = 0; dg < 4; dg++) {
                mma16816h(Oa[dg * 2 + 0], pa, vf[dg][0], vf[dg][1]);
                mma16816h(Oa[dg * 2 + 1], pa, vf[dg][2], vf[dg][3]);
            }
        }
        __syncthreads();  // all reads of this stage done before it is refilled
    }

    l0 += __shfl_xor_sync(0xffffffffu, l0, 1);
    l0 += __shfl_xor_sync(0xffffffffu, l0, 2);
    l1 += __shfl_xor_sync(0xffffffffu, l1, 1);
    l1 += __shfl_xor_sync(0xffffffffu, l1, 2);
    float inv0 = 1.0f / l0, inv1 = 1.0f / l1;
    int g = lane >> 2, t2 = (lane & 3) * 2;
    int rowg = q0 + wid * 16 + g;
#pragma unroll
    for (int j = 0; j < 8; j++) {
        int d = h * DH + j * 8 + t2;
        *(__half2*)&y[(size_t)(b * TSEQ + rowg) * CH + d] =
            __floats2half2_rn(Oa[j][0] * inv0, Oa[j][1] * inv0);
        *(__half2*)&y[(size_t)(b * TSEQ + rowg + 8) * CH + d] =
            __floats2half2_rn(Oa[j][2] * inv1, Oa[j][3] * inv1);
    }
}

// ---------------------------------------------------------------------------
__global__ void zero_loss_k(float* num, float* den) { *num = 0.f; *den = 0.f; }

__global__ void loss_k(const float* __restrict__ logits, const int* __restrict__ tg,
                       float* num, float* den) {
    __shared__ float rm[256], rs[256];
    int row = blockIdx.x;
    const float* lr = logits + (size_t)row * VOC;
    float m = -3.0e38f, s = 0.f;
    for (int j = threadIdx.x; j < VOC; j += 256) {
        float v = lr[j];
        if (v > m) { s = s * __expf(m - v) + 1.0f; m = v; }
        else s += __expf(v - m);
    }
    rm[threadIdx.x] = m; rs[threadIdx.x] = s;
    __syncthreads();
    for (int off = 128; off > 0; off >>= 1) {
        if (threadIdx.x < off) {
            float m2 = rm[threadIdx.x + off], s2 = rs[threadIdx.x + off];
            float m1 = rm[threadIdx.x], s1 = rs[threadIdx.x];
            float mn = fmaxf(m1, m2);
            rs[threadIdx.x] = s1 * __expf(m1 - mn) + s2 * __expf(m2 - mn);
            rm[threadIdx.x] = mn;
        }
        __syncthreads();
    }
    if (threadIdx.x == 0) {
        int t = tg[row];
        if (t != 0) {
            float lse = rm[0] + logf(rs[0]);
            atomicAdd(num, lse - lr[t]);
            atomicAdd(den, 1.0f);
        }
    }
}

__global__ void final_loss_k(const float* num, const float* den, float* out) {
    out[0] = *num / fmaxf(*den, 1.0f);
}

// ---------------------------------------------------------------------------
extern "C" void kernel_launch(void* const* d_in, const int* in_sizes, int n_in,
                              void* d_out, int out_size) {
    const int*   idx     = (const int*)d_in[0];
    const int*   targets = (const int*)d_in[1];
    const float* wte     = (const float*)d_in[2];
    const float* wpe     = (const float*)d_in[3];
    const float* ln1_g   = (const float*)d_in[4];
    const float* ln1_b   = (const float*)d_in[5];
    const float* attn_w  = (const float*)d_in[6];
    const float* attn_b  = (const float*)d_in[7];
    const float* proj_w  = (const float*)d_in[8];
    const float* proj_b  = (const float*)d_in[9];
    const float* ln2_g   = (const float*)d_in[10];
    const float* ln2_b   = (const float*)d_in[11];
    const float* fc_w    = (const float*)d_in[12];
    const float* fc_b    = (const float*)d_in[13];
    const float* fc2_w   = (const float*)d_in[14];
    const float* fc2_b   = (const float*)d_in[15];
    const float* lnf_g   = (const float*)d_in[16];
    const float* lnf_b   = (const float*)d_in[17];
    float* out = (float*)d_out;

    float *x, *h, *pnum, *pden;
    __half *qkv_h, *h_h, *y_h, *m_h, *wt_h, *wte_h;
    cudaGetSymbolAddress((void**)&x, g_x);
    cudaGetSymbolAddress((void**)&h, g_hf);
    cudaGetSymbolAddress((void**)&qkv_h, g_qkv_h);
    cudaGetSymbolAddress((void**)&h_h, g_h_h);
    cudaGetSymbolAddress((void**)&y_h, g_y_h);
    cudaGetSymbolAddress((void**)&m_h, g_m_h);
    cudaGetSymbolAddress((void**)&wt_h, g_wt_h);
    cudaGetSymbolAddress((void**)&wte_h, g_wte_h);
    cudaGetSymbolAddress((void**)&pnum, g_num);
    cudaGetSymbolAddress((void**)&pden, g_den);

    const size_t LOGN = (size_t)BT * VOC;
    float* out_loss = out + LOGN;
    float* out_x    = out + LOGN + 1;  // 4B-aligned only: scalar access

    cudaFuncSetAttribute(hgemm_k<0>, cudaFuncAttributeMaxDynamicSharedMemorySize, HSMEM);
    cudaFuncSetAttribute(hgemm_k<1>, cudaFuncAttributeMaxDynamicSharedMemorySize, HSMEM);
    cudaFuncSetAttribute(hgemm_k<2>, cudaFuncAttributeMaxDynamicSharedMemorySize, HSMEM);
    cudaFuncSetAttribute(hgemm_k<3>, cudaFuncAttributeMaxDynamicSharedMemorySize, HSMEM);
    cudaFuncSetAttribute(hgemm_k<4>, cudaFuncAttributeMaxDynamicSharedMemorySize, HSMEM);
    cudaFuncSetAttribute(flash_k, cudaFuncAttributeMaxDynamicSharedMemorySize, FSMEM);

    dim3 tblk(32, 8);

    // ---- weight preprocessing ----
    conv_k<<<(VOC * CH + 255) / 256, 256>>>(wte, wte_h, VOC * CH);
    for (int l = 0; l < NLAY; l++) {
        tconv_k<<<dim3(2304 / 32, 768 / 32), tblk>>>(
            attn_w + (size_t)l * W_ATTN_SZ, wt_h + W_ATTN_OFF + (size_t)l * W_ATTN_SZ, 768, 2304);
        tconv_k<<<dim3(768 / 32, 768 / 32), tblk>>>(
            proj_w + (size_t)l * W_PROJ_SZ, wt_h + W_PROJ_OFF + (size_t)l * W_PROJ_SZ, 768, 768);
        tconv_k<<<dim3(3072 / 32, 768 / 32), tblk>>>(
            fc_w + (size_t)l * W_FC_SZ, wt_h + W_FC_OFF + (size_t)l * W_FC_SZ, 768, 3072);
        tconv_k<<<dim3(768 / 32, 3072 / 32), tblk>>>(
            fc2_w + (size_t)l * W_FC2_SZ, wt_h + W_FC2_OFF + (size_t)l * W_FC2_SZ, 3072, 768);
    }

    embed_k<<<BT, 256>>>(idx, wte, wpe, x);

    for (int l = 0; l < NLAY; l++) {
        const __half* wa = wt_h + W_ATTN_OFF + (size_t)l * W_ATTN_SZ;
        const __half* wp = wt_h + W_PROJ_OFF + (size_t)l * W_PROJ_SZ;
        const __half* wf = wt_h + W_FC_OFF + (size_t)l * W_FC_SZ;
        const __half* w2 = wt_h + W_FC2_OFF + (size_t)l * W_FC2_SZ;

        ln_k<<<BT, 256>>>(x, ln1_g + l * CH, ln1_b + l * CH, h, h_h);
        hgemm_k<4><<<dim3(2304 / 128, BT / 128), 256, HSMEM>>>(
            h_h, wa, attn_b + (size_t)l * 3 * CH, nullptr, nullptr, qkv_h, BT, 3 * CH, CH);
        flash_k<<<dim3(TSEQ / 128, NH, 4), 256, FSMEM>>>(qkv_h, y_h);
        hgemm_k<2><<<dim3(CH / 128, BT / 128), 256, HSMEM>>>(
            y_h, wp, proj_b + (size_t)l * CH, x, x, nullptr, BT, CH, CH);
        ln_k<<<BT, 256>>>(x, ln2_g + l * CH, ln2_b + l * CH, h, h_h);
        hgemm_k<1><<<dim3(4 * CH / 128, BT / 128), 256, HSMEM>>>(
            h_h, wf, fc_b + (size_t)l * 4 * CH, nullptr, nullptr, m_h, BT, 4 * CH, CH);
        hgemm_k<2><<<dim3(CH / 128, BT / 128), 256, HSMEM>>>(
            m_h, w2, fc2_b + (size_t)l * CH, x, x, nullptr, BT, CH, 4 * CH);
    }

    ln_k<<<BT, 256>>>(x, lnf_g, lnf_b, h, h_h);
    copy_k<<<(BT * CH + 255) / 256, 256>>>(h, out_x, BT * CH);
    hgemm_k<3><<<dim3(VOC / 128, BT / 128), 256, HSMEM>>>(
        h_h, wte_h, nullptr, nullptr, out, nullptr, BT, VOC, CH);
    zero_loss_k<<<1, 1>>>(pnum, pden);
    loss_k<<<BT, 256>>>(out, targets, pnum, pden);
    final_loss_k<<<1, 1>>>(pnum, pden, out_loss);
}

// round 14
// speedup vs baseline: 26.5210x; 1.0246x over previous
#include <cuda_runtime.h>
#include <cuda_bf16.h>
#include <cuda_fp16.h>
#include <math.h>
#include <stdint.h>

// ---------------------------------------------------------------------------
// GPT-2 small forward: L=6, C=768, H=12, D=64, B=4, T=1024, V=32000
// Output layout: logits [4096*32000] | loss [1] | x_final [4096*768]
// Round 14: fp16 mma GEMMs + flash attention. Overhead pass: flash CTA
// reorder (heavy tiles first), batched weight transpose, LN fp32-write elision.
// ---------------------------------------------------------------------------

#define BT   4096
#define CH   768
#define NH   12
#define DH   64
#define TSEQ 1024
#define VOC  32000
#define NLAY 6

#define W_ATTN_OFF 0
#define W_ATTN_SZ  (2304 * 768)
#define W_PROJ_OFF (W_ATTN_OFF + 6 * W_ATTN_SZ)
#define W_PROJ_SZ  (768 * 768)
#define W_FC_OFF   (W_PROJ_OFF + 6 * W_PROJ_SZ)
#define W_FC_SZ    (3072 * 768)
#define W_FC2_OFF  (W_FC_OFF + 6 * W_FC_SZ)
#define W_FC2_SZ   (768 * 3072)
#define W_TOTAL    (W_FC2_OFF + 6 * W_FC2_SZ)

// Scratch (device globals: no allocation allowed)
__device__ float g_x[BT * CH];
__device__ float g_hf[BT * CH];
__device__ __half g_qkv_h[BT * 3 * CH];
__device__ __half g_h_h[BT * CH];
__device__ __half g_y_h[BT * CH];
__device__ __half g_m_h[BT * 4 * CH];
__device__ __half g_wt_h[W_TOTAL];
__device__ __half g_wte_h[VOC * CH];
__device__ float g_num;
__device__ float g_den;

// ---------------------------------------------------------------------------
__global__ void conv_k(const float4* __restrict__ src, __half* __restrict__ dst, int n4) {
    int i = blockIdx.x * 256 + threadIdx.x;
    if (i < n4) {
        float4 v = src[i];
        __half2 a = __floats2half2_rn(v.x, v.y);
        __half2 b = __floats2half2_rn(v.z, v.w);
        *(__half2*)&dst[i * 4] = a;
        *(__half2*)&dst[i * 4 + 2] = b;
    }
}

// batched transpose + convert: W[l][K,N] fp32 -> T[l][N,K] fp16, blockIdx.z = layer
__global__ void tconv_k(const float* __restrict__ W, __half* __restrict__ T,
                        int K, int N, size_t wstride, size_t tstride) {
    __shared__ float s[32][33];
    int n0 = blockIdx.x * 32, k0 = blockIdx.y * 32;
    const float* Wl = W + (size_t)blockIdx.z * wstride;
    __half* Tl = T + (size_t)blockIdx.z * tstride;
    int tx = threadIdx.x, ty = threadIdx.y;
#pragma unroll
    for (int i = 0; i < 4; i++)
        s[ty + i * 8][tx] = Wl[(size_t)(k0 + ty + i * 8) * N + n0 + tx];
    __syncthreads();
#pragma unroll
    for (int i = 0; i < 4; i++)
        Tl[(size_t)(n0 + ty + i * 8) * K + k0 + tx] = __float2half(s[tx][ty + i * 8]);
}

// ---------------------------------------------------------------------------
__global__ void embed_k(const int* __restrict__ idx, const float* __restrict__ wte,
                        const float* __restrict__ wpe, float* __restrict__ x) {
    int row = blockIdx.x;
    int t = row & (TSEQ - 1);
    int tok = idx[row];
    const float* a = wte + (size_t)tok * CH;
    const float* b = wpe + (size_t)t * CH;
    float* o = x + (size_t)row * CH;
    for (int c = threadIdx.x; c < CH; c += blockDim.x) o[c] = a[c] + b[c];
}

__global__ void copy_k(const float* __restrict__ src, float* __restrict__ dst, int n) {
    int i = blockIdx.x * blockDim.x + threadIdx.x;
    if (i < n) dst[i] = src[i];
}

// LayerNorm; WF32: also write fp32 output (only needed for the final LN)
template <int WF32>
__global__ void ln_k(const float* __restrict__ x, const float* __restrict__ g,
                     const float* __restrict__ b, float* __restrict__ o,
                     __half* __restrict__ oh) {
    __shared__ float r1[256], r2[256];
    int row = blockIdx.x;
    const float* xr = x + (size_t)row * CH;
    float s = 0.f, s2 = 0.f;
    for (int i = threadIdx.x; i < CH; i += 256) { float v = xr[i]; s += v; s2 += v * v; }
    r1[threadIdx.x] = s; r2[threadIdx.x] = s2;
    __syncthreads();
    for (int off = 128; off > 0; off >>= 1) {
        if (threadIdx.x < off) {
            r1[threadIdx.x] += r1[threadIdx.x + off];
            r2[threadIdx.x] += r2[threadIdx.x + off];
        }
        __syncthreads();
    }
    float mean = r1[0] * (1.0f / CH);
    float var  = r2[0] * (1.0f / CH) - mean * mean;
    float rstd = rsqrtf(var + 1e-5f);
    for (int i = threadIdx.x; i < CH; i += 256) {
        float v = (xr[i] - mean) * rstd * g[i] + b[i];
        size_t oo = (size_t)row * CH + i;
        if (WF32) o[oo] = v;
        oh[oo] = __float2half(v);
    }
}

// ---------------------------------------------------------------------------
// primitives
__device__ __forceinline__ void ldmx4(unsigned addr, unsigned r[4]) {
    asm volatile("ldmatrix.sync.aligned.m8n8.x4.shared.b16 {%0,%1,%2,%3}, [%4];"
                 : "=r"(r[0]), "=r"(r[1]), "=r"(r[2]), "=r"(r[3]) : "r"(addr));
}
__device__ __forceinline__ void ldmx4t(unsigned addr, unsigned r[4]) {
    asm volatile("ldmatrix.sync.aligned.m8n8.x4.trans.shared.b16 {%0,%1,%2,%3}, [%4];"
                 : "=r"(r[0]), "=r"(r[1]), "=r"(r[2]), "=r"(r[3]) : "r"(addr));
}
__device__ __forceinline__ void mma16816h(float d[4], const unsigned a[4],
                                          unsigned b0, unsigned b1) {
    asm volatile("mma.sync.aligned.m16n8k16.row.col.f32.f16.f16.f32 "
                 "{%0,%1,%2,%3},{%4,%5,%6,%7},{%8,%9},{%0,%1,%2,%3};"
                 : "+f"(d[0]), "+f"(d[1]), "+f"(d[2]), "+f"(d[3])
                 : "r"(a[0]), "r"(a[1]), "r"(a[2]), "r"(a[3]), "r"(b0), "r"(b1));
}
__device__ __forceinline__ void cp16(unsigned sa, const void* gm) {
    asm volatile("cp.async.cg.shared.global [%0], [%1], 16;" :: "r"(sa), "l"(gm));
}
__device__ __forceinline__ void cp_commit() { asm volatile("cp.async.commit_group;"); }
template <int N>
__device__ __forceinline__ void cp_wait() {
    asm volatile("cp.async.wait_group %0;" :: "n"(N));
}

#define SPITCH 40
#define ARR    (128 * SPITCH)
#define STGB   (2 * ARR * 2)
#define HSMEM  (2 * STGB)

// ---------------------------------------------------------------------------
// fp16 NT GEMM: D[M,N] = A[M,K] @ (B[N,K])^T, fp32 accum.
// MODE 0: +bias->fp32.  MODE 1: +bias,GELU->fp16.  MODE 2: +bias+res->fp32.
// MODE 3: plain->fp32.  MODE 4: +bias->fp16.
template <int MODE>
__global__ __launch_bounds__(256, 2)
void hgemm_k(const __half* __restrict__ A, const __half* __restrict__ B,
             const float* __restrict__ bias, const float* __restrict__ res,
             float* __restrict__ C, __half* __restrict__ O,
             int M, int N, int K) {
    extern __shared__ __align__(16) __half smbuf[];
    int tid = threadIdx.x, lane = tid & 31, wid = tid >> 5;
    int wm = wid >> 2, wn = wid & 3;
    int row0 = blockIdx.y * 128, col0 = blockIdx.x * 128;

    int r0 = tid >> 2, sg = (tid & 3) * 8;
    size_t aoff0 = (size_t)(row0 + r0) * K + sg;
    size_t aoff1 = aoff0 + (size_t)64 * K;
    size_t boff0 = (size_t)(col0 + r0) * K + sg;
    size_t boff1 = boff0 + (size_t)64 * K;
    int sm0 = r0 * SPITCH + sg, sm1 = sm0 + 64 * SPITCH;

    unsigned smbase = (unsigned)__cvta_generic_to_shared(smbuf);
    unsigned dA0 = smbase + sm0 * 2,         dA1 = smbase + sm1 * 2;
    unsigned dB0 = smbase + (ARR + sm0) * 2, dB1 = smbase + (ARR + sm1) * 2;

    int lr  = (lane & 7) + ((lane >> 3) & 1) * 8;
    int lcb = (lane >> 4) * 16;
    unsigned adA[4], adB[2];
#pragma unroll
    for (int i = 0; i < 4; i++) {
        int rr = wm * 64 + i * 16 + lr;
        adA[i] = smbase + (unsigned)(rr * SPITCH) * 2 + lcb;
    }
#pragma unroll
    for (int p = 0; p < 2; p++) {
        int rr = wn * 32 + p * 16 + lr;
        adB[p] = smbase + (unsigned)(ARR + rr * SPITCH) * 2 + lcb;
    }

    float acc[4][4][4];
#pragma unroll
    for (int i = 0; i < 4; i++)
#pragma unroll
        for (int j = 0; j < 4; j++)
#pragma unroll
            for (int q = 0; q < 4; q++) acc[i][j][q] = 0.f;

    int nC = K >> 5;
    cp16(dA0, A + aoff0); cp16(dA1, A + aoff1);
    cp16(dB0, B + boff0); cp16(dB1, B + boff1);
    cp_commit();

    for (int c = 0; c < nC; c++) {
        if (c + 1 < nC) {
            unsigned so = (unsigned)((c + 1) & 1) * STGB;
            size_t ko = (size_t)(c + 1) << 5;
            cp16(dA0 + so, A + aoff0 + ko); cp16(dA1 + so, A + aoff1 + ko);
            cp16(dB0 + so, B + boff0 + ko); cp16(dB1 + so, B + boff1 + ko);
            cp_commit();
            cp_wait<1>();
        } else {
            cp_wait<0>();
        }
        __syncthreads();

        unsigned so = (unsigned)(c & 1) * STGB;
#pragma unroll
        for (int s = 0; s < 2; s++) {
            unsigned ah[4][4], bh[2][4];
#pragma unroll
            for (int i = 0; i < 4; i++) ldmx4(adA[i] + so + s * 32, ah[i]);
#pragma unroll
            for (int p = 0; p < 2; p++) ldmx4(adB[p] + so + s * 32, bh[p]);
#pragma unroll
            for (int i = 0; i < 4; i++)
#pragma unroll
                for (int j = 0; j < 4; j++) {
                    int p = j >> 1, q = j & 1;
                    mma16816h(acc[i][j], ah[i], bh[p][q], bh[p][2 + q]);
                }
        }
        __syncthreads();
    }

    int g = lane >> 2, t2 = (lane & 3) * 2;
#pragma unroll
    for (int i = 0; i < 4; i++) {
        int rA = row0 + wm * 64 + i * 16 + g;
#pragma unroll
        for (int j = 0; j < 4; j++) {
            int cA = col0 + wn * 32 + j * 8 + t2;
            float v0 = acc[i][j][0], v1 = acc[i][j][1];
            float w0 = acc[i][j][2], w1 = acc[i][j][3];
            if (MODE != 3) {
                float b0 = bias[cA], b1 = bias[cA + 1];
                v0 += b0; v1 += b1; w0 += b0; w1 += b1;
            }
            if (MODE == 1) {
                v0 = 0.5f * v0 * (1.0f + erff(v0 * 0.70710678118654752440f));
                v1 = 0.5f * v1 * (1.0f + erff(v1 * 0.70710678118654752440f));
                w0 = 0.5f * w0 * (1.0f + erff(w0 * 0.70710678118654752440f));
                w1 = 0.5f * w1 * (1.0f + erff(w1 * 0.70710678118654752440f));
            }
            if (MODE == 1 || MODE == 4) {
                *(__half2*)&O[(size_t)rA * N + cA] = __floats2half2_rn(v0, v1);
                *(__half2*)&O[(size_t)(rA + 8) * N + cA] = __floats2half2_rn(w0, w1);
            } else {
                if (MODE == 2) {
                    float2 q0 = *(const float2*)&res[(size_t)rA * N + cA];
                    float2 q1 = *(const float2*)&res[(size_t)(rA + 8) * N + cA];
                    v0 += q0.x; v1 += q0.y; w0 += q1.x; w1 += q1.y;
                }
                *(float2*)&C[(size_t)rA * N + cA] = make_float2(v0, v1);
                *(float2*)&C[(size_t)(rA + 8) * N + cA] = make_float2(w0, w1);
            }
        }
    }
}

// ---------------------------------------------------------------------------
// Flash attention: q-tile 128, s-tile 64, fp16 mma, online softmax.
// Heaviest q-tiles scheduled first (qt = gridDim.x-1-blockIdx.x).
#define FKP   72
#define FQB   (128 * FKP * 2)
#define FKVST (64 * FKP * 2)
#define FSTG  (2 * FKVST)
#define FSMEM (FQB + 2 * FSTG)

__global__ __launch_bounds__(256)
void flash_k(const __half* __restrict__ qkv, __half* __restrict__ y) {
    extern __shared__ __align__(16) __half fsm[];
    int tid = threadIdx.x, lane = tid & 31, wid = tid >> 5;
    int qt = gridDim.x - 1 - blockIdx.x;   // heavy tiles first
    int h = blockIdx.y, b = blockIdx.z;
    int q0 = qt * 128;
    const __half* base = qkv + (size_t)b * TSEQ * (3 * CH);
    unsigned Qb = (unsigned)__cvta_generic_to_shared(fsm);
    unsigned KVb = Qb + FQB;

#pragma unroll
    for (int i = 0; i < 4; i++) {
        int idx = tid + i * 256;
        int row = idx >> 3, seg = idx & 7;
        cp16(Qb + row * 144 + seg * 16,
             base + (size_t)(q0 + row) * (3 * CH) + h * DH + seg * 8);
    }
#pragma unroll
    for (int i = 0; i < 2; i++) {
        int idx = tid + i * 256;
        int row = idx >> 3, seg = idx & 7;
        cp16(KVb + row * 144 + seg * 16,
             base + (size_t)row * (3 * CH) + CH + h * DH + seg * 8);
        cp16(KVb + FKVST + row * 144 + seg * 16,
             base + (size_t)row * (3 * CH) + 2 * CH + h * DH + seg * 8);
    }
    cp_commit();

    int lr  = (lane & 7) + ((lane >> 3) & 1) * 8;
    int lcb = (lane >> 4) * 16;
    unsigned qad[4];
#pragma unroll
    for (int kk = 0; kk < 4; kk++)
        qad[kk] = Qb + (unsigned)((wid * 16 + lr) * 144) + kk * 32 + lcb;

    unsigned Qf[4][4];
    float Oa[8][4];
#pragma unroll
    for (int j = 0; j < 8; j++)
#pragma unroll
        for (int q = 0; q < 4; q++) Oa[j][q] = 0.f;
    float m0 = -1e30f, m1 = -1e30f, l0 = 0.f, l1 = 0.f;

    int nT = 2 * (qt + 1);
    for (int t = 0; t < nT; t++) {
        if (t + 1 < nT) {
            unsigned kb = KVb + (unsigned)((t + 1) & 1) * FSTG;
            int s0n = (t + 1) * 64;
#pragma unroll
            for (int i = 0; i < 2; i++) {
                int idx = tid + i * 256;
                int row = idx >> 3, seg = idx & 7;
                cp16(kb + row * 144 + seg * 16,
                     base + (size_t)(s0n + row) * (3 * CH) + CH + h * DH + seg * 8);
                cp16(kb + FKVST + row * 144 + seg * 16,
                     base + (size_t)(s0n + row) * (3 * CH) + 2 * CH + h * DH + seg * 8);
            }
            cp_commit();
            cp_wait<1>();
        } else {
            cp_wait<0>();
        }
        __syncthreads();
        if (t == 0) {
#pragma unroll
            for (int kk = 0; kk < 4; kk++) ldmx4(qad[kk], Qf[kk]);
        }
        unsigned kb = KVb + (unsigned)(t & 1) * FSTG;

        float S[8][4];
#pragma unroll
        for (int j = 0; j < 8; j++)
#pragma unroll
            for (int q = 0; q < 4; q++) S[j][q] = 0.f;
#pragma unroll
        for (int kk = 0; kk < 4; kk++) {
            unsigned kf[4][4];
#pragma unroll
            for (int p = 0; p < 4; p++)
                ldmx4(kb + (unsigned)((p * 16 + lr) * 144) + kk * 32 + lcb, kf[p]);
#pragma unroll
            for (int p = 0; p < 4; p++)
#pragma unroll
                for (int qn = 0; qn < 2; qn++)
                    mma16816h(S[p * 2 + qn], Qf[kk], kf[p][qn], kf[p][2 + qn]);
        }

        int s0 = t * 64;
        int rg = q0 + wid * 16 + (lane >> 2);
        if (s0 + 63 > q0 + wid * 16) {
#pragma unroll
            for (int j = 0; j < 8; j++) {
                int sc = s0 + j * 8 + (lane & 3) * 2;
                if (sc > rg)     S[j][0] = -1e30f;
                if (sc + 1 > rg) S[j][1] = -1e30f;
                if (sc > rg + 8)     S[j][2] = -1e30f;
                if (sc + 1 > rg + 8) S[j][3] = -1e30f;
            }
        }
        float mx0 = -1e30f, mx1 = -1e30f;
#pragma unroll
        for (int j = 0; j < 8; j++) {
            mx0 = fmaxf(mx0, fmaxf(S[j][0], S[j][1]));
            mx1 = fmaxf(mx1, fmaxf(S[j][2], S[j][3]));
        }
        mx0 = fmaxf(mx0, __shfl_xor_sync(0xffffffffu, mx0, 1));
        mx0 = fmaxf(mx0, __shfl_xor_sync(0xffffffffu, mx0, 2));
        mx1 = fmaxf(mx1, __shfl_xor_sync(0xffffffffu, mx1, 1));
        mx1 = fmaxf(mx1, __shfl_xor_sync(0xffffffffu, mx1, 2));
        mx0 *= 0.125f; mx1 *= 0.125f;
        float mn0 = fmaxf(m0, mx0), mn1 = fmaxf(m1, mx1);
        float a0 = __expf(m0 - mn0), a1 = __expf(m1 - mn1);
        m0 = mn0; m1 = mn1;
        float rs0 = 0.f, rs1 = 0.f;
        __half2 P[8][2];
#pragma unroll
        for (int j = 0; j < 8; j++) {
            float p0 = __expf(S[j][0] * 0.125f - m0);
            float p1 = __expf(S[j][1] * 0.125f - m0);
            float p2 = __expf(S[j][2] * 0.125f - m1);
            float p3 = __expf(S[j][3] * 0.125f - m1);
            rs0 += p0 + p1; rs1 += p2 + p3;
            P[j][0] = __floats2half2_rn(p0, p1);
            P[j][1] = __floats2half2_rn(p2, p3);
        }
        l0 = l0 * a0 + rs0; l1 = l1 * a1 + rs1;
#pragma unroll
        for (int j = 0; j < 8; j++) {
            Oa[j][0] *= a0; Oa[j][1] *= a0; Oa[j][2] *= a1; Oa[j][3] *= a1;
        }
        unsigned vb = kb + FKVST;
#pragma unroll
        for (int kt = 0; kt < 4; kt++) {
            unsigned vf[4][4];
#pragma unroll
            for (int dg = 0; dg < 4; dg++)
                ldmx4t(vb + (unsigned)((kt * 16 + lr) * 144) + dg * 32 + lcb, vf[dg]);
            unsigned pa[4];
            pa[0] = *(unsigned*)&P[2 * kt][0];
            pa[1] = *(unsigned*)&P[2 * kt][1];
            pa[2] = *(unsigned*)&P[2 * kt + 1][0];
            pa[3] = *(unsigned*)&P[2 * kt + 1][1];
#pragma unroll
            for (int dg = 0; dg < 4; dg++) {
                mma16816h(Oa[dg * 2 + 0], pa, vf[dg][0], vf[dg][1]);
                mma16816h(Oa[dg * 2 + 1], pa, vf[dg][2], vf[dg][3]);
            }
        }
        __syncthreads();
    }

    l0 += __shfl_xor_sync(0xffffffffu, l0, 1);
    l0 += __shfl_xor_sync(0xffffffffu, l0, 2);
    l1 += __shfl_xor_sync(0xffffffffu, l1, 1);
    l1 += __shfl_xor_sync(0xffffffffu, l1, 2);
    float inv0 = 1.0f / l0, inv1 = 1.0f / l1;
    int g = lane >> 2, t2 = (lane & 3) * 2;
    int rowg = q0 + wid * 16 + g;
#pragma unroll
    for (int j = 0; j < 8; j++) {
        int d = h * DH + j * 8 + t2;
        *(__half2*)&y[(size_t)(b * TSEQ + rowg) * CH + d] =
            __floats2half2_rn(Oa[j][0] * inv0, Oa[j][1] * inv0);
        *(__half2*)&y[(size_t)(b * TSEQ + rowg + 8) * CH + d] =
            __floats2half2_rn(Oa[j][2] * inv1, Oa[j][3] * inv1);
    }
}

// ---------------------------------------------------------------------------
__global__ void zero_loss_k(float* num, float* den) { *num = 0.f; *den = 0.f; }

__global__ void loss_k(const float* __restrict__ logits, const int* __restrict__ tg,
                       float* num, float* den) {
    __shared__ float rm[256], rs[256];
    int row = blockIdx.x;
    const float* lr = logits + (size_t)row * VOC;
    float m = -3.0e38f, s = 0.f;
    for (int j = threadIdx.x; j < VOC; j += 256) {
        float v = lr[j];
        if (v > m) { s = s * __expf(m - v) + 1.0f; m = v; }
        else s += __expf(v - m);
    }
    rm[threadIdx.x] = m; rs[threadIdx.x] = s;
    __syncthreads();
    for (int off = 128; off > 0; off >>= 1) {
        if (threadIdx.x < off) {
            float m2 = rm[threadIdx.x + off], s2 = rs[threadIdx.x + off];
            float m1 = rm[threadIdx.x], s1 = rs[threadIdx.x];
            float mn = fmaxf(m1, m2);
            rs[threadIdx.x] = s1 * __expf(m1 - mn) + s2 * __expf(m2 - mn);
            rm[threadIdx.x] = mn;
        }
        __syncthreads();
    }
    if (threadIdx.x == 0) {
        int t = tg[row];
        if (t != 0) {
            float lse = rm[0] + logf(rs[0]);
            atomicAdd(num, lse - lr[t]);
            atomicAdd(den, 1.0f);
        }
    }
}

__global__ void final_loss_k(const float* num, const float* den, float* out) {
    out[0] = *num / fmaxf(*den, 1.0f);
}

// ---------------------------------------------------------------------------
extern "C" void kernel_launch(void* const* d_in, const int* in_sizes, int n_in,
                              void* d_out, int out_size) {
    const int*   idx     = (const int*)d_in[0];
    const int*   targets = (const int*)d_in[1];
    const float* wte     = (const float*)d_in[2];
    const float* wpe     = (const float*)d_in[3];
    const float* ln1_g   = (const float*)d_in[4];
    const float* ln1_b   = (const float*)d_in[5];
    const float* attn_w  = (const float*)d_in[6];
    const float* attn_b  = (const float*)d_in[7];
    const float* proj_w  = (const float*)d_in[8];
    const float* proj_b  = (const float*)d_in[9];
    const float* ln2_g   = (const float*)d_in[10];
    const float* ln2_b   = (const float*)d_in[11];
    const float* fc_w    = (const float*)d_in[12];
    const float* fc_b    = (const float*)d_in[13];
    const float* fc2_w   = (const float*)d_in[14];
    const float* fc2_b   = (const float*)d_in[15];
    const float* lnf_g   = (const float*)d_in[16];
    const float* lnf_b   = (const float*)d_in[17];
    float* out = (float*)d_out;

    float *x, *h, *pnum, *pden;
    __half *qkv_h, *h_h, *y_h, *m_h, *wt_h, *wte_h;
    cudaGetSymbolAddress((void**)&x, g_x);
    cudaGetSymbolAddress((void**)&h, g_hf);
    cudaGetSymbolAddress((void**)&qkv_h, g_qkv_h);
    cudaGetSymbolAddress((void**)&h_h, g_h_h);
    cudaGetSymbolAddress((void**)&y_h, g_y_h);
    cudaGetSymbolAddress((void**)&m_h, g_m_h);
    cudaGetSymbolAddress((void**)&wt_h, g_wt_h);
    cudaGetSymbolAddress((void**)&wte_h, g_wte_h);
    cudaGetSymbolAddress((void**)&pnum, g_num);
    cudaGetSymbolAddress((void**)&pden, g_den);

    const size_t LOGN = (size_t)BT * VOC;
    float* out_loss = out + LOGN;
    float* out_x    = out + LOGN + 1;  // 4B-aligned only: scalar access

    cudaFuncSetAttribute(hgemm_k<0>, cudaFuncAttributeMaxDynamicSharedMemorySize, HSMEM);
    cudaFuncSetAttribute(hgemm_k<1>, cudaFuncAttributeMaxDynamicSharedMemorySize, HSMEM);
    cudaFuncSetAttribute(hgemm_k<2>, cudaFuncAttributeMaxDynamicSharedMemorySize, HSMEM);
    cudaFuncSetAttribute(hgemm_k<3>, cudaFuncAttributeMaxDynamicSharedMemorySize, HSMEM);
    cudaFuncSetAttribute(hgemm_k<4>, cudaFuncAttributeMaxDynamicSharedMemorySize, HSMEM);
    cudaFuncSetAttribute(flash_k, cudaFuncAttributeMaxDynamicSharedMemorySize, FSMEM);

    dim3 tblk(32, 8);

    // ---- weight preprocessing (batched over layers) ----
    conv_k<<<(VOC * CH / 4 + 255) / 256, 256>>>((const float4*)wte, wte_h, VOC * CH / 4);
    tconv_k<<<dim3(2304 / 32, 768 / 32, NLAY), tblk>>>(
        attn_w, wt_h + W_ATTN_OFF, 768, 2304, (size_t)W_ATTN_SZ, (size_t)W_ATTN_SZ);
    tconv_k<<<dim3(768 / 32, 768 / 32, NLAY), tblk>>>(
        proj_w, wt_h + W_PROJ_OFF, 768, 768, (size_t)W_PROJ_SZ, (size_t)W_PROJ_SZ);
    tconv_k<<<dim3(3072 / 32, 768 / 32, NLAY), tblk>>>(
        fc_w, wt_h + W_FC_OFF, 768, 3072, (size_t)W_FC_SZ, (size_t)W_FC_SZ);
    tconv_k<<<dim3(768 / 32, 3072 / 32, NLAY), tblk>>>(
        fc2_w, wt_h + W_FC2_OFF, 3072, 768, (size_t)W_FC2_SZ, (size_t)W_FC2_SZ);

    embed_k<<<BT, 256>>>(idx, wte, wpe, x);

    for (int l = 0; l < NLAY; l++) {
        const __half* wa = wt_h + W_ATTN_OFF + (size_t)l * W_ATTN_SZ;
        const __half* wp = wt_h + W_PROJ_OFF + (size_t)l * W_PROJ_SZ;
        const __half* wf = wt_h + W_FC_OFF + (size_t)l * W_FC_SZ;
        const __half* w2 = wt_h + W_FC2_OFF + (size_t)l * W_FC2_SZ;

        ln_k<0><<<BT, 256>>>(x, ln1_g + l * CH, ln1_b + l * CH, nullptr, h_h);
        hgemm_k<4><<<dim3(2304 / 128, BT / 128), 256, HSMEM>>>(
            h_h, wa, attn_b + (size_t)l * 3 * CH, nullptr, nullptr, qkv_h, BT, 3 * CH, CH);
        flash_k<<<dim3(TSEQ / 128, NH, 4), 256, FSMEM>>>(qkv_h, y_h);
        hgemm_k<2><<<dim3(CH / 128, BT / 128), 256, HSMEM>>>(
            y_h, wp, proj_b + (size_t)l * CH, x, x, nullptr, BT, CH, CH);
        ln_k<0><<<BT, 256>>>(x, ln2_g + l * CH, ln2_b + l * CH, nullptr, h_h);
        hgemm_k<1><<<dim3(4 * CH / 128, BT / 128), 256, HSMEM>>>(
            h_h, wf, fc_b + (size_t)l * 4 * CH, nullptr, nullptr, m_h, BT, 4 * CH, CH);
        hgemm_k<2><<<dim3(CH / 128, BT / 128), 256, HSMEM>>>(
            m_h, w2, fc2_b + (size_t)l * CH, x, x, nullptr, BT, CH, 4 * CH);
    }

    ln_k<1><<<BT, 256>>>(x, lnf_g, lnf_b, h, h_h);
    copy_k<<<(BT * CH + 255) / 256, 256>>>(h, out_x, BT * CH);
    hgemm_k<3><<<dim3(VOC / 128, BT / 128), 256, HSMEM>>>(
        h_h, wte_h, nullptr, nullptr, out, nullptr, BT, VOC, CH);
    zero_loss_k<<<1, 1>>>(pnum, pden);
    loss_k<<<BT, 256>>>(out, targets, pnum, pden);
    final_loss_k<<<1, 1>>>(pnum, pden, out_loss);
}